// round 12
// baseline (speedup 1.0000x reference)
#include <cuda_runtime.h>
#include <math.h>
#include <stdint.h>

// ---------------- problem constants ----------------
#define Dm   768
#define Hh   12
#define HDm  64
#define Mm   3072
#define Lm   12
#define Em   8
#define Km   2
#define Bm   32
#define Sm   196
#define GSm  392
#define NGm  16
#define CAPm 98
#define NTOK (Bm*Sm)     // 6272
#define EROWS (NGm*CAPm) // 1568
#define TROWS (Em*EROWS) // 12544
#define K2D  (Dm/2)      // 384 k-pairs
#define K2M  (Mm/2)      // 1536 k-pairs

// ---------------- scratch ----------------
__device__ float g_x [(size_t)NTOK*Dm];
__device__ float g_h [(size_t)NTOK*Dm];
__device__ float g_q [(size_t)NTOK*Dm];
__device__ float g_k [(size_t)NTOK*Dm];
__device__ float g_v [(size_t)NTOK*Dm];
__device__ float g_y [(size_t)TROWS*Dm];
// bf16-split planes (packed k-pairs: lo16 = even k, hi16 = odd k)
__device__ uint32_t g_h_hi [(size_t)NTOK*K2D],  g_h_lo [(size_t)NTOK*K2D];
__device__ uint32_t g_ao_hi[(size_t)NTOK*K2D],  g_ao_lo[(size_t)NTOK*K2D];
__device__ uint32_t g_ml_hi[(size_t)NTOK*K2M],  g_ml_lo[(size_t)NTOK*K2M];
__device__ uint32_t g_bf_hi[(size_t)(TROWS+128)*K2D], g_bf_lo[(size_t)(TROWS+128)*K2D];
__device__ uint32_t g_hx_hi[(size_t)(TROWS+128)*K2M], g_hx_lo[(size_t)(TROWS+128)*K2M];
__device__ uint32_t g_whi[(size_t)Em*K2D*Mm], g_wlo[(size_t)Em*K2D*Mm];
__device__ int   g_slot_src[TROWS];
__device__ int   g_comb_idx[NTOK*Km];
__device__ float g_comb_gate[NTOK*Km];

// ---------------- helpers ----------------
__device__ __forceinline__ float gelu_f(float x) {
    const float c = 0.7978845608028654f;
    float t = tanhf(c * (x + 0.044715f * x * x * x));
    return 0.5f * x * (1.0f + t);
}

__device__ __forceinline__ uint32_t smem_u32(const void* p) {
    uint32_t a;
    asm("{ .reg .u64 t; cvta.to.shared.u64 t, %1; cvt.u32.u64 %0, t; }" : "=r"(a) : "l"(p));
    return a;
}

__device__ __forceinline__ void cp16(uint32_t dst, const void* src, uint32_t sz) {
    asm volatile("cp.async.ca.shared.global [%0], [%1], 16, %2;"
                 :: "r"(dst), "l"(src), "r"(sz));
}
#define CP_COMMIT() asm volatile("cp.async.commit_group;" ::: "memory")
#define CP_WAIT(n)  asm volatile("cp.async.wait_group %0;" :: "n"(n) : "memory")

__device__ __forceinline__ void mma16(float* c, const uint32_t* a, const uint32_t* b) {
    asm volatile(
        "mma.sync.aligned.m16n8k16.row.col.f32.bf16.bf16.f32 "
        "{%0,%1,%2,%3},{%4,%5,%6,%7},{%8,%9},{%0,%1,%2,%3};"
        : "+f"(c[0]), "+f"(c[1]), "+f"(c[2]), "+f"(c[3])
        : "r"(a[0]), "r"(a[1]), "r"(a[2]), "r"(a[3]), "r"(b[0]), "r"(b[1]));
}

// pack two floats (x0=even k -> lo16, x1=odd k -> hi16)
__device__ __forceinline__ uint32_t packbf(float x1, float x0) {
    uint32_t d;
    asm("cvt.rn.bf16x2.f32 %0, %1, %2;" : "=r"(d) : "f"(x1), "f"(x0));
    return d;
}
// bf16 split: (x0,x1) -> hi pair + lo pair (exact residual split)
__device__ __forceinline__ void split_bf(float x0, float x1, uint32_t& hi, uint32_t& lo) {
    hi = packbf(x1, x0);
    float h0 = __uint_as_float(hi << 16);
    float h1 = __uint_as_float(hi & 0xFFFF0000u);
    lo = packbf(x1 - h1, x0 - h0);
}

// ---------------- weight split prepass: W[K][P] -> planes [K/2][P] ----------
__global__ void wsplit_kernel(const float* __restrict__ w, uint32_t* __restrict__ whi,
                              uint32_t* __restrict__ wlo, int P, long np) {
    long j = ((long)blockIdx.x * blockDim.x + threadIdx.x) * 4;
    if (j >= np) return;
    long k2 = j / P;
    int n = (int)(j - k2 * P);
    const float* r0 = w + (2 * k2) * (long)P + n;
    float4 a = *reinterpret_cast<const float4*>(r0);
    float4 b = *reinterpret_cast<const float4*>(r0 + P);
    uint32_t h0,l0,h1,l1,h2,l2,h3,l3;
    split_bf(a.x, b.x, h0, l0);
    split_bf(a.y, b.y, h1, l1);
    split_bf(a.z, b.z, h2, l2);
    split_bf(a.w, b.w, h3, l3);
    *reinterpret_cast<uint4*>(whi + j) = make_uint4(h0, h1, h2, h3);
    *reinterpret_cast<uint4*>(wlo + j) = make_uint4(l0, l1, l2, l3);
}

// ---------------- 3xBF16 GEMM (separate hi/lo planes, K=32 chunks) ---------
// A smem: [2 buf][128 rows][20] per plane;  B smem: [2 buf][16 rows][136] per plane
#define KCH 16
#define AST 20
#define BST 136
#define A_PLANE (128*AST)   // 2560 u32
#define B_PLANE (KCH*BST)   // 2176 u32
#define GEMM_SMEM ((4*A_PLANE + 4*B_PLANE)*4)   // 75776 bytes

__global__ void __launch_bounds__(256, 2)
mma_gemm(const uint32_t* __restrict__ Ahi, const uint32_t* __restrict__ Alo,
         const uint32_t* __restrict__ Whi, const uint32_t* __restrict__ Wlo,
         const float* __restrict__ bias,
         float* __restrict__ Cf, uint32_t* __restrict__ Chi, uint32_t* __restrict__ Clo,
         int Nrows, int K2, int Pc,
         long strA, long strW, long strBias, long strC,
         float alpha, int act, int accum) {
    int z = blockIdx.z;
    Ahi += (long)z * strA; Alo += (long)z * strA;
    Whi += (long)z * strW; Wlo += (long)z * strW;
    const float* Bp = bias + (long)z * strBias;

    extern __shared__ uint32_t smw[];
    uint32_t* sAhi = smw;
    uint32_t* sAlo = smw + 2 * A_PLANE;
    uint32_t* sBhi = smw + 4 * A_PLANE;
    uint32_t* sBlo = smw + 4 * A_PLANE + 2 * B_PLANE;

    int tid = threadIdx.x;
    int row0 = blockIdx.y * 128, col0 = blockIdx.x * 128;

    // staging: A 2 threads/row, 8 u32 each (2 cp16/plane); B 16 threads/row, 8 u32 each
    int ar = tid >> 1, ao_ = (tid & 1) * 8;
    int bkr = tid >> 4, bseg = (tid & 15) * 8;
    const uint32_t* gAhi = Ahi + (long)(row0 + ar) * K2 + ao_;
    const uint32_t* gAlo = Alo + (long)(row0 + ar) * K2 + ao_;
    const uint32_t* gBhi = Whi + (long)bkr * Pc + col0 + bseg;
    const uint32_t* gBlo = Wlo + (long)bkr * Pc + col0 + bseg;
    uint32_t asz = ((row0 + ar) < Nrows) ? 16u : 0u;
    uint32_t dAhi = smem_u32(sAhi) + (uint32_t)(ar * AST + ao_) * 4u;
    uint32_t dAlo = smem_u32(sAlo) + (uint32_t)(ar * AST + ao_) * 4u;
    uint32_t dBhi = smem_u32(sBhi) + (uint32_t)(bkr * BST + bseg) * 4u;
    uint32_t dBlo = smem_u32(sBlo) + (uint32_t)(bkr * BST + bseg) * 4u;
    long bstep = (long)KCH * Pc;

    int nk = K2 / KCH;

    cp16(dAhi, gAhi, asz); cp16(dAhi + 16, gAhi + 4, asz);
    cp16(dAlo, gAlo, asz); cp16(dAlo + 16, gAlo + 4, asz);
    cp16(dBhi, gBhi, 16);  cp16(dBhi + 16, gBhi + 4, 16);
    cp16(dBlo, gBlo, 16);  cp16(dBlo + 16, gBlo + 4, 16);
    CP_COMMIT();

    int warp = tid >> 5, lane = tid & 31;
    int wm = (warp & 3) * 32, wn = (warp >> 2) * 64;
    int gid = lane >> 2, tig = lane & 3;

    float acc[2][8][4];
    #pragma unroll
    for (int mt = 0; mt < 2; mt++)
        #pragma unroll
        for (int nt = 0; nt < 8; nt++)
            #pragma unroll
            for (int r = 0; r < 4; r++) acc[mt][nt][r] = 0.0f;

    for (int i = 0; i < nk; i++) {
        int b = i & 1;
        if (i + 1 < nk) {
            int nb = b ^ 1;
            const uint32_t* pah = gAhi + (i + 1) * KCH;
            const uint32_t* pal = gAlo + (i + 1) * KCH;
            const uint32_t* pbh = gBhi + (long)(i + 1) * bstep;
            const uint32_t* pbl = gBlo + (long)(i + 1) * bstep;
            uint32_t oA = (uint32_t)(nb * A_PLANE) * 4u;
            uint32_t oB = (uint32_t)(nb * B_PLANE) * 4u;
            cp16(dAhi + oA, pah, asz); cp16(dAhi + oA + 16, pah + 4, asz);
            cp16(dAlo + oA, pal, asz); cp16(dAlo + oA + 16, pal + 4, asz);
            cp16(dBhi + oB, pbh, 16);  cp16(dBhi + oB + 16, pbh + 4, 16);
            cp16(dBlo + oB, pbl, 16);  cp16(dBlo + oB + 16, pbl + 4, 16);
            CP_COMMIT();
            CP_WAIT(1);
        } else {
            CP_WAIT(0);
        }
        __syncthreads();

        const uint32_t* Ah = sAhi + b * A_PLANE;
        const uint32_t* Al = sAlo + b * A_PLANE;
        const uint32_t* Bh = sBhi + b * B_PLANE;
        const uint32_t* Bl = sBlo + b * B_PLANE;

        #pragma unroll
        for (int ks = 0; ks < 2; ks++) {
            int kq = ks * 8;
            uint32_t afh[2][4], afl[2][4];
            #pragma unroll
            for (int mt = 0; mt < 2; mt++) {
                int base = (wm + mt * 16 + gid) * AST + kq + tig;
                afh[mt][0] = Ah[base];           afh[mt][1] = Ah[base + 8 * AST];
                afh[mt][2] = Ah[base + 4];       afh[mt][3] = Ah[base + 8 * AST + 4];
                afl[mt][0] = Al[base];           afl[mt][1] = Al[base + 8 * AST];
                afl[mt][2] = Al[base + 4];       afl[mt][3] = Al[base + 8 * AST + 4];
            }
            // nt processed in pairs; MMA issue is pass-major so consecutive
            // instructions never share an accumulator (reuse distance = 4).
            #pragma unroll
            for (int np_ = 0; np_ < 4; np_++) {
                int nt0 = np_ * 2, nt1 = nt0 + 1;
                int bb0 = (kq + tig) * BST + wn + nt0 * 8 + gid;
                int bb1 = bb0 + 8;
                uint32_t bh0[2] = { Bh[bb0], Bh[bb0 + 4 * BST] };
                uint32_t bl0[2] = { Bl[bb0], Bl[bb0 + 4 * BST] };
                uint32_t bh1[2] = { Bh[bb1], Bh[bb1 + 4 * BST] };
                uint32_t bl1[2] = { Bl[bb1], Bl[bb1 + 4 * BST] };
                // pass 1: hi * lo
                mma16(acc[0][nt0], afh[0], bl0);
                mma16(acc[1][nt0], afh[1], bl0);
                mma16(acc[0][nt1], afh[0], bl1);
                mma16(acc[1][nt1], afh[1], bl1);
                // pass 2: lo * hi
                mma16(acc[0][nt0], afl[0], bh0);
                mma16(acc[1][nt0], afl[1], bh0);
                mma16(acc[0][nt1], afl[0], bh1);
                mma16(acc[1][nt1], afl[1], bh1);
                // pass 3: hi * hi
                mma16(acc[0][nt0], afh[0], bh0);
                mma16(acc[1][nt0], afh[1], bh0);
                mma16(acc[0][nt1], afh[0], bh1);
                mma16(acc[1][nt1], afh[1], bh1);
            }
        }
        __syncthreads();
    }

    // epilogue
    int P2 = Pc >> 1;
    #pragma unroll
    for (int mt = 0; mt < 2; mt++) {
        int r0 = row0 + wm + mt * 16 + gid;
        #pragma unroll
        for (int half = 0; half < 2; half++) {
            int gr = r0 + half * 8;
            if (gr >= Nrows) continue;
            #pragma unroll
            for (int nt = 0; nt < 8; nt++) {
                int gc = col0 + wn + nt * 8 + 2 * tig;
                float2 bv = *reinterpret_cast<const float2*>(Bp + gc);
                float v0 = (acc[mt][nt][half * 2 + 0] + bv.x) * alpha;
                float v1 = (acc[mt][nt][half * 2 + 1] + bv.y) * alpha;
                if (act) { v0 = gelu_f(v0); v1 = gelu_f(v1); }
                if (Chi) {
                    long o = (long)z * strC + (long)gr * P2 + (gc >> 1);
                    uint32_t hi, lo;
                    split_bf(v0, v1, hi, lo);
                    Chi[o] = hi; Clo[o] = lo;
                } else {
                    float* Cp = Cf + (long)z * strC + (long)gr * Pc + gc;
                    if (accum) {
                        float2 o = *reinterpret_cast<float2*>(Cp);
                        v0 += o.x; v1 += o.y;
                    }
                    *reinterpret_cast<float2*>(Cp) = make_float2(v0, v1);
                }
            }
        }
    }
}

// ---------------- elementwise ----------------
__global__ void addpos_kernel(const float* __restrict__ x, const float* __restrict__ pe,
                              float* __restrict__ out) {
    int i = blockIdx.x * blockDim.x + threadIdx.x;
    if (i < NTOK * Dm) out[i] = x[i] + pe[i % (Sm * Dm)];
}

__device__ __forceinline__ float block_reduce_sum(float v) {
    __shared__ float sh[33];
    int lane = threadIdx.x & 31, w = threadIdx.x >> 5;
    #pragma unroll
    for (int o = 16; o; o >>= 1) v += __shfl_xor_sync(0xffffffffu, v, o);
    if (lane == 0) sh[w] = v;
    __syncthreads();
    int nw = blockDim.x >> 5;
    float r = (threadIdx.x < nw) ? sh[threadIdx.x] : 0.0f;
    if (w == 0) {
        #pragma unroll
        for (int o = 16; o; o >>= 1) r += __shfl_xor_sync(0xffffffffu, r, o);
        if (lane == 0) sh[32] = r;
    }
    __syncthreads();
    float out = sh[32];
    __syncthreads();
    return out;
}

__global__ void ln_kernel(const float* __restrict__ in, float* __restrict__ outf,
                          uint32_t* __restrict__ ohi, uint32_t* __restrict__ olo,
                          const float* __restrict__ s, const float* __restrict__ b) {
    int t = blockIdx.x;
    const float* xr = in + (size_t)t * Dm;
    float sum = 0.0f;
    for (int i = threadIdx.x; i < Dm; i += blockDim.x) sum += xr[i];
    float mu = block_reduce_sum(sum) * (1.0f / Dm);
    float vs = 0.0f;
    for (int i = threadIdx.x; i < Dm; i += blockDim.x) { float d = xr[i] - mu; vs += d * d; }
    float var = block_reduce_sum(vs) * (1.0f / Dm);
    float inv = rsqrtf(var + 1e-6f);
    for (int i = threadIdx.x * 2; i < Dm; i += blockDim.x * 2) {
        float v0 = (xr[i] - mu) * inv * s[i] + b[i];
        float v1 = (xr[i + 1] - mu) * inv * s[i + 1] + b[i + 1];
        if (outf) { outf[(size_t)t * Dm + i] = v0; outf[(size_t)t * Dm + i + 1] = v1; }
        if (ohi) {
            uint32_t hi, lo;
            split_bf(v0, v1, hi, lo);
            ohi[(size_t)t * K2D + (i >> 1)] = hi;
            olo[(size_t)t * K2D + (i >> 1)] = lo;
        }
    }
}

// ---------------- attention (writes bf16-split planes) ----------------
#define KPAD (HDm + 1)
__global__ void attn_kernel(const float* __restrict__ q, const float* __restrict__ k,
                            const float* __restrict__ v,
                            uint32_t* __restrict__ ohi, uint32_t* __restrict__ olo) {
    extern __shared__ float sm[];
    float* Ks = sm;
    float* Vs = sm + Sm * KPAD;
    __shared__ float att[8][Sm];
    __shared__ float qrow[8][HDm];

    int bh = blockIdx.x;
    int b = bh / Hh, h = bh % Hh;
    int tid = threadIdx.x, warp = tid >> 5, lane = tid & 31;
    const long base = (long)(b * Sm) * Dm + h * HDm;
    const long base2 = (long)(b * Sm) * K2D + h * (HDm / 2);

    for (int idx = tid; idx < Sm * HDm; idx += blockDim.x) {
        int j = idx >> 6, c = idx & 63;
        Ks[j * KPAD + c] = k[base + (long)j * Dm + c];
        Vs[j * KPAD + c] = v[base + (long)j * Dm + c];
    }
    __syncthreads();

    for (int i = warp; i < Sm; i += 8) {
        for (int c = lane; c < HDm; c += 32) qrow[warp][c] = q[base + (long)i * Dm + c];
        __syncwarp();
        float lmax = -1e30f;
        for (int j = lane; j < Sm; j += 32) {
            float d = 0.0f;
            #pragma unroll
            for (int c = 0; c < HDm; c++) d += qrow[warp][c] * Ks[j * KPAD + c];
            att[warp][j] = d;
            lmax = fmaxf(lmax, d);
        }
        #pragma unroll
        for (int off = 16; off; off >>= 1)
            lmax = fmaxf(lmax, __shfl_xor_sync(0xffffffffu, lmax, off));
        float lsum = 0.0f;
        for (int j = lane; j < Sm; j += 32) {
            float e = expf(att[warp][j] - lmax);
            att[warp][j] = e;
            lsum += e;
        }
        #pragma unroll
        for (int off = 16; off; off >>= 1)
            lsum += __shfl_xor_sync(0xffffffffu, lsum, off);
        float inv = 1.0f / lsum;
        __syncwarp();
        {
            int c = lane * 2;
            float a0 = 0.0f, a1 = 0.0f;
            for (int j = 0; j < Sm; j++) {
                float w = att[warp][j];
                a0 += w * Vs[j * KPAD + c];
                a1 += w * Vs[j * KPAD + c + 1];
            }
            uint32_t hi, lo;
            split_bf(a0 * inv, a1 * inv, hi, lo);
            ohi[base2 + (long)i * K2D + (c >> 1)] = hi;
            olo[base2 + (long)i * K2D + (c >> 1)] = lo;
        }
        __syncwarp();
    }
}

// ---------------- MoE routing ----------------
__global__ void route_kernel(const float* __restrict__ h, const float* __restrict__ wr) {
    int n = blockIdx.x;
    __shared__ float wrs[Em * Dm];
    __shared__ float tv[GSm][Km];
    __shared__ int   ti[GSm][Km];
    int tid = threadIdx.x, warp = tid >> 5, lane = tid & 31;

    for (int idx = tid; idx < Em * Dm; idx += blockDim.x) {
        int e = idx / Dm, c = idx % Dm;
        wrs[e * Dm + c] = wr[c * Em + e];
    }
    for (int s = tid; s < Em * CAPm; s += blockDim.x) {
        int e = s / CAPm, c = s % CAPm;
        g_slot_src[(e * NGm + n) * CAPm + c] = -1;
    }
    __syncthreads();

    for (int t = warp; t < GSm; t += 8) {
        const float* xr = h + (long)(n * GSm + t) * Dm;
        float a[Em];
        #pragma unroll
        for (int e = 0; e < Em; e++) a[e] = 0.0f;
        for (int c = lane; c < Dm; c += 32) {
            float xv = xr[c];
            #pragma unroll
            for (int e = 0; e < Em; e++) a[e] += xv * wrs[e * Dm + c];
        }
        #pragma unroll
        for (int e = 0; e < Em; e++)
            #pragma unroll
            for (int o = 16; o; o >>= 1) a[e] += __shfl_xor_sync(0xffffffffu, a[e], o);
        if (lane == 0) {
            float mx = a[0];
            #pragma unroll
            for (int e = 1; e < Em; e++) mx = fmaxf(mx, a[e]);
            float p[Em], sum = 0.0f;
            #pragma unroll
            for (int e = 0; e < Em; e++) { p[e] = expf(a[e] - mx); sum += p[e]; }
            float inv = 1.0f / sum;
            #pragma unroll
            for (int e = 0; e < Em; e++) p[e] *= inv;
            int i0 = 0;
            #pragma unroll
            for (int e = 1; e < Em; e++) if (p[e] > p[i0]) i0 = e;
            int i1 = (i0 == 0) ? 1 : 0;
            #pragma unroll
            for (int e = 0; e < Em; e++) if (e != i0 && p[e] > p[i1]) i1 = e;
            ti[t][0] = i0; tv[t][0] = p[i0];
            ti[t][1] = i1; tv[t][1] = p[i1];
        }
    }
    __syncthreads();

    if (tid == 0) {
        int cnt[Em];
        #pragma unroll
        for (int e = 0; e < Em; e++) cnt[e] = 0;
        for (int kk = 0; kk < Km; kk++) {
            for (int t = 0; t < GSm; t++) {
                int e = ti[t][kk];
                int pos = cnt[e]++;
                int gt = n * GSm + t;
                if (pos < CAPm) {
                    int row = (e * NGm + n) * CAPm + pos;
                    g_slot_src[row] = gt;
                    g_comb_idx[gt * Km + kk] = row;
                    g_comb_gate[gt * Km + kk] = tv[t][kk];
                } else {
                    g_comb_idx[gt * Km + kk] = -1;
                    g_comb_gate[gt * Km + kk] = 0.0f;
                }
            }
        }
    }
}

__global__ void gather_kernel(const float* __restrict__ h) {
    int i = blockIdx.x * blockDim.x + threadIdx.x;
    if (i >= TROWS * K2D) return;
    int row = i / K2D, kp = i - row * K2D;
    int src = g_slot_src[row];
    float v0 = 0.0f, v1 = 0.0f;
    if (src >= 0) {
        float2 p = *reinterpret_cast<const float2*>(h + (long)src * Dm + 2 * kp);
        v0 = p.x; v1 = p.y;
    }
    uint32_t hi, lo;
    split_bf(v0, v1, hi, lo);
    g_bf_hi[i] = hi; g_bf_lo[i] = lo;
}

__global__ void combine_kernel(float* __restrict__ x) {
    int i = blockIdx.x * blockDim.x + threadIdx.x;
    if (i >= NTOK * Dm) return;
    int t = i / Dm, c = i - t * Dm;
    float acc = 0.0f;
    #pragma unroll
    for (int kk = 0; kk < Km; kk++) {
        int r = g_comb_idx[t * Km + kk];
        if (r >= 0) acc += g_comb_gate[t * Km + kk] * g_y[(long)r * Dm + c];
    }
    x[i] += acc;
}

// ---------------- host ----------------
static inline void wsplit(const float* w, uint32_t* whi, uint32_t* wlo, int P, long np) {
    wsplit_kernel<<<(unsigned)((np / 4 + 255) / 256), 256>>>(w, whi, wlo, P, np);
}

extern "C" void kernel_launch(void* const* d_in, const int* in_sizes, int n_in,
                              void* d_out, int out_size) {
    (void)in_sizes; (void)n_in; (void)out_size;
    const float* in_x     = (const float*)d_in[0];
    const float* posemb   = (const float*)d_in[1];
    const float* ln1_s    = (const float*)d_in[2];
    const float* ln1_b    = (const float*)d_in[3];
    const float* wq       = (const float*)d_in[4];
    const float* bq       = (const float*)d_in[5];
    const float* wk       = (const float*)d_in[6];
    const float* bk       = (const float*)d_in[7];
    const float* wv       = (const float*)d_in[8];
    const float* bv       = (const float*)d_in[9];
    const float* wo       = (const float*)d_in[10];
    const float* bo       = (const float*)d_in[11];
    const float* ln2_s    = (const float*)d_in[12];
    const float* ln2_b    = (const float*)d_in[13];
    const float* dw1      = (const float*)d_in[14];
    const float* db1      = (const float*)d_in[15];
    const float* dw2      = (const float*)d_in[16];
    const float* db2      = (const float*)d_in[17];
    const float* router_w = (const float*)d_in[18];
    const float* mw1      = (const float*)d_in[19];
    const float* mb1      = (const float*)d_in[20];
    const float* mw2      = (const float*)d_in[21];
    const float* mb2      = (const float*)d_in[22];
    const float* out_s    = (const float*)d_in[23];
    const float* out_b    = (const float*)d_in[24];
    float* out = (float*)d_out;

    float *x, *h, *q, *k, *v, *y;
    uint32_t *h_hi, *h_lo, *ao_hi, *ao_lo, *ml_hi, *ml_lo, *bf_hi, *bf_lo, *hx_hi, *hx_lo, *whi, *wlo;
    cudaGetSymbolAddress((void**)&x,     g_x);
    cudaGetSymbolAddress((void**)&h,     g_h);
    cudaGetSymbolAddress((void**)&q,     g_q);
    cudaGetSymbolAddress((void**)&k,     g_k);
    cudaGetSymbolAddress((void**)&v,     g_v);
    cudaGetSymbolAddress((void**)&y,     g_y);
    cudaGetSymbolAddress((void**)&h_hi,  g_h_hi);
    cudaGetSymbolAddress((void**)&h_lo,  g_h_lo);
    cudaGetSymbolAddress((void**)&ao_hi, g_ao_hi);
    cudaGetSymbolAddress((void**)&ao_lo, g_ao_lo);
    cudaGetSymbolAddress((void**)&ml_hi, g_ml_hi);
    cudaGetSymbolAddress((void**)&ml_lo, g_ml_lo);
    cudaGetSymbolAddress((void**)&bf_hi, g_bf_hi);
    cudaGetSymbolAddress((void**)&bf_lo, g_bf_lo);
    cudaGetSymbolAddress((void**)&hx_hi, g_hx_hi);
    cudaGetSymbolAddress((void**)&hx_lo, g_hx_lo);
    cudaGetSymbolAddress((void**)&whi,   g_whi);
    cudaGetSymbolAddress((void**)&wlo,   g_wlo);

    const int ATTN_SMEM = 2 * Sm * KPAD * (int)sizeof(float);
    cudaFuncSetAttribute(attn_kernel, cudaFuncAttributeMaxDynamicSharedMemorySize, ATTN_SMEM);
    cudaFuncSetAttribute(mma_gemm, cudaFuncAttributeMaxDynamicSharedMemorySize, GEMM_SMEM);

    const float qscale = 0.125f;
    const long WDD = (long)Dm * Dm;
    const long WDM = (long)Dm * Mm;

    addpos_kernel<<<(NTOK * Dm + 255) / 256, 256>>>(in_x, posemb, x);

    int di = 0, mi = 0;
    for (int l = 0; l < Lm; l++) {
        // ---- attention block ----
        ln_kernel<<<NTOK, 256>>>(x, nullptr, h_hi, h_lo,
                                 ln1_s + (size_t)l * Dm, ln1_b + (size_t)l * Dm);
        dim3 gdd(Dm / 128, NTOK / 128, 1);
        wsplit(wq + (size_t)l * WDD, whi, wlo, Dm, WDD / 2);
        mma_gemm<<<gdd, 256, GEMM_SMEM>>>(h_hi, h_lo, whi, wlo, bq + (size_t)l * Dm,
                                          q, nullptr, nullptr,
                                          NTOK, K2D, Dm, 0, 0, 0, 0, qscale, 0, 0);
        wsplit(wk + (size_t)l * WDD, whi, wlo, Dm, WDD / 2);
        mma_gemm<<<gdd, 256, GEMM_SMEM>>>(h_hi, h_lo, whi, wlo, bk + (size_t)l * Dm,
                                          k, nullptr, nullptr,
                                          NTOK, K2D, Dm, 0, 0, 0, 0, 1.0f, 0, 0);
        wsplit(wv + (size_t)l * WDD, whi, wlo, Dm, WDD / 2);
        mma_gemm<<<gdd, 256, GEMM_SMEM>>>(h_hi, h_lo, whi, wlo, bv + (size_t)l * Dm,
                                          v, nullptr, nullptr,
                                          NTOK, K2D, Dm, 0, 0, 0, 0, 1.0f, 0, 0);
        attn_kernel<<<Bm * Hh, 256, ATTN_SMEM>>>(q, k, v, ao_hi, ao_lo);
        wsplit(wo + (size_t)l * WDD, whi, wlo, Dm, WDD / 2);
        mma_gemm<<<gdd, 256, GEMM_SMEM>>>(ao_hi, ao_lo, whi, wlo, bo + (size_t)l * Dm,
                                          x, nullptr, nullptr,
                                          NTOK, K2D, Dm, 0, 0, 0, 0, 1.0f, 0, 1);

        // ---- mlp / moe block ----
        ln_kernel<<<NTOK, 256>>>(x, h, h_hi, h_lo,
                                 ln2_s + (size_t)l * Dm, ln2_b + (size_t)l * Dm);
        if (l & 1) {
            route_kernel<<<NGm, 256>>>(h, router_w + (size_t)mi * Dm * Em);
            gather_kernel<<<(TROWS * K2D + 255) / 256, 256>>>(h);
            wsplit(mw1 + (size_t)mi * Em * WDM, whi, wlo, Mm, (long)Em * WDM / 2);
            dim3 g1(Mm / 128, (EROWS + 127) / 128, Em);
            mma_gemm<<<g1, 256, GEMM_SMEM>>>(bf_hi, bf_lo, whi, wlo, mb1 + (size_t)mi * Em * Mm,
                                             nullptr, hx_hi, hx_lo,
                                             EROWS, K2D, Mm,
                                             (long)EROWS * K2D, (long)K2D * Mm, Mm,
                                             (long)EROWS * K2M, 1.0f, 1, 0);
            wsplit(mw2 + (size_t)mi * Em * WDM, whi, wlo, Dm, (long)Em * WDM / 2);
            dim3 g2(Dm / 128, (EROWS + 127) / 128, Em);
            mma_gemm<<<g2, 256, GEMM_SMEM>>>(hx_hi, hx_lo, whi, wlo, mb2 + (size_t)mi * Em * Dm,
                                             y, nullptr, nullptr,
                                             EROWS, K2M, Dm,
                                             (long)EROWS * K2M, (long)K2M * Dm, Dm,
                                             (long)EROWS * Dm, 1.0f, 0, 0);
            combine_kernel<<<(NTOK * Dm + 255) / 256, 256>>>(x);
            mi++;
        } else {
            wsplit(dw1 + (size_t)di * WDM, whi, wlo, Mm, WDM / 2);
            dim3 g1(Mm / 128, NTOK / 128, 1);
            mma_gemm<<<g1, 256, GEMM_SMEM>>>(h_hi, h_lo, whi, wlo, db1 + (size_t)di * Mm,
                                             nullptr, ml_hi, ml_lo,
                                             NTOK, K2D, Mm, 0, 0, 0, 0, 1.0f, 1, 0);
            wsplit(dw2 + (size_t)di * WDM, whi, wlo, Dm, WDM / 2);
            dim3 g2(Dm / 128, NTOK / 128, 1);
            mma_gemm<<<g2, 256, GEMM_SMEM>>>(ml_hi, ml_lo, whi, wlo, db2 + (size_t)di * Dm,
                                             x, nullptr, nullptr,
                                             NTOK, K2M, Dm, 0, 0, 0, 0, 1.0f, 0, 1);
            di++;
        }
    }

    ln_kernel<<<NTOK, 256>>>(x, out, nullptr, nullptr, out_s, out_b);
}

// round 13
// speedup vs baseline: 1.0336x; 1.0336x over previous
#include <cuda_runtime.h>
#include <math.h>
#include <stdint.h>

// ---------------- problem constants ----------------
#define Dm   768
#define Hh   12
#define HDm  64
#define Mm   3072
#define Lm   12
#define Em   8
#define Km   2
#define Bm   32
#define Sm   196
#define GSm  392
#define NGm  16
#define CAPm 98
#define NTOK (Bm*Sm)     // 6272
#define EROWS (NGm*CAPm) // 1568
#define TROWS (Em*EROWS) // 12544
#define K2D  (Dm/2)      // 384 k-pairs
#define K2M  (Mm/2)      // 1536 k-pairs

// ---------------- scratch ----------------
__device__ float g_x [(size_t)NTOK*Dm];
__device__ float g_h [(size_t)NTOK*Dm];
__device__ float g_q [(size_t)NTOK*Dm];
__device__ float g_k [(size_t)NTOK*Dm];
__device__ float g_v [(size_t)NTOK*Dm];
__device__ float g_y [(size_t)TROWS*Dm];
// bf16-split planes (packed k-pairs: lo16 = even k, hi16 = odd k)
__device__ uint32_t g_h_hi [(size_t)NTOK*K2D],  g_h_lo [(size_t)NTOK*K2D];
__device__ uint32_t g_ao_hi[(size_t)NTOK*K2D],  g_ao_lo[(size_t)NTOK*K2D];
__device__ uint32_t g_ml_hi[(size_t)NTOK*K2M],  g_ml_lo[(size_t)NTOK*K2M];
__device__ uint32_t g_bf_hi[(size_t)(TROWS+128)*K2D], g_bf_lo[(size_t)(TROWS+128)*K2D];
__device__ uint32_t g_hx_hi[(size_t)(TROWS+128)*K2M], g_hx_lo[(size_t)(TROWS+128)*K2M];
// transposed weight planes: [P][K2]
__device__ uint32_t g_whi[(size_t)Em*K2D*Mm], g_wlo[(size_t)Em*K2D*Mm];
__device__ int   g_slot_src[TROWS];
__device__ int   g_comb_idx[NTOK*Km];
__device__ float g_comb_gate[NTOK*Km];

// ---------------- helpers ----------------
__device__ __forceinline__ float gelu_f(float x) {
    const float c = 0.7978845608028654f;
    float t = tanhf(c * (x + 0.044715f * x * x * x));
    return 0.5f * x * (1.0f + t);
}

__device__ __forceinline__ uint32_t smem_u32(const void* p) {
    uint32_t a;
    asm("{ .reg .u64 t; cvta.to.shared.u64 t, %1; cvt.u32.u64 %0, t; }" : "=r"(a) : "l"(p));
    return a;
}

__device__ __forceinline__ void cp16(uint32_t dst, const void* src, uint32_t sz) {
    asm volatile("cp.async.ca.shared.global [%0], [%1], 16, %2;"
                 :: "r"(dst), "l"(src), "r"(sz));
}
#define CP_COMMIT() asm volatile("cp.async.commit_group;" ::: "memory")
#define CP_WAIT(n)  asm volatile("cp.async.wait_group %0;" :: "n"(n) : "memory")

__device__ __forceinline__ void mma16(float* c, const uint32_t* a, const uint32_t* b) {
    asm volatile(
        "mma.sync.aligned.m16n8k16.row.col.f32.bf16.bf16.f32 "
        "{%0,%1,%2,%3},{%4,%5,%6,%7},{%8,%9},{%0,%1,%2,%3};"
        : "+f"(c[0]), "+f"(c[1]), "+f"(c[2]), "+f"(c[3])
        : "r"(a[0]), "r"(a[1]), "r"(a[2]), "r"(a[3]), "r"(b[0]), "r"(b[1]));
}

__device__ __forceinline__ void ldsm4(uint32_t& r0, uint32_t& r1, uint32_t& r2, uint32_t& r3,
                                      uint32_t addr) {
    asm volatile("ldmatrix.sync.aligned.m8n8.x4.shared.b16 {%0,%1,%2,%3}, [%4];"
                 : "=r"(r0), "=r"(r1), "=r"(r2), "=r"(r3) : "r"(addr));
}

// pack two floats (x0=even k -> lo16, x1=odd k -> hi16)
__device__ __forceinline__ uint32_t packbf(float x1, float x0) {
    uint32_t d;
    asm("cvt.rn.bf16x2.f32 %0, %1, %2;" : "=r"(d) : "f"(x1), "f"(x0));
    return d;
}
// bf16 split: (x0,x1) -> hi pair + lo pair (exact residual split)
__device__ __forceinline__ void split_bf(float x0, float x1, uint32_t& hi, uint32_t& lo) {
    hi = packbf(x1, x0);
    float h0 = __uint_as_float(hi << 16);
    float h1 = __uint_as_float(hi & 0xFFFF0000u);
    lo = packbf(x1 - h1, x0 - h0);
}

// ---------------- transposing weight split: W[Kd][P] -> planes [P][K2] ------
__global__ void wsplit_t_kernel(const float* __restrict__ w, uint32_t* __restrict__ whi,
                                uint32_t* __restrict__ wlo, int P, int K2,
                                long wstride, long ostride) {
    int z = blockIdx.z;
    w += (long)z * wstride; whi += (long)z * ostride; wlo += (long)z * ostride;
    __shared__ uint32_t shi[32][33], slo[32][33];
    int n0 = blockIdx.x * 32, k20 = blockIdx.y * 32;
    int tx = threadIdx.x, ty = threadIdx.y;   // block (32,8)
    #pragma unroll
    for (int rr = ty; rr < 32; rr += 8) {
        int k2 = k20 + rr;
        float v0 = w[(long)(2 * k2) * P + n0 + tx];
        float v1 = w[(long)(2 * k2 + 1) * P + n0 + tx];
        uint32_t hi, lo;
        split_bf(v0, v1, hi, lo);
        shi[rr][tx] = hi; slo[rr][tx] = lo;
    }
    __syncthreads();
    #pragma unroll
    for (int cc = ty; cc < 32; cc += 8) {
        whi[(long)(n0 + cc) * K2 + k20 + tx] = shi[tx][cc];
        wlo[(long)(n0 + cc) * K2 + k20 + tx] = slo[tx][cc];
    }
}

// ---------------- 3xBF16 GEMM (ldmatrix fragments, K=32 chunks) ------------
// A smem: [2 buf][128 rows][20] per plane;  B smem (transposed): same shape
#define KCH 16
#define AST 20
#define BST 20
#define A_PLANE (128*AST)   // 2560 u32
#define B_PLANE (128*BST)   // 2560 u32
#define GEMM_SMEM ((4*A_PLANE + 4*B_PLANE)*4)   // 81920 bytes

__global__ void __launch_bounds__(256, 2)
mma_gemm(const uint32_t* __restrict__ Ahi, const uint32_t* __restrict__ Alo,
         const uint32_t* __restrict__ Whi, const uint32_t* __restrict__ Wlo,
         const float* __restrict__ bias,
         float* __restrict__ Cf, uint32_t* __restrict__ Chi, uint32_t* __restrict__ Clo,
         int Nrows, int K2, int Pc,
         long strA, long strW, long strBias, long strC,
         float alpha, int act, int accum) {
    int z = blockIdx.z;
    Ahi += (long)z * strA; Alo += (long)z * strA;
    Whi += (long)z * strW; Wlo += (long)z * strW;
    const float* Bp = bias + (long)z * strBias;

    extern __shared__ uint32_t smw[];
    uint32_t* sAhi = smw;
    uint32_t* sAlo = smw + 2 * A_PLANE;
    uint32_t* sBhi = smw + 4 * A_PLANE;
    uint32_t* sBlo = smw + 4 * A_PLANE + 2 * B_PLANE;

    int tid = threadIdx.x;
    int row0 = blockIdx.y * 128, col0 = blockIdx.x * 128;

    // staging: 2 threads/row for both A and B(transposed), 8 u32 each (2 cp16/plane)
    int ar = tid >> 1, ako = (tid & 1) * 8;
    const uint32_t* gAhi = Ahi + (long)(row0 + ar) * K2 + ako;
    const uint32_t* gAlo = Alo + (long)(row0 + ar) * K2 + ako;
    const uint32_t* gBhi = Whi + (long)(col0 + ar) * K2 + ako;
    const uint32_t* gBlo = Wlo + (long)(col0 + ar) * K2 + ako;
    uint32_t asz = ((row0 + ar) < Nrows) ? 16u : 0u;
    uint32_t dAhi = smem_u32(sAhi) + (uint32_t)(ar * AST + ako) * 4u;
    uint32_t dAlo = smem_u32(sAlo) + (uint32_t)(ar * AST + ako) * 4u;
    uint32_t dBhi = smem_u32(sBhi) + (uint32_t)(ar * BST + ako) * 4u;
    uint32_t dBlo = smem_u32(sBlo) + (uint32_t)(ar * BST + ako) * 4u;

    int nk = K2 / KCH;

    cp16(dAhi, gAhi, asz); cp16(dAhi + 16, gAhi + 4, asz);
    cp16(dAlo, gAlo, asz); cp16(dAlo + 16, gAlo + 4, asz);
    cp16(dBhi, gBhi, 16);  cp16(dBhi + 16, gBhi + 4, 16);
    cp16(dBlo, gBlo, 16);  cp16(dBlo + 16, gBlo + 4, 16);
    CP_COMMIT();

    int warp = tid >> 5, lane = tid & 31;
    int wm = (warp & 3) * 32, wn = (warp >> 2) * 64;
    int gid = lane >> 2, tig = lane & 3;

    // ldmatrix lane addressing: lanes 0-15 -> rows 0-15 of 16x16 tile,
    // lanes 16-31 -> same rows, k+8 half (u32 offset +4)
    int l16 = lane & 15, kh4 = (lane >> 4) * 4;
    uint32_t fAhi = smem_u32(sAhi), fAlo = smem_u32(sAlo);
    uint32_t fBhi = smem_u32(sBhi), fBlo = smem_u32(sBlo);
    uint32_t aRow = (uint32_t)((wm + l16) * AST + kh4);
    uint32_t bRow = (uint32_t)((wn + l16) * BST + kh4);

    float acc[2][8][4];
    #pragma unroll
    for (int mt = 0; mt < 2; mt++)
        #pragma unroll
        for (int nt = 0; nt < 8; nt++)
            #pragma unroll
            for (int r = 0; r < 4; r++) acc[mt][nt][r] = 0.0f;

    for (int i = 0; i < nk; i++) {
        int b = i & 1;
        if (i + 1 < nk) {
            int nb = b ^ 1;
            const uint32_t* pah = gAhi + (i + 1) * KCH;
            const uint32_t* pal = gAlo + (i + 1) * KCH;
            const uint32_t* pbh = gBhi + (i + 1) * KCH;
            const uint32_t* pbl = gBlo + (i + 1) * KCH;
            uint32_t oA = (uint32_t)(nb * A_PLANE) * 4u;
            uint32_t oB = (uint32_t)(nb * B_PLANE) * 4u;
            cp16(dAhi + oA, pah, asz); cp16(dAhi + oA + 16, pah + 4, asz);
            cp16(dAlo + oA, pal, asz); cp16(dAlo + oA + 16, pal + 4, asz);
            cp16(dBhi + oB, pbh, 16);  cp16(dBhi + oB + 16, pbh + 4, 16);
            cp16(dBlo + oB, pbl, 16);  cp16(dBlo + oB + 16, pbl + 4, 16);
            CP_COMMIT();
            CP_WAIT(1);
        } else {
            CP_WAIT(0);
        }
        __syncthreads();

        uint32_t baseA = (uint32_t)(b * A_PLANE) * 4u;
        uint32_t baseB = (uint32_t)(b * B_PLANE) * 4u;
        #pragma unroll
        for (int ks = 0; ks < 2; ks++) {
            int kq = ks * 8;
            uint32_t afh[2][4], afl[2][4];
            #pragma unroll
            for (int mt = 0; mt < 2; mt++) {
                uint32_t off = (aRow + (uint32_t)(mt * 16 * AST + kq)) * 4u;
                ldsm4(afh[mt][0], afh[mt][1], afh[mt][2], afh[mt][3], fAhi + baseA + off);
                ldsm4(afl[mt][0], afl[mt][1], afl[mt][2], afl[mt][3], fAlo + baseA + off);
            }
            #pragma unroll
            for (int np_ = 0; np_ < 4; np_++) {
                int nt0 = np_ * 2, nt1 = nt0 + 1;
                uint32_t off = (bRow + (uint32_t)(np_ * 16 * BST + kq)) * 4u;
                uint32_t bh[4], bl[4];
                ldsm4(bh[0], bh[1], bh[2], bh[3], fBhi + baseB + off);
                ldsm4(bl[0], bl[1], bl[2], bl[3], fBlo + baseB + off);
                uint32_t b0h[2] = { bh[0], bh[2] }, b1h[2] = { bh[1], bh[3] };
                uint32_t b0l[2] = { bl[0], bl[2] }, b1l[2] = { bl[1], bl[3] };
                mma16(acc[0][nt0], afh[0], b0l);
                mma16(acc[1][nt0], afh[1], b0l);
                mma16(acc[0][nt1], afh[0], b1l);
                mma16(acc[1][nt1], afh[1], b1l);
                mma16(acc[0][nt0], afl[0], b0h);
                mma16(acc[1][nt0], afl[1], b0h);
                mma16(acc[0][nt1], afl[0], b1h);
                mma16(acc[1][nt1], afl[1], b1h);
                mma16(acc[0][nt0], afh[0], b0h);
                mma16(acc[1][nt0], afh[1], b0h);
                mma16(acc[0][nt1], afh[0], b1h);
                mma16(acc[1][nt1], afh[1], b1h);
            }
        }
        __syncthreads();
    }

    // epilogue
    int P2 = Pc >> 1;
    #pragma unroll
    for (int mt = 0; mt < 2; mt++) {
        int r0 = row0 + wm + mt * 16 + gid;
        #pragma unroll
        for (int half = 0; half < 2; half++) {
            int gr = r0 + half * 8;
            if (gr >= Nrows) continue;
            #pragma unroll
            for (int nt = 0; nt < 8; nt++) {
                int gc = col0 + wn + nt * 8 + 2 * tig;
                float2 bv = *reinterpret_cast<const float2*>(Bp + gc);
                float v0 = (acc[mt][nt][half * 2 + 0] + bv.x) * alpha;
                float v1 = (acc[mt][nt][half * 2 + 1] + bv.y) * alpha;
                if (act) { v0 = gelu_f(v0); v1 = gelu_f(v1); }
                if (Chi) {
                    long o = (long)z * strC + (long)gr * P2 + (gc >> 1);
                    uint32_t hi, lo;
                    split_bf(v0, v1, hi, lo);
                    Chi[o] = hi; Clo[o] = lo;
                } else {
                    float* Cp = Cf + (long)z * strC + (long)gr * Pc + gc;
                    if (accum) {
                        float2 o = *reinterpret_cast<float2*>(Cp);
                        v0 += o.x; v1 += o.y;
                    }
                    *reinterpret_cast<float2*>(Cp) = make_float2(v0, v1);
                }
            }
        }
    }
}

// ---------------- elementwise ----------------
__global__ void addpos_kernel(const float* __restrict__ x, const float* __restrict__ pe,
                              float* __restrict__ out) {
    int i = blockIdx.x * blockDim.x + threadIdx.x;
    if (i < NTOK * Dm) out[i] = x[i] + pe[i % (Sm * Dm)];
}

__device__ __forceinline__ float block_reduce_sum(float v) {
    __shared__ float sh[33];
    int lane = threadIdx.x & 31, w = threadIdx.x >> 5;
    #pragma unroll
    for (int o = 16; o; o >>= 1) v += __shfl_xor_sync(0xffffffffu, v, o);
    if (lane == 0) sh[w] = v;
    __syncthreads();
    int nw = blockDim.x >> 5;
    float r = (threadIdx.x < nw) ? sh[threadIdx.x] : 0.0f;
    if (w == 0) {
        #pragma unroll
        for (int o = 16; o; o >>= 1) r += __shfl_xor_sync(0xffffffffu, r, o);
        if (lane == 0) sh[32] = r;
    }
    __syncthreads();
    float out = sh[32];
    __syncthreads();
    return out;
}

__global__ void ln_kernel(const float* __restrict__ in, float* __restrict__ outf,
                          uint32_t* __restrict__ ohi, uint32_t* __restrict__ olo,
                          const float* __restrict__ s, const float* __restrict__ b) {
    int t = blockIdx.x;
    const float* xr = in + (size_t)t * Dm;
    float sum = 0.0f;
    for (int i = threadIdx.x; i < Dm; i += blockDim.x) sum += xr[i];
    float mu = block_reduce_sum(sum) * (1.0f / Dm);
    float vs = 0.0f;
    for (int i = threadIdx.x; i < Dm; i += blockDim.x) { float d = xr[i] - mu; vs += d * d; }
    float var = block_reduce_sum(vs) * (1.0f / Dm);
    float inv = rsqrtf(var + 1e-6f);
    for (int i = threadIdx.x * 2; i < Dm; i += blockDim.x * 2) {
        float v0 = (xr[i] - mu) * inv * s[i] + b[i];
        float v1 = (xr[i + 1] - mu) * inv * s[i + 1] + b[i + 1];
        if (outf) { outf[(size_t)t * Dm + i] = v0; outf[(size_t)t * Dm + i + 1] = v1; }
        if (ohi) {
            uint32_t hi, lo;
            split_bf(v0, v1, hi, lo);
            ohi[(size_t)t * K2D + (i >> 1)] = hi;
            olo[(size_t)t * K2D + (i >> 1)] = lo;
        }
    }
}

// ---------------- attention (writes bf16-split planes) ----------------
#define KPAD (HDm + 1)
__global__ void attn_kernel(const float* __restrict__ q, const float* __restrict__ k,
                            const float* __restrict__ v,
                            uint32_t* __restrict__ ohi, uint32_t* __restrict__ olo) {
    extern __shared__ float sm[];
    float* Ks = sm;
    float* Vs = sm + Sm * KPAD;
    __shared__ float att[8][Sm];
    __shared__ float qrow[8][HDm];

    int bh = blockIdx.x;
    int b = bh / Hh, h = bh % Hh;
    int tid = threadIdx.x, warp = tid >> 5, lane = tid & 31;
    const long base = (long)(b * Sm) * Dm + h * HDm;
    const long base2 = (long)(b * Sm) * K2D + h * (HDm / 2);

    for (int idx = tid; idx < Sm * HDm; idx += blockDim.x) {
        int j = idx >> 6, c = idx & 63;
        Ks[j * KPAD + c] = k[base + (long)j * Dm + c];
        Vs[j * KPAD + c] = v[base + (long)j * Dm + c];
    }
    __syncthreads();

    for (int i = warp; i < Sm; i += 8) {
        for (int c = lane; c < HDm; c += 32) qrow[warp][c] = q[base + (long)i * Dm + c];
        __syncwarp();
        float lmax = -1e30f;
        for (int j = lane; j < Sm; j += 32) {
            float d = 0.0f;
            #pragma unroll
            for (int c = 0; c < HDm; c++) d += qrow[warp][c] * Ks[j * KPAD + c];
            att[warp][j] = d;
            lmax = fmaxf(lmax, d);
        }
        #pragma unroll
        for (int off = 16; off; off >>= 1)
            lmax = fmaxf(lmax, __shfl_xor_sync(0xffffffffu, lmax, off));
        float lsum = 0.0f;
        for (int j = lane; j < Sm; j += 32) {
            float e = expf(att[warp][j] - lmax);
            att[warp][j] = e;
            lsum += e;
        }
        #pragma unroll
        for (int off = 16; off; off >>= 1)
            lsum += __shfl_xor_sync(0xffffffffu, lsum, off);
        float inv = 1.0f / lsum;
        __syncwarp();
        {
            int c = lane * 2;
            float a0 = 0.0f, a1 = 0.0f;
            for (int j = 0; j < Sm; j++) {
                float w = att[warp][j];
                a0 += w * Vs[j * KPAD + c];
                a1 += w * Vs[j * KPAD + c + 1];
            }
            uint32_t hi, lo;
            split_bf(a0 * inv, a1 * inv, hi, lo);
            ohi[base2 + (long)i * K2D + (c >> 1)] = hi;
            olo[base2 + (long)i * K2D + (c >> 1)] = lo;
        }
        __syncwarp();
    }
}

// ---------------- MoE routing ----------------
__global__ void route_kernel(const float* __restrict__ h, const float* __restrict__ wr) {
    int n = blockIdx.x;
    __shared__ float wrs[Em * Dm];
    __shared__ float tv[GSm][Km];
    __shared__ int   ti[GSm][Km];
    int tid = threadIdx.x, warp = tid >> 5, lane = tid & 31;

    for (int idx = tid; idx < Em * Dm; idx += blockDim.x) {
        int e = idx / Dm, c = idx % Dm;
        wrs[e * Dm + c] = wr[c * Em + e];
    }
    for (int s = tid; s < Em * CAPm; s += blockDim.x) {
        int e = s / CAPm, c = s % CAPm;
        g_slot_src[(e * NGm + n) * CAPm + c] = -1;
    }
    __syncthreads();

    for (int t = warp; t < GSm; t += 8) {
        const float* xr = h + (long)(n * GSm + t) * Dm;
        float a[Em];
        #pragma unroll
        for (int e = 0; e < Em; e++) a[e] = 0.0f;
        for (int c = lane; c < Dm; c += 32) {
            float xv = xr[c];
            #pragma unroll
            for (int e = 0; e < Em; e++) a[e] += xv * wrs[e * Dm + c];
        }
        #pragma unroll
        for (int e = 0; e < Em; e++)
            #pragma unroll
            for (int o = 16; o; o >>= 1) a[e] += __shfl_xor_sync(0xffffffffu, a[e], o);
        if (lane == 0) {
            float mx = a[0];
            #pragma unroll
            for (int e = 1; e < Em; e++) mx = fmaxf(mx, a[e]);
            float p[Em], sum = 0.0f;
            #pragma unroll
            for (int e = 0; e < Em; e++) { p[e] = expf(a[e] - mx); sum += p[e]; }
            float inv = 1.0f / sum;
            #pragma unroll
            for (int e = 0; e < Em; e++) p[e] *= inv;
            int i0 = 0;
            #pragma unroll
            for (int e = 1; e < Em; e++) if (p[e] > p[i0]) i0 = e;
            int i1 = (i0 == 0) ? 1 : 0;
            #pragma unroll
            for (int e = 0; e < Em; e++) if (e != i0 && p[e] > p[i1]) i1 = e;
            ti[t][0] = i0; tv[t][0] = p[i0];
            ti[t][1] = i1; tv[t][1] = p[i1];
        }
    }
    __syncthreads();

    if (tid == 0) {
        int cnt[Em];
        #pragma unroll
        for (int e = 0; e < Em; e++) cnt[e] = 0;
        for (int kk = 0; kk < Km; kk++) {
            for (int t = 0; t < GSm; t++) {
                int e = ti[t][kk];
                int pos = cnt[e]++;
                int gt = n * GSm + t;
                if (pos < CAPm) {
                    int row = (e * NGm + n) * CAPm + pos;
                    g_slot_src[row] = gt;
                    g_comb_idx[gt * Km + kk] = row;
                    g_comb_gate[gt * Km + kk] = tv[t][kk];
                } else {
                    g_comb_idx[gt * Km + kk] = -1;
                    g_comb_gate[gt * Km + kk] = 0.0f;
                }
            }
        }
    }
}

__global__ void gather_kernel(const float* __restrict__ h) {
    int i = blockIdx.x * blockDim.x + threadIdx.x;
    if (i >= TROWS * K2D) return;
    int row = i / K2D, kp = i - row * K2D;
    int src = g_slot_src[row];
    float v0 = 0.0f, v1 = 0.0f;
    if (src >= 0) {
        float2 p = *reinterpret_cast<const float2*>(h + (long)src * Dm + 2 * kp);
        v0 = p.x; v1 = p.y;
    }
    uint32_t hi, lo;
    split_bf(v0, v1, hi, lo);
    g_bf_hi[i] = hi; g_bf_lo[i] = lo;
}

__global__ void combine_kernel(float* __restrict__ x) {
    int i = blockIdx.x * blockDim.x + threadIdx.x;
    if (i >= NTOK * Dm) return;
    int t = i / Dm, c = i - t * Dm;
    float acc = 0.0f;
    #pragma unroll
    for (int kk = 0; kk < Km; kk++) {
        int r = g_comb_idx[t * Km + kk];
        if (r >= 0) acc += g_comb_gate[t * Km + kk] * g_y[(long)r * Dm + c];
    }
    x[i] += acc;
}

// ---------------- host ----------------
static inline void wsplit_t(const float* w, uint32_t* whi, uint32_t* wlo,
                            int P, int K2, int nmat) {
    dim3 g(P / 32, K2 / 32, nmat);
    wsplit_t_kernel<<<g, dim3(32, 8, 1)>>>(w, whi, wlo, P, K2,
                                           (long)2 * K2 * P, (long)P * K2);
}

extern "C" void kernel_launch(void* const* d_in, const int* in_sizes, int n_in,
                              void* d_out, int out_size) {
    (void)in_sizes; (void)n_in; (void)out_size;
    const float* in_x     = (const float*)d_in[0];
    const float* posemb   = (const float*)d_in[1];
    const float* ln1_s    = (const float*)d_in[2];
    const float* ln1_b    = (const float*)d_in[3];
    const float* wq       = (const float*)d_in[4];
    const float* bq       = (const float*)d_in[5];
    const float* wk       = (const float*)d_in[6];
    const float* bk       = (const float*)d_in[7];
    const float* wv       = (const float*)d_in[8];
    const float* bv       = (const float*)d_in[9];
    const float* wo       = (const float*)d_in[10];
    const float* bo       = (const float*)d_in[11];
    const float* ln2_s    = (const float*)d_in[12];
    const float* ln2_b    = (const float*)d_in[13];
    const float* dw1      = (const float*)d_in[14];
    const float* db1      = (const float*)d_in[15];
    const float* dw2      = (const float*)d_in[16];
    const float* db2      = (const float*)d_in[17];
    const float* router_w = (const float*)d_in[18];
    const float* mw1      = (const float*)d_in[19];
    const float* mb1      = (const float*)d_in[20];
    const float* mw2      = (const float*)d_in[21];
    const float* mb2      = (const float*)d_in[22];
    const float* out_s    = (const float*)d_in[23];
    const float* out_b    = (const float*)d_in[24];
    float* out = (float*)d_out;

    float *x, *h, *q, *k, *v, *y;
    uint32_t *h_hi, *h_lo, *ao_hi, *ao_lo, *ml_hi, *ml_lo, *bf_hi, *bf_lo, *hx_hi, *hx_lo, *whi, *wlo;
    cudaGetSymbolAddress((void**)&x,     g_x);
    cudaGetSymbolAddress((void**)&h,     g_h);
    cudaGetSymbolAddress((void**)&q,     g_q);
    cudaGetSymbolAddress((void**)&k,     g_k);
    cudaGetSymbolAddress((void**)&v,     g_v);
    cudaGetSymbolAddress((void**)&y,     g_y);
    cudaGetSymbolAddress((void**)&h_hi,  g_h_hi);
    cudaGetSymbolAddress((void**)&h_lo,  g_h_lo);
    cudaGetSymbolAddress((void**)&ao_hi, g_ao_hi);
    cudaGetSymbolAddress((void**)&ao_lo, g_ao_lo);
    cudaGetSymbolAddress((void**)&ml_hi, g_ml_hi);
    cudaGetSymbolAddress((void**)&ml_lo, g_ml_lo);
    cudaGetSymbolAddress((void**)&bf_hi, g_bf_hi);
    cudaGetSymbolAddress((void**)&bf_lo, g_bf_lo);
    cudaGetSymbolAddress((void**)&hx_hi, g_hx_hi);
    cudaGetSymbolAddress((void**)&hx_lo, g_hx_lo);
    cudaGetSymbolAddress((void**)&whi,   g_whi);
    cudaGetSymbolAddress((void**)&wlo,   g_wlo);

    const int ATTN_SMEM = 2 * Sm * KPAD * (int)sizeof(float);
    cudaFuncSetAttribute(attn_kernel, cudaFuncAttributeMaxDynamicSharedMemorySize, ATTN_SMEM);
    cudaFuncSetAttribute(mma_gemm, cudaFuncAttributeMaxDynamicSharedMemorySize, GEMM_SMEM);

    const float qscale = 0.125f;

    addpos_kernel<<<(NTOK * Dm + 255) / 256, 256>>>(in_x, posemb, x);

    int di = 0, mi = 0;
    for (int l = 0; l < Lm; l++) {
        // ---- attention block ----
        ln_kernel<<<NTOK, 256>>>(x, nullptr, h_hi, h_lo,
                                 ln1_s + (size_t)l * Dm, ln1_b + (size_t)l * Dm);
        dim3 gdd(Dm / 128, NTOK / 128, 1);
        wsplit_t(wq + (size_t)l * Dm * Dm, whi, wlo, Dm, K2D, 1);
        mma_gemm<<<gdd, 256, GEMM_SMEM>>>(h_hi, h_lo, whi, wlo, bq + (size_t)l * Dm,
                                          q, nullptr, nullptr,
                                          NTOK, K2D, Dm, 0, 0, 0, 0, qscale, 0, 0);
        wsplit_t(wk + (size_t)l * Dm * Dm, whi, wlo, Dm, K2D, 1);
        mma_gemm<<<gdd, 256, GEMM_SMEM>>>(h_hi, h_lo, whi, wlo, bk + (size_t)l * Dm,
                                          k, nullptr, nullptr,
                                          NTOK, K2D, Dm, 0, 0, 0, 0, 1.0f, 0, 0);
        wsplit_t(wv + (size_t)l * Dm * Dm, whi, wlo, Dm, K2D, 1);
        mma_gemm<<<gdd, 256, GEMM_SMEM>>>(h_hi, h_lo, whi, wlo, bv + (size_t)l * Dm,
                                          v, nullptr, nullptr,
                                          NTOK, K2D, Dm, 0, 0, 0, 0, 1.0f, 0, 0);
        attn_kernel<<<Bm * Hh, 256, ATTN_SMEM>>>(q, k, v, ao_hi, ao_lo);
        wsplit_t(wo + (size_t)l * Dm * Dm, whi, wlo, Dm, K2D, 1);
        mma_gemm<<<gdd, 256, GEMM_SMEM>>>(ao_hi, ao_lo, whi, wlo, bo + (size_t)l * Dm,
                                          x, nullptr, nullptr,
                                          NTOK, K2D, Dm, 0, 0, 0, 0, 1.0f, 0, 1);

        // ---- mlp / moe block ----
        ln_kernel<<<NTOK, 256>>>(x, h, h_hi, h_lo,
                                 ln2_s + (size_t)l * Dm, ln2_b + (size_t)l * Dm);
        if (l & 1) {
            route_kernel<<<NGm, 256>>>(h, router_w + (size_t)mi * Dm * Em);
            gather_kernel<<<(TROWS * K2D + 255) / 256, 256>>>(h);
            wsplit_t(mw1 + (size_t)mi * Em * Dm * Mm, whi, wlo, Mm, K2D, Em);
            dim3 g1(Mm / 128, (EROWS + 127) / 128, Em);
            mma_gemm<<<g1, 256, GEMM_SMEM>>>(bf_hi, bf_lo, whi, wlo, mb1 + (size_t)mi * Em * Mm,
                                             nullptr, hx_hi, hx_lo,
                                             EROWS, K2D, Mm,
                                             (long)EROWS * K2D, (long)Mm * K2D, Mm,
                                             (long)EROWS * K2M, 1.0f, 1, 0);
            wsplit_t(mw2 + (size_t)mi * Em * Mm * Dm, whi, wlo, Dm, K2M, Em);
            dim3 g2(Dm / 128, (EROWS + 127) / 128, Em);
            mma_gemm<<<g2, 256, GEMM_SMEM>>>(hx_hi, hx_lo, whi, wlo, mb2 + (size_t)mi * Em * Dm,
                                             y, nullptr, nullptr,
                                             EROWS, K2M, Dm,
                                             (long)EROWS * K2M, (long)Dm * K2M, Dm,
                                             (long)EROWS * Dm, 1.0f, 0, 0);
            combine_kernel<<<(NTOK * Dm + 255) / 256, 256>>>(x);
            mi++;
        } else {
            wsplit_t(dw1 + (size_t)di * Dm * Mm, whi, wlo, Mm, K2D, 1);
            dim3 g1(Mm / 128, NTOK / 128, 1);
            mma_gemm<<<g1, 256, GEMM_SMEM>>>(h_hi, h_lo, whi, wlo, db1 + (size_t)di * Mm,
                                             nullptr, ml_hi, ml_lo,
                                             NTOK, K2D, Mm, 0, 0, 0, 0, 1.0f, 1, 0);
            wsplit_t(dw2 + (size_t)di * Mm * Dm, whi, wlo, Dm, K2M, 1);
            dim3 g2(Dm / 128, NTOK / 128, 1);
            mma_gemm<<<g2, 256, GEMM_SMEM>>>(ml_hi, ml_lo, whi, wlo, db2 + (size_t)di * Dm,
                                             x, nullptr, nullptr,
                                             NTOK, K2M, Dm, 0, 0, 0, 0, 1.0f, 0, 1);
            di++;
        }
    }

    ln_kernel<<<NTOK, 256>>>(x, out, nullptr, nullptr, out_s, out_b);
}

// round 14
// speedup vs baseline: 1.0724x; 1.0376x over previous
#include <cuda_runtime.h>
#include <math.h>
#include <stdint.h>

// ---------------- problem constants ----------------
#define Dm   768
#define Hh   12
#define HDm  64
#define Mm   3072
#define Lm   12
#define Em   8
#define Km   2
#define Bm   32
#define Sm   196
#define GSm  392
#define NGm  16
#define CAPm 98
#define NTOK (Bm*Sm)     // 6272
#define EROWS (NGm*CAPm) // 1568
#define TROWS (Em*EROWS) // 12544
#define K2D  (Dm/2)      // 384 k-pairs
#define K2M  (Mm/2)      // 1536 k-pairs

// ---------------- scratch ----------------
__device__ float g_x [(size_t)NTOK*Dm];
__device__ float g_h [(size_t)NTOK*Dm];
__device__ float g_q [(size_t)NTOK*Dm];
__device__ float g_k [(size_t)NTOK*Dm];
__device__ float g_v [(size_t)NTOK*Dm];
__device__ float g_y [(size_t)TROWS*Dm];
// bf16-split planes (packed k-pairs: lo16 = even k, hi16 = odd k)
__device__ uint32_t g_h_hi [(size_t)NTOK*K2D],  g_h_lo [(size_t)NTOK*K2D];
__device__ uint32_t g_ao_hi[(size_t)NTOK*K2D],  g_ao_lo[(size_t)NTOK*K2D];
__device__ uint32_t g_ml_hi[(size_t)NTOK*K2M],  g_ml_lo[(size_t)NTOK*K2M];
__device__ uint32_t g_bf_hi[(size_t)(TROWS+128)*K2D], g_bf_lo[(size_t)(TROWS+128)*K2D];
__device__ uint32_t g_hx_hi[(size_t)(TROWS+128)*K2M], g_hx_lo[(size_t)(TROWS+128)*K2M];
// transposed weight planes: [P][K2]
__device__ uint32_t g_whi[(size_t)Em*K2D*Mm], g_wlo[(size_t)Em*K2D*Mm];
__device__ int   g_slot_src[TROWS];
__device__ int   g_comb_idx[NTOK*Km];
__device__ float g_comb_gate[NTOK*Km];

// ---------------- helpers ----------------
__device__ __forceinline__ float gelu_f(float x) {
    const float c = 0.7978845608028654f;
    float t = tanhf(c * (x + 0.044715f * x * x * x));
    return 0.5f * x * (1.0f + t);
}

__device__ __forceinline__ uint32_t smem_u32(const void* p) {
    uint32_t a;
    asm("{ .reg .u64 t; cvta.to.shared.u64 t, %1; cvt.u32.u64 %0, t; }" : "=r"(a) : "l"(p));
    return a;
}

__device__ __forceinline__ void cp16(uint32_t dst, const void* src, uint32_t sz) {
    asm volatile("cp.async.ca.shared.global [%0], [%1], 16, %2;"
                 :: "r"(dst), "l"(src), "r"(sz));
}
#define CP_COMMIT() asm volatile("cp.async.commit_group;" ::: "memory")
#define CP_WAIT(n)  asm volatile("cp.async.wait_group %0;" :: "n"(n) : "memory")

__device__ __forceinline__ void mma16(float* c, const uint32_t* a, const uint32_t* b) {
    asm volatile(
        "mma.sync.aligned.m16n8k16.row.col.f32.bf16.bf16.f32 "
        "{%0,%1,%2,%3},{%4,%5,%6,%7},{%8,%9},{%0,%1,%2,%3};"
        : "+f"(c[0]), "+f"(c[1]), "+f"(c[2]), "+f"(c[3])
        : "r"(a[0]), "r"(a[1]), "r"(a[2]), "r"(a[3]), "r"(b[0]), "r"(b[1]));
}

__device__ __forceinline__ void ldsm4(uint32_t& r0, uint32_t& r1, uint32_t& r2, uint32_t& r3,
                                      uint32_t addr) {
    asm volatile("ldmatrix.sync.aligned.m8n8.x4.shared.b16 {%0,%1,%2,%3}, [%4];"
                 : "=r"(r0), "=r"(r1), "=r"(r2), "=r"(r3) : "r"(addr));
}

// packed f32x2 helpers
__device__ __forceinline__ unsigned long long pack2(float x, float y) {
    unsigned long long r;
    asm("mov.b64 %0, {%1, %2};" : "=l"(r) : "f"(x), "f"(y));
    return r;
}
__device__ __forceinline__ void unpack2(unsigned long long v, float& x, float& y) {
    asm("mov.b64 {%0, %1}, %2;" : "=f"(x), "=f"(y) : "l"(v));
}
__device__ __forceinline__ unsigned long long fma2(unsigned long long a,
                                                   unsigned long long b,
                                                   unsigned long long c) {
    unsigned long long d;
    asm("fma.rn.f32x2 %0, %1, %2, %3;" : "=l"(d) : "l"(a), "l"(b), "l"(c));
    return d;
}

// pack two floats (x0=even k -> lo16, x1=odd k -> hi16)
__device__ __forceinline__ uint32_t packbf(float x1, float x0) {
    uint32_t d;
    asm("cvt.rn.bf16x2.f32 %0, %1, %2;" : "=r"(d) : "f"(x1), "f"(x0));
    return d;
}
// bf16 split: (x0,x1) -> hi pair + lo pair (exact residual split)
__device__ __forceinline__ void split_bf(float x0, float x1, uint32_t& hi, uint32_t& lo) {
    hi = packbf(x1, x0);
    float h0 = __uint_as_float(hi << 16);
    float h1 = __uint_as_float(hi & 0xFFFF0000u);
    lo = packbf(x1 - h1, x0 - h0);
}

// ---------------- transposing weight split: W[Kd][P] -> planes [P][K2] ------
__global__ void wsplit_t_kernel(const float* __restrict__ w, uint32_t* __restrict__ whi,
                                uint32_t* __restrict__ wlo, int P, int K2,
                                long wstride, long ostride) {
    int z = blockIdx.z;
    w += (long)z * wstride; whi += (long)z * ostride; wlo += (long)z * ostride;
    __shared__ uint32_t shi[32][33], slo[32][33];
    int n0 = blockIdx.x * 32, k20 = blockIdx.y * 32;
    int tx = threadIdx.x, ty = threadIdx.y;   // block (32,8)
    #pragma unroll
    for (int rr = ty; rr < 32; rr += 8) {
        int k2 = k20 + rr;
        float v0 = w[(long)(2 * k2) * P + n0 + tx];
        float v1 = w[(long)(2 * k2 + 1) * P + n0 + tx];
        uint32_t hi, lo;
        split_bf(v0, v1, hi, lo);
        shi[rr][tx] = hi; slo[rr][tx] = lo;
    }
    __syncthreads();
    #pragma unroll
    for (int cc = ty; cc < 32; cc += 8) {
        whi[(long)(n0 + cc) * K2 + k20 + tx] = shi[tx][cc];
        wlo[(long)(n0 + cc) * K2 + k20 + tx] = slo[tx][cc];
    }
}

// ---------------- 3xBF16 GEMM (ldmatrix fragments, K=32 chunks) ------------
// A smem: [2 buf][128 rows][20] per plane;  B smem (transposed): same shape
#define KCH 16
#define AST 20
#define BST 20
#define A_PLANE (128*AST)   // 2560 u32
#define B_PLANE (128*BST)   // 2560 u32
#define GEMM_SMEM ((4*A_PLANE + 4*B_PLANE)*4)   // 81920 bytes

__global__ void __launch_bounds__(256, 2)
mma_gemm(const uint32_t* __restrict__ Ahi, const uint32_t* __restrict__ Alo,
         const uint32_t* __restrict__ Whi, const uint32_t* __restrict__ Wlo,
         const float* __restrict__ bias,
         float* __restrict__ Cf, uint32_t* __restrict__ Chi, uint32_t* __restrict__ Clo,
         int Nrows, int K2, int Pc,
         long strA, long strW, long strBias, long strC,
         float alpha, int act, int accum) {
    int z = blockIdx.z;
    Ahi += (long)z * strA; Alo += (long)z * strA;
    Whi += (long)z * strW; Wlo += (long)z * strW;
    const float* Bp = bias + (long)z * strBias;

    extern __shared__ uint32_t smw[];
    uint32_t* sAhi = smw;
    uint32_t* sAlo = smw + 2 * A_PLANE;
    uint32_t* sBhi = smw + 4 * A_PLANE;
    uint32_t* sBlo = smw + 4 * A_PLANE + 2 * B_PLANE;

    int tid = threadIdx.x;
    int row0 = blockIdx.y * 128, col0 = blockIdx.x * 128;

    // staging: 2 threads/row for both A and B(transposed), 8 u32 each (2 cp16/plane)
    int ar = tid >> 1, ako = (tid & 1) * 8;
    const uint32_t* gAhi = Ahi + (long)(row0 + ar) * K2 + ako;
    const uint32_t* gAlo = Alo + (long)(row0 + ar) * K2 + ako;
    const uint32_t* gBhi = Whi + (long)(col0 + ar) * K2 + ako;
    const uint32_t* gBlo = Wlo + (long)(col0 + ar) * K2 + ako;
    uint32_t asz = ((row0 + ar) < Nrows) ? 16u : 0u;
    uint32_t dAhi = smem_u32(sAhi) + (uint32_t)(ar * AST + ako) * 4u;
    uint32_t dAlo = smem_u32(sAlo) + (uint32_t)(ar * AST + ako) * 4u;
    uint32_t dBhi = smem_u32(sBhi) + (uint32_t)(ar * BST + ako) * 4u;
    uint32_t dBlo = smem_u32(sBlo) + (uint32_t)(ar * BST + ako) * 4u;

    int nk = K2 / KCH;

    cp16(dAhi, gAhi, asz); cp16(dAhi + 16, gAhi + 4, asz);
    cp16(dAlo, gAlo, asz); cp16(dAlo + 16, gAlo + 4, asz);
    cp16(dBhi, gBhi, 16);  cp16(dBhi + 16, gBhi + 4, 16);
    cp16(dBlo, gBlo, 16);  cp16(dBlo + 16, gBlo + 4, 16);
    CP_COMMIT();

    int warp = tid >> 5, lane = tid & 31;
    int wm = (warp & 3) * 32, wn = (warp >> 2) * 64;
    int gid = lane >> 2, tig = lane & 3;

    // ldmatrix lane addressing: lanes 0-15 -> rows 0-15 of 16x16 tile,
    // lanes 16-31 -> same rows, k+8 half (u32 offset +4)
    int l16 = lane & 15, kh4 = (lane >> 4) * 4;
    uint32_t fAhi = smem_u32(sAhi), fAlo = smem_u32(sAlo);
    uint32_t fBhi = smem_u32(sBhi), fBlo = smem_u32(sBlo);
    uint32_t aRow = (uint32_t)((wm + l16) * AST + kh4);
    uint32_t bRow = (uint32_t)((wn + l16) * BST + kh4);

    float acc[2][8][4];
    #pragma unroll
    for (int mt = 0; mt < 2; mt++)
        #pragma unroll
        for (int nt = 0; nt < 8; nt++)
            #pragma unroll
            for (int r = 0; r < 4; r++) acc[mt][nt][r] = 0.0f;

    for (int i = 0; i < nk; i++) {
        int b = i & 1;
        if (i + 1 < nk) {
            int nb = b ^ 1;
            const uint32_t* pah = gAhi + (i + 1) * KCH;
            const uint32_t* pal = gAlo + (i + 1) * KCH;
            const uint32_t* pbh = gBhi + (i + 1) * KCH;
            const uint32_t* pbl = gBlo + (i + 1) * KCH;
            uint32_t oA = (uint32_t)(nb * A_PLANE) * 4u;
            uint32_t oB = (uint32_t)(nb * B_PLANE) * 4u;
            cp16(dAhi + oA, pah, asz); cp16(dAhi + oA + 16, pah + 4, asz);
            cp16(dAlo + oA, pal, asz); cp16(dAlo + oA + 16, pal + 4, asz);
            cp16(dBhi + oB, pbh, 16);  cp16(dBhi + oB + 16, pbh + 4, 16);
            cp16(dBlo + oB, pbl, 16);  cp16(dBlo + oB + 16, pbl + 4, 16);
            CP_COMMIT();
            CP_WAIT(1);
        } else {
            CP_WAIT(0);
        }
        __syncthreads();

        uint32_t baseA = (uint32_t)(b * A_PLANE) * 4u;
        uint32_t baseB = (uint32_t)(b * B_PLANE) * 4u;
        #pragma unroll
        for (int ks = 0; ks < 2; ks++) {
            int kq = ks * 8;
            uint32_t afh[2][4], afl[2][4];
            #pragma unroll
            for (int mt = 0; mt < 2; mt++) {
                uint32_t off = (aRow + (uint32_t)(mt * 16 * AST + kq)) * 4u;
                ldsm4(afh[mt][0], afh[mt][1], afh[mt][2], afh[mt][3], fAhi + baseA + off);
                ldsm4(afl[mt][0], afl[mt][1], afl[mt][2], afl[mt][3], fAlo + baseA + off);
            }
            #pragma unroll
            for (int np_ = 0; np_ < 4; np_++) {
                int nt0 = np_ * 2, nt1 = nt0 + 1;
                uint32_t off = (bRow + (uint32_t)(np_ * 16 * BST + kq)) * 4u;
                uint32_t bh[4], bl[4];
                ldsm4(bh[0], bh[1], bh[2], bh[3], fBhi + baseB + off);
                ldsm4(bl[0], bl[1], bl[2], bl[3], fBlo + baseB + off);
                uint32_t b0h[2] = { bh[0], bh[2] }, b1h[2] = { bh[1], bh[3] };
                uint32_t b0l[2] = { bl[0], bl[2] }, b1l[2] = { bl[1], bl[3] };
                mma16(acc[0][nt0], afh[0], b0l);
                mma16(acc[1][nt0], afh[1], b0l);
                mma16(acc[0][nt1], afh[0], b1l);
                mma16(acc[1][nt1], afh[1], b1l);
                mma16(acc[0][nt0], afl[0], b0h);
                mma16(acc[1][nt0], afl[1], b0h);
                mma16(acc[0][nt1], afl[0], b1h);
                mma16(acc[1][nt1], afl[1], b1h);
                mma16(acc[0][nt0], afh[0], b0h);
                mma16(acc[1][nt0], afh[1], b0h);
                mma16(acc[0][nt1], afh[0], b1h);
                mma16(acc[1][nt1], afh[1], b1h);
            }
        }
        __syncthreads();
    }

    // epilogue
    int P2 = Pc >> 1;
    #pragma unroll
    for (int mt = 0; mt < 2; mt++) {
        int r0 = row0 + wm + mt * 16 + gid;
        #pragma unroll
        for (int half = 0; half < 2; half++) {
            int gr = r0 + half * 8;
            if (gr >= Nrows) continue;
            #pragma unroll
            for (int nt = 0; nt < 8; nt++) {
                int gc = col0 + wn + nt * 8 + 2 * tig;
                float2 bv = *reinterpret_cast<const float2*>(Bp + gc);
                float v0 = (acc[mt][nt][half * 2 + 0] + bv.x) * alpha;
                float v1 = (acc[mt][nt][half * 2 + 1] + bv.y) * alpha;
                if (act) { v0 = gelu_f(v0); v1 = gelu_f(v1); }
                if (Chi) {
                    long o = (long)z * strC + (long)gr * P2 + (gc >> 1);
                    uint32_t hi, lo;
                    split_bf(v0, v1, hi, lo);
                    Chi[o] = hi; Clo[o] = lo;
                } else {
                    float* Cp = Cf + (long)z * strC + (long)gr * Pc + gc;
                    if (accum) {
                        float2 o = *reinterpret_cast<float2*>(Cp);
                        v0 += o.x; v1 += o.y;
                    }
                    *reinterpret_cast<float2*>(Cp) = make_float2(v0, v1);
                }
            }
        }
    }
}

// ---------------- elementwise ----------------
__global__ void addpos_kernel(const float* __restrict__ x, const float* __restrict__ pe,
                              float* __restrict__ out) {
    int i = blockIdx.x * blockDim.x + threadIdx.x;
    if (i < NTOK * Dm) out[i] = x[i] + pe[i % (Sm * Dm)];
}

__device__ __forceinline__ float block_reduce_sum(float v) {
    __shared__ float sh[33];
    int lane = threadIdx.x & 31, w = threadIdx.x >> 5;
    #pragma unroll
    for (int o = 16; o; o >>= 1) v += __shfl_xor_sync(0xffffffffu, v, o);
    if (lane == 0) sh[w] = v;
    __syncthreads();
    int nw = blockDim.x >> 5;
    float r = (threadIdx.x < nw) ? sh[threadIdx.x] : 0.0f;
    if (w == 0) {
        #pragma unroll
        for (int o = 16; o; o >>= 1) r += __shfl_xor_sync(0xffffffffu, r, o);
        if (lane == 0) sh[32] = r;
    }
    __syncthreads();
    float out = sh[32];
    __syncthreads();
    return out;
}

__global__ void ln_kernel(const float* __restrict__ in, float* __restrict__ outf,
                          uint32_t* __restrict__ ohi, uint32_t* __restrict__ olo,
                          const float* __restrict__ s, const float* __restrict__ b) {
    int t = blockIdx.x;
    const float* xr = in + (size_t)t * Dm;
    float sum = 0.0f;
    for (int i = threadIdx.x; i < Dm; i += blockDim.x) sum += xr[i];
    float mu = block_reduce_sum(sum) * (1.0f / Dm);
    float vs = 0.0f;
    for (int i = threadIdx.x; i < Dm; i += blockDim.x) { float d = xr[i] - mu; vs += d * d; }
    float var = block_reduce_sum(vs) * (1.0f / Dm);
    float inv = rsqrtf(var + 1e-6f);
    for (int i = threadIdx.x * 2; i < Dm; i += blockDim.x * 2) {
        float v0 = (xr[i] - mu) * inv * s[i] + b[i];
        float v1 = (xr[i + 1] - mu) * inv * s[i + 1] + b[i + 1];
        if (outf) { outf[(size_t)t * Dm + i] = v0; outf[(size_t)t * Dm + i + 1] = v1; }
        if (ohi) {
            uint32_t hi, lo;
            split_bf(v0, v1, hi, lo);
            ohi[(size_t)t * K2D + (i >> 1)] = hi;
            olo[(size_t)t * K2D + (i >> 1)] = lo;
        }
    }
}

// ---------------- attention (f32x2-vectorized; writes bf16-split planes) ----
#define KP2 33   // u64 pairs per row (32 data + 1 pad); 66 words == 2 mod 32
__global__ void attn_kernel(const float* __restrict__ q, const float* __restrict__ k,
                            const float* __restrict__ v,
                            uint32_t* __restrict__ ohi, uint32_t* __restrict__ olo) {
    extern __shared__ unsigned long long sm64[];
    unsigned long long* Ks = sm64;             // [Sm][KP2]
    unsigned long long* Vs = sm64 + Sm * KP2;  // [Sm][KP2]
    __shared__ float att[8][Sm];
    __shared__ unsigned long long qrow[8][32];

    int bh = blockIdx.x;
    int b = bh / Hh, h = bh % Hh;
    int tid = threadIdx.x, warp = tid >> 5, lane = tid & 31;
    const long base = (long)(b * Sm) * Dm + h * HDm;
    const long base2 = (long)(b * Sm) * K2D + h * (HDm / 2);

    for (int idx = tid; idx < Sm * 32; idx += blockDim.x) {
        int j = idx >> 5, c2 = idx & 31;
        float2 kk = *reinterpret_cast<const float2*>(k + base + (long)j * Dm + 2 * c2);
        float2 vv = *reinterpret_cast<const float2*>(v + base + (long)j * Dm + 2 * c2);
        Ks[j * KP2 + c2] = pack2(kk.x, kk.y);
        Vs[j * KP2 + c2] = pack2(vv.x, vv.y);
    }
    __syncthreads();

    for (int i = warp; i < Sm; i += 8) {
        {
            float2 qq = *reinterpret_cast<const float2*>(q + base + (long)i * Dm + 2 * lane);
            qrow[warp][lane] = pack2(qq.x, qq.y);
        }
        __syncwarp();
        float lmax = -1e30f;
        for (int j = lane; j < Sm; j += 32) {
            unsigned long long a2 = 0ull;
            const unsigned long long* kr = Ks + j * KP2;
            #pragma unroll
            for (int c2 = 0; c2 < 32; c2++)
                a2 = fma2(qrow[warp][c2], kr[c2], a2);
            float s0, s1;
            unpack2(a2, s0, s1);
            float d = s0 + s1;
            att[warp][j] = d;
            lmax = fmaxf(lmax, d);
        }
        #pragma unroll
        for (int off = 16; off; off >>= 1)
            lmax = fmaxf(lmax, __shfl_xor_sync(0xffffffffu, lmax, off));
        float lsum = 0.0f;
        for (int j = lane; j < Sm; j += 32) {
            float e = __expf(att[warp][j] - lmax);
            att[warp][j] = e;
            lsum += e;
        }
        #pragma unroll
        for (int off = 16; off; off >>= 1)
            lsum += __shfl_xor_sync(0xffffffffu, lsum, off);
        float inv = 1.0f / lsum;
        __syncwarp();
        {
            unsigned long long a2 = 0ull;
            const unsigned long long* vr = Vs + lane;
            for (int j = 0; j < Sm; j++) {
                float w = att[warp][j];
                a2 = fma2(pack2(w, w), vr[j * KP2], a2);
            }
            float a0, a1;
            unpack2(a2, a0, a1);
            uint32_t hi, lo;
            split_bf(a0 * inv, a1 * inv, hi, lo);
            ohi[base2 + (long)i * K2D + lane] = hi;
            olo[base2 + (long)i * K2D + lane] = lo;
        }
        __syncwarp();
    }
}

// ---------------- MoE routing ----------------
__global__ void route_kernel(const float* __restrict__ h, const float* __restrict__ wr) {
    int n = blockIdx.x;
    __shared__ float wrs[Em * Dm];
    __shared__ float tv[GSm][Km];
    __shared__ int   ti[GSm][Km];
    int tid = threadIdx.x, warp = tid >> 5, lane = tid & 31;

    for (int idx = tid; idx < Em * Dm; idx += blockDim.x) {
        int e = idx / Dm, c = idx % Dm;
        wrs[e * Dm + c] = wr[c * Em + e];
    }
    for (int s = tid; s < Em * CAPm; s += blockDim.x) {
        int e = s / CAPm, c = s % CAPm;
        g_slot_src[(e * NGm + n) * CAPm + c] = -1;
    }
    __syncthreads();

    for (int t = warp; t < GSm; t += 8) {
        const float* xr = h + (long)(n * GSm + t) * Dm;
        float a[Em];
        #pragma unroll
        for (int e = 0; e < Em; e++) a[e] = 0.0f;
        for (int c = lane; c < Dm; c += 32) {
            float xv = xr[c];
            #pragma unroll
            for (int e = 0; e < Em; e++) a[e] += xv * wrs[e * Dm + c];
        }
        #pragma unroll
        for (int e = 0; e < Em; e++)
            #pragma unroll
            for (int o = 16; o; o >>= 1) a[e] += __shfl_xor_sync(0xffffffffu, a[e], o);
        if (lane == 0) {
            float mx = a[0];
            #pragma unroll
            for (int e = 1; e < Em; e++) mx = fmaxf(mx, a[e]);
            float p[Em], sum = 0.0f;
            #pragma unroll
            for (int e = 0; e < Em; e++) { p[e] = expf(a[e] - mx); sum += p[e]; }
            float inv = 1.0f / sum;
            #pragma unroll
            for (int e = 0; e < Em; e++) p[e] *= inv;
            int i0 = 0;
            #pragma unroll
            for (int e = 1; e < Em; e++) if (p[e] > p[i0]) i0 = e;
            int i1 = (i0 == 0) ? 1 : 0;
            #pragma unroll
            for (int e = 0; e < Em; e++) if (e != i0 && p[e] > p[i1]) i1 = e;
            ti[t][0] = i0; tv[t][0] = p[i0];
            ti[t][1] = i1; tv[t][1] = p[i1];
        }
    }
    __syncthreads();

    if (tid == 0) {
        int cnt[Em];
        #pragma unroll
        for (int e = 0; e < Em; e++) cnt[e] = 0;
        for (int kk = 0; kk < Km; kk++) {
            for (int t = 0; t < GSm; t++) {
                int e = ti[t][kk];
                int pos = cnt[e]++;
                int gt = n * GSm + t;
                if (pos < CAPm) {
                    int row = (e * NGm + n) * CAPm + pos;
                    g_slot_src[row] = gt;
                    g_comb_idx[gt * Km + kk] = row;
                    g_comb_gate[gt * Km + kk] = tv[t][kk];
                } else {
                    g_comb_idx[gt * Km + kk] = -1;
                    g_comb_gate[gt * Km + kk] = 0.0f;
                }
            }
        }
    }
}

__global__ void gather_kernel(const float* __restrict__ h) {
    int i = blockIdx.x * blockDim.x + threadIdx.x;
    if (i >= TROWS * K2D) return;
    int row = i / K2D, kp = i - row * K2D;
    int src = g_slot_src[row];
    float v0 = 0.0f, v1 = 0.0f;
    if (src >= 0) {
        float2 p = *reinterpret_cast<const float2*>(h + (long)src * Dm + 2 * kp);
        v0 = p.x; v1 = p.y;
    }
    uint32_t hi, lo;
    split_bf(v0, v1, hi, lo);
    g_bf_hi[i] = hi; g_bf_lo[i] = lo;
}

__global__ void combine_kernel(float* __restrict__ x) {
    int i = blockIdx.x * blockDim.x + threadIdx.x;
    if (i >= NTOK * Dm) return;
    int t = i / Dm, c = i - t * Dm;
    float acc = 0.0f;
    #pragma unroll
    for (int kk = 0; kk < Km; kk++) {
        int r = g_comb_idx[t * Km + kk];
        if (r >= 0) acc += g_comb_gate[t * Km + kk] * g_y[(long)r * Dm + c];
    }
    x[i] += acc;
}

// ---------------- host ----------------
static inline void wsplit_t(const float* w, uint32_t* whi, uint32_t* wlo,
                            int P, int K2, int nmat) {
    dim3 g(P / 32, K2 / 32, nmat);
    wsplit_t_kernel<<<g, dim3(32, 8, 1)>>>(w, whi, wlo, P, K2,
                                           (long)2 * K2 * P, (long)P * K2);
}

extern "C" void kernel_launch(void* const* d_in, const int* in_sizes, int n_in,
                              void* d_out, int out_size) {
    (void)in_sizes; (void)n_in; (void)out_size;
    const float* in_x     = (const float*)d_in[0];
    const float* posemb   = (const float*)d_in[1];
    const float* ln1_s    = (const float*)d_in[2];
    const float* ln1_b    = (const float*)d_in[3];
    const float* wq       = (const float*)d_in[4];
    const float* bq       = (const float*)d_in[5];
    const float* wk       = (const float*)d_in[6];
    const float* bk       = (const float*)d_in[7];
    const float* wv       = (const float*)d_in[8];
    const float* bv       = (const float*)d_in[9];
    const float* wo       = (const float*)d_in[10];
    const float* bo       = (const float*)d_in[11];
    const float* ln2_s    = (const float*)d_in[12];
    const float* ln2_b    = (const float*)d_in[13];
    const float* dw1      = (const float*)d_in[14];
    const float* db1      = (const float*)d_in[15];
    const float* dw2      = (const float*)d_in[16];
    const float* db2      = (const float*)d_in[17];
    const float* router_w = (const float*)d_in[18];
    const float* mw1      = (const float*)d_in[19];
    const float* mb1      = (const float*)d_in[20];
    const float* mw2      = (const float*)d_in[21];
    const float* mb2      = (const float*)d_in[22];
    const float* out_s    = (const float*)d_in[23];
    const float* out_b    = (const float*)d_in[24];
    float* out = (float*)d_out;

    float *x, *h, *q, *k, *v, *y;
    uint32_t *h_hi, *h_lo, *ao_hi, *ao_lo, *ml_hi, *ml_lo, *bf_hi, *bf_lo, *hx_hi, *hx_lo, *whi, *wlo;
    cudaGetSymbolAddress((void**)&x,     g_x);
    cudaGetSymbolAddress((void**)&h,     g_h);
    cudaGetSymbolAddress((void**)&q,     g_q);
    cudaGetSymbolAddress((void**)&k,     g_k);
    cudaGetSymbolAddress((void**)&v,     g_v);
    cudaGetSymbolAddress((void**)&y,     g_y);
    cudaGetSymbolAddress((void**)&h_hi,  g_h_hi);
    cudaGetSymbolAddress((void**)&h_lo,  g_h_lo);
    cudaGetSymbolAddress((void**)&ao_hi, g_ao_hi);
    cudaGetSymbolAddress((void**)&ao_lo, g_ao_lo);
    cudaGetSymbolAddress((void**)&ml_hi, g_ml_hi);
    cudaGetSymbolAddress((void**)&ml_lo, g_ml_lo);
    cudaGetSymbolAddress((void**)&bf_hi, g_bf_hi);
    cudaGetSymbolAddress((void**)&bf_lo, g_bf_lo);
    cudaGetSymbolAddress((void**)&hx_hi, g_hx_hi);
    cudaGetSymbolAddress((void**)&hx_lo, g_hx_lo);
    cudaGetSymbolAddress((void**)&whi,   g_whi);
    cudaGetSymbolAddress((void**)&wlo,   g_wlo);

    const int ATTN_SMEM = 2 * Sm * KP2 * (int)sizeof(unsigned long long);
    cudaFuncSetAttribute(attn_kernel, cudaFuncAttributeMaxDynamicSharedMemorySize, ATTN_SMEM);
    cudaFuncSetAttribute(mma_gemm, cudaFuncAttributeMaxDynamicSharedMemorySize, GEMM_SMEM);

    const float qscale = 0.125f;

    addpos_kernel<<<(NTOK * Dm + 255) / 256, 256>>>(in_x, posemb, x);

    int di = 0, mi = 0;
    for (int l = 0; l < Lm; l++) {
        // ---- attention block ----
        ln_kernel<<<NTOK, 256>>>(x, nullptr, h_hi, h_lo,
                                 ln1_s + (size_t)l * Dm, ln1_b + (size_t)l * Dm);
        dim3 gdd(Dm / 128, NTOK / 128, 1);
        wsplit_t(wq + (size_t)l * Dm * Dm, whi, wlo, Dm, K2D, 1);
        mma_gemm<<<gdd, 256, GEMM_SMEM>>>(h_hi, h_lo, whi, wlo, bq + (size_t)l * Dm,
                                          q, nullptr, nullptr,
                                          NTOK, K2D, Dm, 0, 0, 0, 0, qscale, 0, 0);
        wsplit_t(wk + (size_t)l * Dm * Dm, whi, wlo, Dm, K2D, 1);
        mma_gemm<<<gdd, 256, GEMM_SMEM>>>(h_hi, h_lo, whi, wlo, bk + (size_t)l * Dm,
                                          k, nullptr, nullptr,
                                          NTOK, K2D, Dm, 0, 0, 0, 0, 1.0f, 0, 0);
        wsplit_t(wv + (size_t)l * Dm * Dm, whi, wlo, Dm, K2D, 1);
        mma_gemm<<<gdd, 256, GEMM_SMEM>>>(h_hi, h_lo, whi, wlo, bv + (size_t)l * Dm,
                                          v, nullptr, nullptr,
                                          NTOK, K2D, Dm, 0, 0, 0, 0, 1.0f, 0, 0);
        attn_kernel<<<Bm * Hh, 256, ATTN_SMEM>>>(q, k, v, ao_hi, ao_lo);
        wsplit_t(wo + (size_t)l * Dm * Dm, whi, wlo, Dm, K2D, 1);
        mma_gemm<<<gdd, 256, GEMM_SMEM>>>(ao_hi, ao_lo, whi, wlo, bo + (size_t)l * Dm,
                                          x, nullptr, nullptr,
                                          NTOK, K2D, Dm, 0, 0, 0, 0, 1.0f, 0, 1);

        // ---- mlp / moe block ----
        ln_kernel<<<NTOK, 256>>>(x, h, h_hi, h_lo,
                                 ln2_s + (size_t)l * Dm, ln2_b + (size_t)l * Dm);
        if (l & 1) {
            route_kernel<<<NGm, 256>>>(h, router_w + (size_t)mi * Dm * Em);
            gather_kernel<<<(TROWS * K2D + 255) / 256, 256>>>(h);
            wsplit_t(mw1 + (size_t)mi * Em * Dm * Mm, whi, wlo, Mm, K2D, Em);
            dim3 g1(Mm / 128, (EROWS + 127) / 128, Em);
            mma_gemm<<<g1, 256, GEMM_SMEM>>>(bf_hi, bf_lo, whi, wlo, mb1 + (size_t)mi * Em * Mm,
                                             nullptr, hx_hi, hx_lo,
                                             EROWS, K2D, Mm,
                                             (long)EROWS * K2D, (long)Mm * K2D, Mm,
                                             (long)EROWS * K2M, 1.0f, 1, 0);
            wsplit_t(mw2 + (size_t)mi * Em * Mm * Dm, whi, wlo, Dm, K2M, Em);
            dim3 g2(Dm / 128, (EROWS + 127) / 128, Em);
            mma_gemm<<<g2, 256, GEMM_SMEM>>>(hx_hi, hx_lo, whi, wlo, mb2 + (size_t)mi * Em * Dm,
                                             y, nullptr, nullptr,
                                             EROWS, K2M, Dm,
                                             (long)EROWS * K2M, (long)Dm * K2M, Dm,
                                             (long)EROWS * Dm, 1.0f, 0, 0);
            combine_kernel<<<(NTOK * Dm + 255) / 256, 256>>>(x);
            mi++;
        } else {
            wsplit_t(dw1 + (size_t)di * Dm * Mm, whi, wlo, Mm, K2D, 1);
            dim3 g1(Mm / 128, NTOK / 128, 1);
            mma_gemm<<<g1, 256, GEMM_SMEM>>>(h_hi, h_lo, whi, wlo, db1 + (size_t)di * Mm,
                                             nullptr, ml_hi, ml_lo,
                                             NTOK, K2D, Mm, 0, 0, 0, 0, 1.0f, 1, 0);
            wsplit_t(dw2 + (size_t)di * Mm * Dm, whi, wlo, Dm, K2M, 1);
            dim3 g2(Dm / 128, NTOK / 128, 1);
            mma_gemm<<<g2, 256, GEMM_SMEM>>>(ml_hi, ml_lo, whi, wlo, db2 + (size_t)di * Dm,
                                             x, nullptr, nullptr,
                                             NTOK, K2M, Dm, 0, 0, 0, 0, 1.0f, 0, 1);
            di++;
        }
    }

    ln_kernel<<<NTOK, 256>>>(x, out, nullptr, nullptr, out_s, out_b);
}

// round 15
// speedup vs baseline: 1.0830x; 1.0098x over previous
#include <cuda_runtime.h>
#include <math.h>
#include <stdint.h>

// ---------------- problem constants ----------------
#define Dm   768
#define Hh   12
#define HDm  64
#define Mm   3072
#define Lm   12
#define Em   8
#define Km   2
#define Bm   32
#define Sm   196
#define GSm  392
#define NGm  16
#define CAPm 98
#define NTOK (Bm*Sm)     // 6272
#define EROWS (NGm*CAPm) // 1568
#define TROWS (Em*EROWS) // 12544
#define K2D  (Dm/2)      // 384 k-pairs
#define K2M  (Mm/2)      // 1536 k-pairs
#define NQKV ((long)NTOK*Dm)

// ---------------- scratch ----------------
__device__ float g_x [(size_t)NTOK*Dm];
__device__ float g_h [(size_t)NTOK*Dm];
__device__ float g_qkv[(size_t)3*NTOK*Dm];
__device__ float g_y [(size_t)TROWS*Dm];
__device__ float g_bqkv[3*Dm];
// bf16-split planes (packed k-pairs: lo16 = even k, hi16 = odd k)
__device__ uint32_t g_h_hi [(size_t)NTOK*K2D],  g_h_lo [(size_t)NTOK*K2D];
__device__ uint32_t g_ao_hi[(size_t)NTOK*K2D],  g_ao_lo[(size_t)NTOK*K2D];
__device__ uint32_t g_ml_hi[(size_t)NTOK*K2M],  g_ml_lo[(size_t)NTOK*K2M];
__device__ uint32_t g_bf_hi[(size_t)(TROWS+128)*K2D], g_bf_lo[(size_t)(TROWS+128)*K2D];
__device__ uint32_t g_hx_hi[(size_t)(TROWS+128)*K2M], g_hx_lo[(size_t)(TROWS+128)*K2M];
// transposed weight planes: [P][K2]
__device__ uint32_t g_whi[(size_t)Em*K2D*Mm], g_wlo[(size_t)Em*K2D*Mm];
__device__ int   g_slot_src[TROWS];
__device__ int   g_comb_idx[NTOK*Km];
__device__ float g_comb_gate[NTOK*Km];

// ---------------- helpers ----------------
__device__ __forceinline__ float gelu_f(float x) {
    const float c = 0.7978845608028654f;
    float t = tanhf(c * (x + 0.044715f * x * x * x));
    return 0.5f * x * (1.0f + t);
}

__device__ __forceinline__ uint32_t smem_u32(const void* p) {
    uint32_t a;
    asm("{ .reg .u64 t; cvta.to.shared.u64 t, %1; cvt.u32.u64 %0, t; }" : "=r"(a) : "l"(p));
    return a;
}

__device__ __forceinline__ void cp16(uint32_t dst, const void* src, uint32_t sz) {
    asm volatile("cp.async.ca.shared.global [%0], [%1], 16, %2;"
                 :: "r"(dst), "l"(src), "r"(sz));
}
#define CP_COMMIT() asm volatile("cp.async.commit_group;" ::: "memory")
#define CP_WAIT(n)  asm volatile("cp.async.wait_group %0;" :: "n"(n) : "memory")

__device__ __forceinline__ void mma16(float* c, const uint32_t* a, const uint32_t* b) {
    asm volatile(
        "mma.sync.aligned.m16n8k16.row.col.f32.bf16.bf16.f32 "
        "{%0,%1,%2,%3},{%4,%5,%6,%7},{%8,%9},{%0,%1,%2,%3};"
        : "+f"(c[0]), "+f"(c[1]), "+f"(c[2]), "+f"(c[3])
        : "r"(a[0]), "r"(a[1]), "r"(a[2]), "r"(a[3]), "r"(b[0]), "r"(b[1]));
}

__device__ __forceinline__ void ldsm4(uint32_t& r0, uint32_t& r1, uint32_t& r2, uint32_t& r3,
                                      uint32_t addr) {
    asm volatile("ldmatrix.sync.aligned.m8n8.x4.shared.b16 {%0,%1,%2,%3}, [%4];"
                 : "=r"(r0), "=r"(r1), "=r"(r2), "=r"(r3) : "r"(addr));
}

// packed f32x2 helpers
__device__ __forceinline__ unsigned long long pack2(float x, float y) {
    unsigned long long r;
    asm("mov.b64 %0, {%1, %2};" : "=l"(r) : "f"(x), "f"(y));
    return r;
}
__device__ __forceinline__ void unpack2(unsigned long long v, float& x, float& y) {
    asm("mov.b64 {%0, %1}, %2;" : "=f"(x), "=f"(y) : "l"(v));
}
__device__ __forceinline__ unsigned long long fma2(unsigned long long a,
                                                   unsigned long long b,
                                                   unsigned long long c) {
    unsigned long long d;
    asm("fma.rn.f32x2 %0, %1, %2, %3;" : "=l"(d) : "l"(a), "l"(b), "l"(c));
    return d;
}

// pack two floats (x0=even k -> lo16, x1=odd k -> hi16)
__device__ __forceinline__ uint32_t packbf(float x1, float x0) {
    uint32_t d;
    asm("cvt.rn.bf16x2.f32 %0, %1, %2;" : "=r"(d) : "f"(x1), "f"(x0));
    return d;
}
// bf16 split: (x0,x1) -> hi pair + lo pair (exact residual split)
__device__ __forceinline__ void split_bf(float x0, float x1, uint32_t& hi, uint32_t& lo) {
    hi = packbf(x1, x0);
    float h0 = __uint_as_float(hi << 16);
    float h1 = __uint_as_float(hi & 0xFFFF0000u);
    lo = packbf(x1 - h1, x0 - h0);
}

// ---------------- transposing weight split: W[Kd][P] -> planes [P][K2] ------
__global__ void wsplit_t_kernel(const float* __restrict__ w, uint32_t* __restrict__ whi,
                                uint32_t* __restrict__ wlo, int P, int K2,
                                long wstride, long ostride) {
    int z = blockIdx.z;
    w += (long)z * wstride; whi += (long)z * ostride; wlo += (long)z * ostride;
    __shared__ uint32_t shi[32][33], slo[32][33];
    int n0 = blockIdx.x * 32, k20 = blockIdx.y * 32;
    int tx = threadIdx.x, ty = threadIdx.y;   // block (32,8)
    #pragma unroll
    for (int rr = ty; rr < 32; rr += 8) {
        int k2 = k20 + rr;
        float v0 = w[(long)(2 * k2) * P + n0 + tx];
        float v1 = w[(long)(2 * k2 + 1) * P + n0 + tx];
        uint32_t hi, lo;
        split_bf(v0, v1, hi, lo);
        shi[rr][tx] = hi; slo[rr][tx] = lo;
    }
    __syncthreads();
    #pragma unroll
    for (int cc = ty; cc < 32; cc += 8) {
        whi[(long)(n0 + cc) * K2 + k20 + tx] = shi[tx][cc];
        wlo[(long)(n0 + cc) * K2 + k20 + tx] = slo[tx][cc];
    }
}

// fused QKV split: 3 source matrices [Dm][Dm] -> one [3*Dm][K2D] plane pair
__global__ void wsplit_qkv_kernel(const float* __restrict__ wq, const float* __restrict__ wk,
                                  const float* __restrict__ wv,
                                  uint32_t* __restrict__ whi, uint32_t* __restrict__ wlo) {
    int z = blockIdx.z;   // 0=q 1=k 2=v
    const float* w = (z == 0) ? wq : (z == 1) ? wk : wv;
    __shared__ uint32_t shi[32][33], slo[32][33];
    int n0 = blockIdx.x * 32, k20 = blockIdx.y * 32;
    int tx = threadIdx.x, ty = threadIdx.y;
    #pragma unroll
    for (int rr = ty; rr < 32; rr += 8) {
        int k2 = k20 + rr;
        float v0 = w[(long)(2 * k2) * Dm + n0 + tx];
        float v1 = w[(long)(2 * k2 + 1) * Dm + n0 + tx];
        uint32_t hi, lo;
        split_bf(v0, v1, hi, lo);
        shi[rr][tx] = hi; slo[rr][tx] = lo;
    }
    __syncthreads();
    long rbase = (long)z * Dm;
    #pragma unroll
    for (int cc = ty; cc < 32; cc += 8) {
        whi[(rbase + n0 + cc) * K2D + k20 + tx] = shi[tx][cc];
        wlo[(rbase + n0 + cc) * K2D + k20 + tx] = slo[tx][cc];
    }
}

__global__ void biaspack_kernel(const float* __restrict__ bq, const float* __restrict__ bk,
                                const float* __restrict__ bv, float* __restrict__ out) {
    int i = blockIdx.x * blockDim.x + threadIdx.x;
    if (i < Dm) { out[i] = bq[i]; out[Dm + i] = bk[i]; out[2 * Dm + i] = bv[i]; }
}

// ---------------- 3xBF16 GEMM (ldmatrix fragments, K=32 chunks) ------------
#define KCH 16
#define AST 20
#define BST 20
#define A_PLANE (128*AST)   // 2560 u32
#define B_PLANE (128*BST)   // 2560 u32
#define GEMM_SMEM ((4*A_PLANE + 4*B_PLANE)*4)   // 81920 bytes

__global__ void __launch_bounds__(256, 2)
mma_gemm(const uint32_t* __restrict__ Ahi, const uint32_t* __restrict__ Alo,
         const uint32_t* __restrict__ Whi, const uint32_t* __restrict__ Wlo,
         const float* __restrict__ bias,
         float* __restrict__ Cf, uint32_t* __restrict__ Chi, uint32_t* __restrict__ Clo,
         int Nrows, int K2, int Pc,
         long strA, long strW, long strBias, long strC,
         float alpha, int act, int accum, int qkv) {
    int z = blockIdx.z;
    Ahi += (long)z * strA; Alo += (long)z * strA;
    Whi += (long)z * strW; Wlo += (long)z * strW;
    const float* Bp = bias + (long)z * strBias;

    extern __shared__ uint32_t smw[];
    uint32_t* sAhi = smw;
    uint32_t* sAlo = smw + 2 * A_PLANE;
    uint32_t* sBhi = smw + 4 * A_PLANE;
    uint32_t* sBlo = smw + 4 * A_PLANE + 2 * B_PLANE;

    int tid = threadIdx.x;
    int row0 = blockIdx.y * 128, col0 = blockIdx.x * 128;

    int ar = tid >> 1, ako = (tid & 1) * 8;
    const uint32_t* gAhi = Ahi + (long)(row0 + ar) * K2 + ako;
    const uint32_t* gAlo = Alo + (long)(row0 + ar) * K2 + ako;
    const uint32_t* gBhi = Whi + (long)(col0 + ar) * K2 + ako;
    const uint32_t* gBlo = Wlo + (long)(col0 + ar) * K2 + ako;
    uint32_t asz = ((row0 + ar) < Nrows) ? 16u : 0u;
    uint32_t dAhi = smem_u32(sAhi) + (uint32_t)(ar * AST + ako) * 4u;
    uint32_t dAlo = smem_u32(sAlo) + (uint32_t)(ar * AST + ako) * 4u;
    uint32_t dBhi = smem_u32(sBhi) + (uint32_t)(ar * BST + ako) * 4u;
    uint32_t dBlo = smem_u32(sBlo) + (uint32_t)(ar * BST + ako) * 4u;

    int nk = K2 / KCH;

    cp16(dAhi, gAhi, asz); cp16(dAhi + 16, gAhi + 4, asz);
    cp16(dAlo, gAlo, asz); cp16(dAlo + 16, gAlo + 4, asz);
    cp16(dBhi, gBhi, 16);  cp16(dBhi + 16, gBhi + 4, 16);
    cp16(dBlo, gBlo, 16);  cp16(dBlo + 16, gBlo + 4, 16);
    CP_COMMIT();

    int warp = tid >> 5, lane = tid & 31;
    int wm = (warp & 3) * 32, wn = (warp >> 2) * 64;
    int gid = lane >> 2, tig = lane & 3;

    int l16 = lane & 15, kh4 = (lane >> 4) * 4;
    uint32_t fAhi = smem_u32(sAhi), fAlo = smem_u32(sAlo);
    uint32_t fBhi = smem_u32(sBhi), fBlo = smem_u32(sBlo);
    uint32_t aRow = (uint32_t)((wm + l16) * AST + kh4);
    uint32_t bRow = (uint32_t)((wn + l16) * BST + kh4);

    float acc[2][8][4];
    #pragma unroll
    for (int mt = 0; mt < 2; mt++)
        #pragma unroll
        for (int nt = 0; nt < 8; nt++)
            #pragma unroll
            for (int r = 0; r < 4; r++) acc[mt][nt][r] = 0.0f;

    for (int i = 0; i < nk; i++) {
        int b = i & 1;
        if (i + 1 < nk) {
            int nb = b ^ 1;
            const uint32_t* pah = gAhi + (i + 1) * KCH;
            const uint32_t* pal = gAlo + (i + 1) * KCH;
            const uint32_t* pbh = gBhi + (i + 1) * KCH;
            const uint32_t* pbl = gBlo + (i + 1) * KCH;
            uint32_t oA = (uint32_t)(nb * A_PLANE) * 4u;
            uint32_t oB = (uint32_t)(nb * B_PLANE) * 4u;
            cp16(dAhi + oA, pah, asz); cp16(dAhi + oA + 16, pah + 4, asz);
            cp16(dAlo + oA, pal, asz); cp16(dAlo + oA + 16, pal + 4, asz);
            cp16(dBhi + oB, pbh, 16);  cp16(dBhi + oB + 16, pbh + 4, 16);
            cp16(dBlo + oB, pbl, 16);  cp16(dBlo + oB + 16, pbl + 4, 16);
            CP_COMMIT();
            CP_WAIT(1);
        } else {
            CP_WAIT(0);
        }
        __syncthreads();

        uint32_t baseA = (uint32_t)(b * A_PLANE) * 4u;
        uint32_t baseB = (uint32_t)(b * B_PLANE) * 4u;
        #pragma unroll
        for (int ks = 0; ks < 2; ks++) {
            int kq = ks * 8;
            uint32_t afh[2][4], afl[2][4];
            #pragma unroll
            for (int mt = 0; mt < 2; mt++) {
                uint32_t off = (aRow + (uint32_t)(mt * 16 * AST + kq)) * 4u;
                ldsm4(afh[mt][0], afh[mt][1], afh[mt][2], afh[mt][3], fAhi + baseA + off);
                ldsm4(afl[mt][0], afl[mt][1], afl[mt][2], afl[mt][3], fAlo + baseA + off);
            }
            #pragma unroll
            for (int np_ = 0; np_ < 4; np_++) {
                int nt0 = np_ * 2, nt1 = nt0 + 1;
                uint32_t off = (bRow + (uint32_t)(np_ * 16 * BST + kq)) * 4u;
                uint32_t bh[4], bl[4];
                ldsm4(bh[0], bh[1], bh[2], bh[3], fBhi + baseB + off);
                ldsm4(bl[0], bl[1], bl[2], bl[3], fBlo + baseB + off);
                uint32_t b0h[2] = { bh[0], bh[2] }, b1h[2] = { bh[1], bh[3] };
                uint32_t b0l[2] = { bl[0], bl[2] }, b1l[2] = { bl[1], bl[3] };
                mma16(acc[0][nt0], afh[0], b0l);
                mma16(acc[1][nt0], afh[1], b0l);
                mma16(acc[0][nt1], afh[0], b1l);
                mma16(acc[1][nt1], afh[1], b1l);
                mma16(acc[0][nt0], afl[0], b0h);
                mma16(acc[1][nt0], afl[1], b0h);
                mme_pass3:
                mma16(acc[0][nt1], afl[0], b1h);
                mma16(acc[1][nt1], afl[1], b1h);
                mma16(acc[0][nt0], afh[0], b0h);
                mma16(acc[1][nt0], afh[1], b0h);
                mma16(acc[0][nt1], afh[0], b1h);
                mma16(acc[1][nt1], afh[1], b1h);
            }
        }
        __syncthreads();
    }

    // epilogue
    int P2 = Pc >> 1;
    #pragma unroll
    for (int mt = 0; mt < 2; mt++) {
        int r0 = row0 + wm + mt * 16 + gid;
        #pragma unroll
        for (int half = 0; half < 2; half++) {
            int gr = r0 + half * 8;
            if (gr >= Nrows) continue;
            #pragma unroll
            for (int nt = 0; nt < 8; nt++) {
                int gc = col0 + wn + nt * 8 + 2 * tig;
                float2 bv = *reinterpret_cast<const float2*>(Bp + gc);
                float v0, v1;
                if (qkv) {
                    int band = gc / Dm;
                    int cc = gc - band * Dm;
                    float a = (band == 0) ? alpha : 1.0f;
                    v0 = (acc[mt][nt][half * 2 + 0] + bv.x) * a;
                    v1 = (acc[mt][nt][half * 2 + 1] + bv.y) * a;
                    float* Cp = Cf + (long)band * strC + (long)gr * Dm + cc;
                    *reinterpret_cast<float2*>(Cp) = make_float2(v0, v1);
                    continue;
                }
                v0 = (acc[mt][nt][half * 2 + 0] + bv.x) * alpha;
                v1 = (acc[mt][nt][half * 2 + 1] + bv.y) * alpha;
                if (act) { v0 = gelu_f(v0); v1 = gelu_f(v1); }
                if (Chi) {
                    long o = (long)z * strC + (long)gr * P2 + (gc >> 1);
                    uint32_t hi, lo;
                    split_bf(v0, v1, hi, lo);
                    Chi[o] = hi; Clo[o] = lo;
                } else {
                    float* Cp = Cf + (long)z * strC + (long)gr * Pc + gc;
                    if (accum) {
                        float2 o = *reinterpret_cast<float2*>(Cp);
                        v0 += o.x; v1 += o.y;
                    }
                    *reinterpret_cast<float2*>(Cp) = make_float2(v0, v1);
                }
            }
        }
    }
}

// ---------------- elementwise ----------------
__global__ void addpos_kernel(const float* __restrict__ x, const float* __restrict__ pe,
                              float* __restrict__ out) {
    int i = blockIdx.x * blockDim.x + threadIdx.x;
    if (i < NTOK * Dm) out[i] = x[i] + pe[i % (Sm * Dm)];
}

__device__ __forceinline__ float block_reduce_sum(float v) {
    __shared__ float sh[33];
    int lane = threadIdx.x & 31, w = threadIdx.x >> 5;
    #pragma unroll
    for (int o = 16; o; o >>= 1) v += __shfl_xor_sync(0xffffffffu, v, o);
    if (lane == 0) sh[w] = v;
    __syncthreads();
    int nw = blockDim.x >> 5;
    float r = (threadIdx.x < nw) ? sh[threadIdx.x] : 0.0f;
    if (w == 0) {
        #pragma unroll
        for (int o = 16; o; o >>= 1) r += __shfl_xor_sync(0xffffffffu, r, o);
        if (lane == 0) sh[32] = r;
    }
    __syncthreads();
    float out = sh[32];
    __syncthreads();
    return out;
}

__global__ void ln_kernel(const float* __restrict__ in, float* __restrict__ outf,
                          uint32_t* __restrict__ ohi, uint32_t* __restrict__ olo,
                          const float* __restrict__ s, const float* __restrict__ b) {
    int t = blockIdx.x;
    const float* xr = in + (size_t)t * Dm;
    float sum = 0.0f;
    for (int i = threadIdx.x; i < Dm; i += blockDim.x) sum += xr[i];
    float mu = block_reduce_sum(sum) * (1.0f / Dm);
    float vs = 0.0f;
    for (int i = threadIdx.x; i < Dm; i += blockDim.x) { float d = xr[i] - mu; vs += d * d; }
    float var = block_reduce_sum(vs) * (1.0f / Dm);
    float inv = rsqrtf(var + 1e-6f);
    for (int i = threadIdx.x * 2; i < Dm; i += blockDim.x * 2) {
        float v0 = (xr[i] - mu) * inv * s[i] + b[i];
        float v1 = (xr[i + 1] - mu) * inv * s[i + 1] + b[i + 1];
        if (outf) { outf[(size_t)t * Dm + i] = v0; outf[(size_t)t * Dm + i + 1] = v1; }
        if (ohi) {
            uint32_t hi, lo;
            split_bf(v0, v1, hi, lo);
            ohi[(size_t)t * K2D + (i >> 1)] = hi;
            olo[(size_t)t * K2D + (i >> 1)] = lo;
        }
    }
}

// ---------------- attention (f32x2-vectorized; writes bf16-split planes) ----
#define KP2 33
__global__ void attn_kernel(const float* __restrict__ q, const float* __restrict__ k,
                            const float* __restrict__ v,
                            uint32_t* __restrict__ ohi, uint32_t* __restrict__ olo) {
    extern __shared__ unsigned long long sm64[];
    unsigned long long* Ks = sm64;
    unsigned long long* Vs = sm64 + Sm * KP2;
    __shared__ float att[8][Sm];
    __shared__ unsigned long long qrow[8][32];

    int bh = blockIdx.x;
    int b = bh / Hh, h = bh % Hh;
    int tid = threadIdx.x, warp = tid >> 5, lane = tid & 31;
    const long base = (long)(b * Sm) * Dm + h * HDm;
    const long base2 = (long)(b * Sm) * K2D + h * (HDm / 2);

    for (int idx = tid; idx < Sm * 32; idx += blockDim.x) {
        int j = idx >> 5, c2 = idx & 31;
        float2 kk = *reinterpret_cast<const float2*>(k + base + (long)j * Dm + 2 * c2);
        float2 vv = *reinterpret_cast<const float2*>(v + base + (long)j * Dm + 2 * c2);
        Ks[j * KP2 + c2] = pack2(kk.x, kk.y);
        Vs[j * KP2 + c2] = pack2(vv.x, vv.y);
    }
    __syncthreads();

    for (int i = warp; i < Sm; i += 8) {
        {
            float2 qq = *reinterpret_cast<const float2*>(q + base + (long)i * Dm + 2 * lane);
            qrow[warp][lane] = pack2(qq.x, qq.y);
        }
        __syncwarp();
        float lmax = -1e30f;
        for (int j = lane; j < Sm; j += 32) {
            unsigned long long a2 = 0ull;
            const unsigned long long* kr = Ks + j * KP2;
            #pragma unroll
            for (int c2 = 0; c2 < 32; c2++)
                a2 = fma2(qrow[warp][c2], kr[c2], a2);
            float s0, s1;
            unpack2(a2, s0, s1);
            float d = s0 + s1;
            att[warp][j] = d;
            lmax = fmaxf(lmax, d);
        }
        #pragma unroll
        for (int off = 16; off; off >>= 1)
            lmax = fmaxf(lmax, __shfl_xor_sync(0xffffffffu, lmax, off));
        float lsum = 0.0f;
        for (int j = lane; j < Sm; j += 32) {
            float e = __expf(att[warp][j] - lmax);
            att[warp][j] = e;
            lsum += e;
        }
        #pragma unroll
        for (int off = 16; off; off >>= 1)
            lsum += __shfl_xor_sync(0xffffffffu, lsum, off);
        float inv = 1.0f / lsum;
        __syncwarp();
        {
            unsigned long long a2 = 0ull;
            const unsigned long long* vr = Vs + lane;
            for (int j = 0; j < Sm; j++) {
                float w = att[warp][j];
                a2 = fma2(pack2(w, w), vr[j * KP2], a2);
            }
            float a0, a1;
            unpack2(a2, a0, a1);
            uint32_t hi, lo;
            split_bf(a0 * inv, a1 * inv, hi, lo);
            ohi[base2 + (long)i * K2D + lane] = hi;
            olo[base2 + (long)i * K2D + lane] = lo;
        }
        __syncwarp();
    }
}

// ---------------- MoE routing ----------------
__global__ void route_kernel(const float* __restrict__ h, const float* __restrict__ wr) {
    int n = blockIdx.x;
    __shared__ float wrs[Em * Dm];
    __shared__ float tv[GSm][Km];
    __shared__ int   ti[GSm][Km];
    int tid = threadIdx.x, warp = tid >> 5, lane = tid & 31;

    for (int idx = tid; idx < Em * Dm; idx += blockDim.x) {
        int e = idx / Dm, c = idx % Dm;
        wrs[e * Dm + c] = wr[c * Em + e];
    }
    for (int s = tid; s < Em * CAPm; s += blockDim.x) {
        int e = s / CAPm, c = s % CAPm;
        g_slot_src[(e * NGm + n) * CAPm + c] = -1;
    }
    __syncthreads();

    for (int t = warp; t < GSm; t += 8) {
        const float* xr = h + (long)(n * GSm + t) * Dm;
        float a[Em];
        #pragma unroll
        for (int e = 0; e < Em; e++) a[e] = 0.0f;
        for (int c = lane; c < Dm; c += 32) {
            float xv = xr[c];
            #pragma unroll
            for (int e = 0; e < Em; e++) a[e] += xv * wrs[e * Dm + c];
        }
        #pragma unroll
        for (int e = 0; e < Em; e++)
            #pragma unroll
            for (int o = 16; o; o >>= 1) a[e] += __shfl_xor_sync(0xffffffffu, a[e], o);
        if (lane == 0) {
            float mx = a[0];
            #pragma unroll
            for (int e = 1; e < Em; e++) mx = fmaxf(mx, a[e]);
            float p[Em], sum = 0.0f;
            #pragma unroll
            for (int e = 0; e < Em; e++) { p[e] = expf(a[e] - mx); sum += p[e]; }
            float inv = 1.0f / sum;
            #pragma unroll
            for (int e = 0; e < Em; e++) p[e] *= inv;
            int i0 = 0;
            #pragma unroll
            for (int e = 1; e < Em; e++) if (p[e] > p[i0]) i0 = e;
            int i1 = (i0 == 0) ? 1 : 0;
            #pragma unroll
            for (int e = 0; e < Em; e++) if (e != i0 && p[e] > p[i1]) i1 = e;
            ti[t][0] = i0; tv[t][0] = p[i0];
            ti[t][1] = i1; tv[t][1] = p[i1];
        }
    }
    __syncthreads();

    if (tid == 0) {
        int cnt[Em];
        #pragma unroll
        for (int e = 0; e < Em; e++) cnt[e] = 0;
        for (int kk = 0; kk < Km; kk++) {
            for (int t = 0; t < GSm; t++) {
                int e = ti[t][kk];
                int pos = cnt[e]++;
                int gt = n * GSm + t;
                if (pos < CAPm) {
                    int row = (e * NGm + n) * CAPm + pos;
                    g_slot_src[row] = gt;
                    g_comb_idx[gt * Km + kk] = row;
                    g_comb_gate[gt * Km + kk] = tv[t][kk];
                } else {
                    g_comb_idx[gt * Km + kk] = -1;
                    g_comb_gate[gt * Km + kk] = 0.0f;
                }
            }
        }
    }
}

__global__ void gather_kernel(const float* __restrict__ h) {
    int i = blockIdx.x * blockDim.x + threadIdx.x;
    if (i >= TROWS * K2D) return;
    int row = i / K2D, kp = i - row * K2D;
    int src = g_slot_src[row];
    float v0 = 0.0f, v1 = 0.0f;
    if (src >= 0) {
        float2 p = *reinterpret_cast<const float2*>(h + (long)src * Dm + 2 * kp);
        v0 = p.x; v1 = p.y;
    }
    uint32_t hi, lo;
    split_bf(v0, v1, hi, lo);
    g_bf_hi[i] = hi; g_bf_lo[i] = lo;
}

__global__ void combine_kernel(float* __restrict__ x) {
    int i = blockIdx.x * blockDim.x + threadIdx.x;
    if (i >= NTOK * Dm) return;
    int t = i / Dm, c = i - t * Dm;
    float acc = 0.0f;
    #pragma unroll
    for (int kk = 0; kk < Km; kk++) {
        int r = g_comb_idx[t * Km + kk];
        if (r >= 0) acc += g_comb_gate[t * Km + kk] * g_y[(long)r * Dm + c];
    }
    x[i] += acc;
}

// ---------------- host ----------------
static inline void wsplit_t(const float* w, uint32_t* whi, uint32_t* wlo,
                            int P, int K2, int nmat) {
    dim3 g(P / 32, K2 / 32, nmat);
    wsplit_t_kernel<<<g, dim3(32, 8, 1)>>>(w, whi, wlo, P, K2,
                                           (long)2 * K2 * P, (long)P * K2);
}

extern "C" void kernel_launch(void* const* d_in, const int* in_sizes, int n_in,
                              void* d_out, int out_size) {
    (void)in_sizes; (void)n_in; (void)out_size;
    const float* in_x     = (const float*)d_in[0];
    const float* posemb   = (const float*)d_in[1];
    const float* ln1_s    = (const float*)d_in[2];
    const float* ln1_b    = (const float*)d_in[3];
    const float* wq       = (const float*)d_in[4];
    const float* bq       = (const float*)d_in[5];
    const float* wk       = (const float*)d_in[6];
    const float* bk       = (const float*)d_in[7];
    const float* wv       = (const float*)d_in[8];
    const float* bv       = (const float*)d_in[9];
    const float* wo       = (const float*)d_in[10];
    const float* bo       = (const float*)d_in[11];
    const float* ln2_s    = (const float*)d_in[12];
    const float* ln2_b    = (const float*)d_in[13];
    const float* dw1      = (const float*)d_in[14];
    const float* db1      = (const float*)d_in[15];
    const float* dw2      = (const float*)d_in[16];
    const float* db2      = (const float*)d_in[17];
    const float* router_w = (const float*)d_in[18];
    const float* mw1      = (const float*)d_in[19];
    const float* mb1      = (const float*)d_in[20];
    const float* mw2      = (const float*)d_in[21];
    const float* mb2      = (const float*)d_in[22];
    const float* out_s    = (const float*)d_in[23];
    const float* out_b    = (const float*)d_in[24];
    float* out = (float*)d_out;

    float *x, *h, *qkv, *y, *bqkv;
    uint32_t *h_hi, *h_lo, *ao_hi, *ao_lo, *ml_hi, *ml_lo, *bf_hi, *bf_lo, *hx_hi, *hx_lo, *whi, *wlo;
    cudaGetSymbolAddress((void**)&x,     g_x);
    cudaGetSymbolAddress((void**)&h,     g_h);
    cudaGetSymbolAddress((void**)&qkv,   g_qkv);
    cudaGetSymbolAddress((void**)&y,     g_y);
    cudaGetSymbolAddress((void**)&bqkv,  g_bqkv);
    cudaGetSymbolAddress((void**)&h_hi,  g_h_hi);
    cudaGetSymbolAddress((void**)&h_lo,  g_h_lo);
    cudaGetSymbolAddress((void**)&ao_hi, g_ao_hi);
    cudaGetSymbolAddress((void**)&ao_lo, g_ao_lo);
    cudaGetSymbolAddress((void**)&ml_hi, g_ml_hi);
    cudaGetSymbolAddress((void**)&ml_lo, g_ml_lo);
    cudaGetSymbolAddress((void**)&bf_hi, g_bf_hi);
    cudaGetSymbolAddress((void**)&bf_lo, g_bf_lo);
    cudaGetSymbolAddress((void**)&hx_hi, g_hx_hi);
    cudaGetSymbolAddress((void**)&hx_lo, g_hx_lo);
    cudaGetSymbolAddress((void**)&whi,   g_whi);
    cudaGetSymbolAddress((void**)&wlo,   g_wlo);

    float* q = qkv;
    float* k = qkv + NQKV;
    float* v = qkv + 2 * NQKV;

    const int ATTN_SMEM = 2 * Sm * KP2 * (int)sizeof(unsigned long long);
    cudaFuncSetAttribute(attn_kernel, cudaFuncAttributeMaxDynamicSharedMemorySize, ATTN_SMEM);
    cudaFuncSetAttribute(mma_gemm, cudaFuncAttributeMaxDynamicSharedMemorySize, GEMM_SMEM);

    const float qscale = 0.125f;

    addpos_kernel<<<(NTOK * Dm + 255) / 256, 256>>>(in_x, posemb, x);

    int di = 0, mi = 0;
    for (int l = 0; l < Lm; l++) {
        // ---- attention block ----
        ln_kernel<<<NTOK, 256>>>(x, nullptr, h_hi, h_lo,
                                 ln1_s + (size_t)l * Dm, ln1_b + (size_t)l * Dm);
        // fused QKV: weights -> [3*Dm][K2D] planes, bias -> [3*Dm]
        {
            dim3 gs(Dm / 32, K2D / 32, 3);
            wsplit_qkv_kernel<<<gs, dim3(32, 8, 1)>>>(wq + (size_t)l * Dm * Dm,
                                                      wk + (size_t)l * Dm * Dm,
                                                      wv + (size_t)l * Dm * Dm, whi, wlo);
            biaspack_kernel<<<3, 256>>>(bq + (size_t)l * Dm, bk + (size_t)l * Dm,
                                        bv + (size_t)l * Dm, bqkv);
            dim3 gq(3 * Dm / 128, NTOK / 128, 1);   // 18, 49
            mma_gemm<<<gq, 256, GEMM_SMEM>>>(h_hi, h_lo, whi, wlo, bqkv,
                                             qkv, nullptr, nullptr,
                                             NTOK, K2D, 3 * Dm, 0, 0, 0, NQKV,
                                             qscale, 0, 0, 1);
        }
        attn_kernel<<<Bm * Hh, 256, ATTN_SMEM>>>(q, k, v, ao_hi, ao_lo);
        wsplit_t(wo + (size_t)l * Dm * Dm, whi, wlo, Dm, K2D, 1);
        dim3 gdd(Dm / 128, NTOK / 128, 1);
        mma_gemm<<<gdd, 256, GEMM_SMEM>>>(ao_hi, ao_lo, whi, wlo, bo + (size_t)l * Dm,
                                          x, nullptr, nullptr,
                                          NTOK, K2D, Dm, 0, 0, 0, 0, 1.0f, 0, 1, 0);

        // ---- mlp / moe block ----
        ln_kernel<<<NTOK, 256>>>(x, h, h_hi, h_lo,
                                 ln2_s + (size_t)l * Dm, ln2_b + (size_t)l * Dm);
        if (l & 1) {
            route_kernel<<<NGm, 256>>>(h, router_w + (size_t)mi * Dm * Em);
            gather_kernel<<<(TROWS * K2D + 255) / 256, 256>>>(h);
            wsplit_t(mw1 + (size_t)mi * Em * Dm * Mm, whi, wlo, Mm, K2D, Em);
            dim3 g1(Mm / 128, (EROWS + 127) / 128, Em);
            mma_gemm<<<g1, 256, GEMM_SMEM>>>(bf_hi, bf_lo, whi, wlo, mb1 + (size_t)mi * Em * Mm,
                                             nullptr, hx_hi, hx_lo,
                                             EROWS, K2D, Mm,
                                             (long)EROWS * K2D, (long)Mm * K2D, Mm,
                                             (long)EROWS * K2M, 1.0f, 1, 0, 0);
            wsplit_t(mw2 + (size_t)mi * Em * Mm * Dm, whi, wlo, Dm, K2M, Em);
            dim3 g2(Dm / 128, (EROWS + 127) / 128, Em);
            mma_gemm<<<g2, 256, GEMM_SMEM>>>(hx_hi, hx_lo, whi, wlo, mb2 + (size_t)mi * Em * Dm,
                                             y, nullptr, nullptr,
                                             EROWS, K2M, Dm,
                                             (long)EROWS * K2M, (long)Dm * K2M, Dm,
                                             (long)EROWS * Dm, 1.0f, 0, 0, 0);
            combine_kernel<<<(NTOK * Dm + 255) / 256, 256>>>(x);
            mi++;
        } else {
            wsplit_t(dw1 + (size_t)di * Dm * Mm, whi, wlo, Mm, K2D, 1);
            dim3 g1(Mm / 128, NTOK / 128, 1);
            mma_gemm<<<g1, 256, GEMM_SMEM>>>(h_hi, h_lo, whi, wlo, db1 + (size_t)di * Mm,
                                             nullptr, ml_hi, ml_lo,
                                             NTOK, K2D, Mm, 0, 0, 0, 0, 1.0f, 1, 0, 0);
            wsplit_t(dw2 + (size_t)di * Mm * Dm, whi, wlo, Dm, K2M, 1);
            dim3 g2(Dm / 128, NTOK / 128, 1);
            mma_gemm<<<g2, 256, GEMM_SMEM>>>(ml_hi, ml_lo, whi, wlo, db2 + (size_t)di * Dm,
                                             x, nullptr, nullptr,
                                             NTOK, K2M, Dm, 0, 0, 0, 0, 1.0f, 0, 1, 0);
            di++;
        }
    }

    ln_kernel<<<NTOK, 256>>>(x, out, nullptr, nullptr, out_s, out_b);
}

// round 16
// speedup vs baseline: 1.0891x; 1.0056x over previous
#include <cuda_runtime.h>
#include <math.h>
#include <stdint.h>

// ---------------- problem constants ----------------
#define Dm   768
#define Hh   12
#define HDm  64
#define Mm   3072
#define Lm   12
#define Em   8
#define Km   2
#define Bm   32
#define Sm   196
#define GSm  392
#define NGm  16
#define CAPm 98
#define NTOK (Bm*Sm)     // 6272
#define EROWS (NGm*CAPm) // 1568
#define TROWS (Em*EROWS) // 12544
#define K2D  (Dm/2)      // 384 k-pairs
#define K2M  (Mm/2)      // 1536 k-pairs
#define NQKV ((long)NTOK*Dm)
#define NDL  6           // dense layers
#define NML  6           // moe layers

// ---------------- scratch ----------------
__device__ float g_x [(size_t)NTOK*Dm];
__device__ float g_h [(size_t)NTOK*Dm];
__device__ float g_qkv[(size_t)3*NTOK*Dm];
__device__ float g_y [(size_t)TROWS*Dm];
__device__ float g_bqkv[(size_t)Lm*3*Dm];
// bf16-split activation planes
__device__ uint32_t g_h_hi [(size_t)NTOK*K2D],  g_h_lo [(size_t)NTOK*K2D];
__device__ uint32_t g_ao_hi[(size_t)NTOK*K2D],  g_ao_lo[(size_t)NTOK*K2D];
__device__ uint32_t g_ml_hi[(size_t)NTOK*K2M],  g_ml_lo[(size_t)NTOK*K2M];
__device__ uint32_t g_bf_hi[(size_t)(TROWS+128)*K2D], g_bf_lo[(size_t)(TROWS+128)*K2D];
__device__ uint32_t g_hx_hi[(size_t)(TROWS+128)*K2M], g_hx_lo[(size_t)(TROWS+128)*K2M];
// pre-split transposed weight planes (all layers)
__device__ uint32_t g_wat_hi[(size_t)Lm*4*Dm*K2D], g_wat_lo[(size_t)Lm*4*Dm*K2D];
__device__ uint32_t g_wd1_hi[(size_t)NDL*Mm*K2D],  g_wd1_lo[(size_t)NDL*Mm*K2D];
__device__ uint32_t g_wd2_hi[(size_t)NDL*Dm*K2M],  g_wd2_lo[(size_t)NDL*Dm*K2M];
__device__ uint32_t g_wm1_hi[(size_t)NML*Em*Mm*K2D], g_wm1_lo[(size_t)NML*Em*Mm*K2D];
__device__ uint32_t g_wm2_hi[(size_t)NML*Em*Dm*K2M], g_wm2_lo[(size_t)NML*Em*Dm*K2M];
__device__ int   g_slot_src[TROWS];
__device__ int   g_comb_idx[NTOK*Km];
__device__ float g_comb_gate[NTOK*Km];

// ---------------- helpers ----------------
__device__ __forceinline__ float gelu_f(float x) {
    const float c = 0.7978845608028654f;
    float t = tanhf(c * (x + 0.044715f * x * x * x));
    return 0.5f * x * (1.0f + t);
}

__device__ __forceinline__ uint32_t smem_u32(const void* p) {
    uint32_t a;
    asm("{ .reg .u64 t; cvta.to.shared.u64 t, %1; cvt.u32.u64 %0, t; }" : "=r"(a) : "l"(p));
    return a;
}

__device__ __forceinline__ void cp16(uint32_t dst, const void* src, uint32_t sz) {
    asm volatile("cp.async.ca.shared.global [%0], [%1], 16, %2;"
                 :: "r"(dst), "l"(src), "r"(sz));
}
#define CP_COMMIT() asm volatile("cp.async.commit_group;" ::: "memory")
#define CP_WAIT(n)  asm volatile("cp.async.wait_group %0;" :: "n"(n) : "memory")

__device__ __forceinline__ void mma16(float* c, const uint32_t* a, const uint32_t* b) {
    asm volatile(
        "mma.sync.aligned.m16n8k16.row.col.f32.bf16.bf16.f32 "
        "{%0,%1,%2,%3},{%4,%5,%6,%7},{%8,%9},{%0,%1,%2,%3};"
        : "+f"(c[0]), "+f"(c[1]), "+f"(c[2]), "+f"(c[3])
        : "r"(a[0]), "r"(a[1]), "r"(a[2]), "r"(a[3]), "r"(b[0]), "r"(b[1]));
}

__device__ __forceinline__ void ldsm4(uint32_t& r0, uint32_t& r1, uint32_t& r2, uint32_t& r3,
                                      uint32_t addr) {
    asm volatile("ldmatrix.sync.aligned.m8n8.x4.shared.b16 {%0,%1,%2,%3}, [%4];"
                 : "=r"(r0), "=r"(r1), "=r"(r2), "=r"(r3) : "r"(addr));
}

// packed f32x2 helpers
__device__ __forceinline__ unsigned long long pack2(float x, float y) {
    unsigned long long r;
    asm("mov.b64 %0, {%1, %2};" : "=l"(r) : "f"(x), "f"(y));
    return r;
}
__device__ __forceinline__ void unpack2(unsigned long long v, float& x, float& y) {
    asm("mov.b64 {%0, %1}, %2;" : "=f"(x), "=f"(y) : "l"(v));
}
__device__ __forceinline__ unsigned long long fma2(unsigned long long a,
                                                   unsigned long long b,
                                                   unsigned long long c) {
    unsigned long long d;
    asm("fma.rn.f32x2 %0, %1, %2, %3;" : "=l"(d) : "l"(a), "l"(b), "l"(c));
    return d;
}

__device__ __forceinline__ uint32_t packbf(float x1, float x0) {
    uint32_t d;
    asm("cvt.rn.bf16x2.f32 %0, %1, %2;" : "=r"(d) : "f"(x1), "f"(x0));
    return d;
}
__device__ __forceinline__ void split_bf(float x0, float x1, uint32_t& hi, uint32_t& lo) {
    hi = packbf(x1, x0);
    float h0 = __uint_as_float(hi << 16);
    float h1 = __uint_as_float(hi & 0xFFFF0000u);
    lo = packbf(x1 - h1, x0 - h0);
}

// ---------------- transposing weight split: W[Kd][P] -> planes [P][K2] ------
__global__ void wsplit_t_kernel(const float* __restrict__ w, uint32_t* __restrict__ whi,
                                uint32_t* __restrict__ wlo, int P, int K2,
                                long wstride, long ostride) {
    int z = blockIdx.z;
    w += (long)z * wstride; whi += (long)z * ostride; wlo += (long)z * ostride;
    __shared__ uint32_t shi[32][33], slo[32][33];
    int n0 = blockIdx.x * 32, k20 = blockIdx.y * 32;
    int tx = threadIdx.x, ty = threadIdx.y;   // block (32,8)
    #pragma unroll
    for (int rr = ty; rr < 32; rr += 8) {
        int k2 = k20 + rr;
        float v0 = w[(long)(2 * k2) * P + n0 + tx];
        float v1 = w[(long)(2 * k2 + 1) * P + n0 + tx];
        uint32_t hi, lo;
        split_bf(v0, v1, hi, lo);
        shi[rr][tx] = hi; slo[rr][tx] = lo;
    }
    __syncthreads();
    #pragma unroll
    for (int cc = ty; cc < 32; cc += 8) {
        whi[(long)(n0 + cc) * K2 + k20 + tx] = shi[tx][cc];
        wlo[(long)(n0 + cc) * K2 + k20 + tx] = slo[tx][cc];
    }
}

// QKV3 split: z = l*3+p; input mats wq/wk/wv [Lm][Dm][Dm]; out rows (l*4+p)*Dm
__global__ void wsplit_qkv3_kernel(const float* __restrict__ wq, const float* __restrict__ wk,
                                   const float* __restrict__ wv,
                                   uint32_t* __restrict__ whi, uint32_t* __restrict__ wlo) {
    int z = blockIdx.z;
    int l = z / 3, p = z - l * 3;
    const float* w = ((p == 0) ? wq : (p == 1) ? wk : wv) + (size_t)l * Dm * Dm;
    __shared__ uint32_t shi[32][33], slo[32][33];
    int n0 = blockIdx.x * 32, k20 = blockIdx.y * 32;
    int tx = threadIdx.x, ty = threadIdx.y;
    #pragma unroll
    for (int rr = ty; rr < 32; rr += 8) {
        int k2 = k20 + rr;
        float v0 = w[(long)(2 * k2) * Dm + n0 + tx];
        float v1 = w[(long)(2 * k2 + 1) * Dm + n0 + tx];
        uint32_t hi, lo;
        split_bf(v0, v1, hi, lo);
        shi[rr][tx] = hi; slo[rr][tx] = lo;
    }
    __syncthreads();
    long rbase = ((long)l * 4 + p) * Dm;
    #pragma unroll
    for (int cc = ty; cc < 32; cc += 8) {
        whi[(rbase + n0 + cc) * K2D + k20 + tx] = shi[tx][cc];
        wlo[(rbase + n0 + cc) * K2D + k20 + tx] = slo[tx][cc];
    }
}

__global__ void biaspack_all_kernel(const float* __restrict__ bq, const float* __restrict__ bk,
                                    const float* __restrict__ bv, float* __restrict__ out) {
    int l = blockIdx.z;
    int i = blockIdx.x * blockDim.x + threadIdx.x;
    if (i < Dm) {
        out[(size_t)l * 3 * Dm + i]          = bq[(size_t)l * Dm + i];
        out[(size_t)l * 3 * Dm + Dm + i]     = bk[(size_t)l * Dm + i];
        out[(size_t)l * 3 * Dm + 2 * Dm + i] = bv[(size_t)l * Dm + i];
    }
}

// ---------------- 3xBF16 GEMM (ldmatrix fragments, K=32 chunks) ------------
#define KCH 16
#define AST 20
#define BST 20
#define A_PLANE (128*AST)
#define B_PLANE (128*BST)
#define GEMM_SMEM ((4*A_PLANE + 4*B_PLANE)*4)   // 81920 bytes

__global__ void __launch_bounds__(256, 2)
mma_gemm(const uint32_t* __restrict__ Ahi, const uint32_t* __restrict__ Alo,
         const uint32_t* __restrict__ Whi, const uint32_t* __restrict__ Wlo,
         const float* __restrict__ bias,
         float* __restrict__ Cf, uint32_t* __restrict__ Chi, uint32_t* __restrict__ Clo,
         int Nrows, int K2, int Pc,
         long strA, long strW, long strBias, long strC,
         float alpha, int act, int accum, int qkv) {
    int z = blockIdx.z;
    Ahi += (long)z * strA; Alo += (long)z * strA;
    Whi += (long)z * strW; Wlo += (long)z * strW;
    const float* Bp = bias + (long)z * strBias;

    extern __shared__ uint32_t smw[];
    uint32_t* sAhi = smw;
    uint32_t* sAlo = smw + 2 * A_PLANE;
    uint32_t* sBhi = smw + 4 * A_PLANE;
    uint32_t* sBlo = smw + 4 * A_PLANE + 2 * B_PLANE;

    int tid = threadIdx.x;
    int row0 = blockIdx.y * 128, col0 = blockIdx.x * 128;

    int ar = tid >> 1, ako = (tid & 1) * 8;
    const uint32_t* gAhi = Ahi + (long)(row0 + ar) * K2 + ako;
    const uint32_t* gAlo = Alo + (long)(row0 + ar) * K2 + ako;
    const uint32_t* gBhi = Whi + (long)(col0 + ar) * K2 + ako;
    const uint32_t* gBlo = Wlo + (long)(col0 + ar) * K2 + ako;
    uint32_t asz = ((row0 + ar) < Nrows) ? 16u : 0u;
    uint32_t dAhi = smem_u32(sAhi) + (uint32_t)(ar * AST + ako) * 4u;
    uint32_t dAlo = smem_u32(sAlo) + (uint32_t)(ar * AST + ako) * 4u;
    uint32_t dBhi = smem_u32(sBhi) + (uint32_t)(ar * BST + ako) * 4u;
    uint32_t dBlo = smem_u32(sBlo) + (uint32_t)(ar * BST + ako) * 4u;

    int nk = K2 / KCH;

    cp16(dAhi, gAhi, asz); cp16(dAhi + 16, gAhi + 4, asz);
    cp16(dAlo, gAlo, asz); cp16(dAlo + 16, gAlo + 4, asz);
    cp16(dBhi, gBhi, 16);  cp16(dBhi + 16, gBhi + 4, 16);
    cp16(dBlo, gBlo, 16);  cp16(dBlo + 16, gBlo + 4, 16);
    CP_COMMIT();

    int warp = tid >> 5, lane = tid & 31;
    int wm = (warp & 3) * 32, wn = (warp >> 2) * 64;
    int gid = lane >> 2, tig = lane & 3;

    int l16 = lane & 15, kh4 = (lane >> 4) * 4;
    uint32_t fAhi = smem_u32(sAhi), fAlo = smem_u32(sAlo);
    uint32_t fBhi = smem_u32(sBhi), fBlo = smem_u32(sBlo);
    uint32_t aRow = (uint32_t)((wm + l16) * AST + kh4);
    uint32_t bRow = (uint32_t)((wn + l16) * BST + kh4);

    float acc[2][8][4];
    #pragma unroll
    for (int mt = 0; mt < 2; mt++)
        #pragma unroll
        for (int nt = 0; nt < 8; nt++)
            #pragma unroll
            for (int r = 0; r < 4; r++) acc[mt][nt][r] = 0.0f;

    for (int i = 0; i < nk; i++) {
        int b = i & 1;
        if (i + 1 < nk) {
            int nb = b ^ 1;
            const uint32_t* pah = gAhi + (i + 1) * KCH;
            const uint32_t* pal = gAlo + (i + 1) * KCH;
            const uint32_t* pbh = gBhi + (i + 1) * KCH;
            const uint32_t* pbl = gBlo + (i + 1) * KCH;
            uint32_t oA = (uint32_t)(nb * A_PLANE) * 4u;
            uint32_t oB = (uint32_t)(nb * B_PLANE) * 4u;
            cp16(dAhi + oA, pah, asz); cp16(dAhi + oA + 16, pah + 4, asz);
            cp16(dAlo + oA, pal, asz); cp16(dAlo + oA + 16, pal + 4, asz);
            cp16(dBhi + oB, pbh, 16);  cp16(dBhi + oB + 16, pbh + 4, 16);
            cp16(dBlo + oB, pbl, 16);  cp16(dBlo + oB + 16, pbl + 4, 16);
            CP_COMMIT();
            CP_WAIT(1);
        } else {
            CP_WAIT(0);
        }
        __syncthreads();

        uint32_t baseA = (uint32_t)(b * A_PLANE) * 4u;
        uint32_t baseB = (uint32_t)(b * B_PLANE) * 4u;
        #pragma unroll
        for (int ks = 0; ks < 2; ks++) {
            int kq = ks * 8;
            uint32_t afh[2][4], afl[2][4];
            #pragma unroll
            for (int mt = 0; mt < 2; mt++) {
                uint32_t off = (aRow + (uint32_t)(mt * 16 * AST + kq)) * 4u;
                ldsm4(afh[mt][0], afh[mt][1], afh[mt][2], afh[mt][3], fAhi + baseA + off);
                ldsm4(afl[mt][0], afl[mt][1], afl[mt][2], afl[mt][3], fAlo + baseA + off);
            }
            #pragma unroll
            for (int np_ = 0; np_ < 4; np_++) {
                int nt0 = np_ * 2, nt1 = nt0 + 1;
                uint32_t off = (bRow + (uint32_t)(np_ * 16 * BST + kq)) * 4u;
                uint32_t bh[4], bl[4];
                ldsm4(bh[0], bh[1], bh[2], bh[3], fBhi + baseB + off);
                ldsm4(bl[0], bl[1], bl[2], bl[3], fBlo + baseB + off);
                uint32_t b0h[2] = { bh[0], bh[2] }, b1h[2] = { bh[1], bh[3] };
                uint32_t b0l[2] = { bl[0], bl[2] }, b1l[2] = { bl[1], bl[3] };
                mma16(acc[0][nt0], afh[0], b0l);
                mma16(acc[1][nt0], afh[1], b0l);
                mma16(acc[0][nt1], afh[0], b1l);
                mma16(acc[1][nt1], afh[1], b1l);
                mma16(acc[0][nt0], afl[0], b0h);
                mma16(acc[1][nt0], afl[1], b0h);
                mma16(acc[0][nt1], afl[0], b1h);
                mma16(acc[1][nt1], afl[1], b1h);
                mma16(acc[0][nt0], afh[0], b0h);
                mma16(acc[1][nt0], afh[1], b0h);
                mma16(acc[0][nt1], afh[0], b1h);
                mma16(acc[1][nt1], afh[1], b1h);
            }
        }
        __syncthreads();
    }

    // epilogue
    int P2 = Pc >> 1;
    #pragma unroll
    for (int mt = 0; mt < 2; mt++) {
        int r0 = row0 + wm + mt * 16 + gid;
        #pragma unroll
        for (int half = 0; half < 2; half++) {
            int gr = r0 + half * 8;
            if (gr >= Nrows) continue;
            #pragma unroll
            for (int nt = 0; nt < 8; nt++) {
                int gc = col0 + wn + nt * 8 + 2 * tig;
                float2 bv = *reinterpret_cast<const float2*>(Bp + gc);
                float v0, v1;
                if (qkv) {
                    int band = gc / Dm;
                    int cc = gc - band * Dm;
                    float a = (band == 0) ? alpha : 1.0f;
                    v0 = (acc[mt][nt][half * 2 + 0] + bv.x) * a;
                    v1 = (acc[mt][nt][half * 2 + 1] + bv.y) * a;
                    float* Cp = Cf + (long)band * strC + (long)gr * Dm + cc;
                    *reinterpret_cast<float2*>(Cp) = make_float2(v0, v1);
                    continue;
                }
                v0 = (acc[mt][nt][half * 2 + 0] + bv.x) * alpha;
                v1 = (acc[mt][nt][half * 2 + 1] + bv.y) * alpha;
                if (act) { v0 = gelu_f(v0); v1 = gelu_f(v1); }
                if (Chi) {
                    long o = (long)z * strC + (long)gr * P2 + (gc >> 1);
                    uint32_t hi, lo;
                    split_bf(v0, v1, hi, lo);
                    Chi[o] = hi; Clo[o] = lo;
                } else {
                    float* Cp = Cf + (long)z * strC + (long)gr * Pc + gc;
                    if (accum) {
                        float2 o = *reinterpret_cast<float2*>(Cp);
                        v0 += o.x; v1 += o.y;
                    }
                    *reinterpret_cast<float2*>(Cp) = make_float2(v0, v1);
                }
            }
        }
    }
}

// ---------------- elementwise ----------------
__global__ void addpos_kernel(const float* __restrict__ x, const float* __restrict__ pe,
                              float* __restrict__ out) {
    int i = blockIdx.x * blockDim.x + threadIdx.x;
    if (i < NTOK * Dm) out[i] = x[i] + pe[i % (Sm * Dm)];
}

__device__ __forceinline__ float block_reduce_sum(float v) {
    __shared__ float sh[33];
    int lane = threadIdx.x & 31, w = threadIdx.x >> 5;
    #pragma unroll
    for (int o = 16; o; o >>= 1) v += __shfl_xor_sync(0xffffffffu, v, o);
    if (lane == 0) sh[w] = v;
    __syncthreads();
    int nw = blockDim.x >> 5;
    float r = (threadIdx.x < nw) ? sh[threadIdx.x] : 0.0f;
    if (w == 0) {
        #pragma unroll
        for (int o = 16; o; o >>= 1) r += __shfl_xor_sync(0xffffffffu, r, o);
        if (lane == 0) sh[32] = r;
    }
    __syncthreads();
    float out = sh[32];
    __syncthreads();
    return out;
}

__global__ void ln_kernel(const float* __restrict__ in, float* __restrict__ outf,
                          uint32_t* __restrict__ ohi, uint32_t* __restrict__ olo,
                          const float* __restrict__ s, const float* __restrict__ b) {
    int t = blockIdx.x;
    const float* xr = in + (size_t)t * Dm;
    float sum = 0.0f;
    for (int i = threadIdx.x; i < Dm; i += blockDim.x) sum += xr[i];
    float mu = block_reduce_sum(sum) * (1.0f / Dm);
    float vs = 0.0f;
    for (int i = threadIdx.x; i < Dm; i += blockDim.x) { float d = xr[i] - mu; vs += d * d; }
    float var = block_reduce_sum(vs) * (1.0f / Dm);
    float inv = rsqrtf(var + 1e-6f);
    for (int i = threadIdx.x * 2; i < Dm; i += blockDim.x * 2) {
        float v0 = (xr[i] - mu) * inv * s[i] + b[i];
        float v1 = (xr[i + 1] - mu) * inv * s[i + 1] + b[i + 1];
        if (outf) { outf[(size_t)t * Dm + i] = v0; outf[(size_t)t * Dm + i + 1] = v1; }
        if (ohi) {
            uint32_t hi, lo;
            split_bf(v0, v1, hi, lo);
            ohi[(size_t)t * K2D + (i >> 1)] = hi;
            olo[(size_t)t * K2D + (i >> 1)] = lo;
        }
    }
}

// ---------------- attention ----------------
#define KP2 33
__global__ void attn_kernel(const float* __restrict__ q, const float* __restrict__ k,
                            const float* __restrict__ v,
                            uint32_t* __restrict__ ohi, uint32_t* __restrict__ olo) {
    extern __shared__ unsigned long long sm64[];
    unsigned long long* Ks = sm64;
    unsigned long long* Vs = sm64 + Sm * KP2;
    __shared__ float att[8][Sm];
    __shared__ unsigned long long qrow[8][32];

    int bh = blockIdx.x;
    int b = bh / Hh, h = bh % Hh;
    int tid = threadIdx.x, warp = tid >> 5, lane = tid & 31;
    const long base = (long)(b * Sm) * Dm + h * HDm;
    const long base2 = (long)(b * Sm) * K2D + h * (HDm / 2);

    for (int idx = tid; idx < Sm * 32; idx += blockDim.x) {
        int j = idx >> 5, c2 = idx & 31;
        float2 kk = *reinterpret_cast<const float2*>(k + base + (long)j * Dm + 2 * c2);
        float2 vv = *reinterpret_cast<const float2*>(v + base + (long)j * Dm + 2 * c2);
        Ks[j * KP2 + c2] = pack2(kk.x, kk.y);
        Vs[j * KP2 + c2] = pack2(vv.x, vv.y);
    }
    __syncthreads();

    for (int i = warp; i < Sm; i += 8) {
        {
            float2 qq = *reinterpret_cast<const float2*>(q + base + (long)i * Dm + 2 * lane);
            qrow[warp][lane] = pack2(qq.x, qq.y);
        }
        __syncwarp();
        float lmax = -1e30f;
        for (int j = lane; j < Sm; j += 32) {
            unsigned long long a2 = 0ull;
            const unsigned long long* kr = Ks + j * KP2;
            #pragma unroll
            for (int c2 = 0; c2 < 32; c2++)
                a2 = fma2(qrow[warp][c2], kr[c2], a2);
            float s0, s1;
            unpack2(a2, s0, s1);
            float d = s0 + s1;
            att[warp][j] = d;
            lmax = fmaxf(lmax, d);
        }
        #pragma unroll
        for (int off = 16; off; off >>= 1)
            lmax = fmaxf(lmax, __shfl_xor_sync(0xffffffffu, lmax, off));
        float lsum = 0.0f;
        for (int j = lane; j < Sm; j += 32) {
            float e = __expf(att[warp][j] - lmax);
            att[warp][j] = e;
            lsum += e;
        }
        #pragma unroll
        for (int off = 16; off; off >>= 1)
            lsum += __shfl_xor_sync(0xffffffffu, lsum, off);
        float inv = 1.0f / lsum;
        __syncwarp();
        {
            unsigned long long a2 = 0ull;
            const unsigned long long* vr = Vs + lane;
            for (int j = 0; j < Sm; j++) {
                float w = att[warp][j];
                a2 = fma2(pack2(w, w), vr[j * KP2], a2);
            }
            float a0, a1;
            unpack2(a2, a0, a1);
            uint32_t hi, lo;
            split_bf(a0 * inv, a1 * inv, hi, lo);
            ohi[base2 + (long)i * K2D + lane] = hi;
            olo[base2 + (long)i * K2D + lane] = lo;
        }
        __syncwarp();
    }
}

// ---------------- MoE routing ----------------
__global__ void route_kernel(const float* __restrict__ h, const float* __restrict__ wr) {
    int n = blockIdx.x;
    __shared__ float wrs[Em * Dm];
    __shared__ float tv[GSm][Km];
    __shared__ int   ti[GSm][Km];
    int tid = threadIdx.x, warp = tid >> 5, lane = tid & 31;

    for (int idx = tid; idx < Em * Dm; idx += blockDim.x) {
        int e = idx / Dm, c = idx % Dm;
        wrs[e * Dm + c] = wr[c * Em + e];
    }
    for (int s = tid; s < Em * CAPm; s += blockDim.x) {
        int e = s / CAPm, c = s % CAPm;
        g_slot_src[(e * NGm + n) * CAPm + c] = -1;
    }
    __syncthreads();

    for (int t = warp; t < GSm; t += 8) {
        const float* xr = h + (long)(n * GSm + t) * Dm;
        float a[Em];
        #pragma unroll
        for (int e = 0; e < Em; e++) a[e] = 0.0f;
        for (int c = lane; c < Dm; c += 32) {
            float xv = xr[c];
            #pragma unroll
            for (int e = 0; e < Em; e++) a[e] += xv * wrs[e * Dm + c];
        }
        #pragma unroll
        for (int e = 0; e < Em; e++)
            #pragma unroll
            for (int o = 16; o; o >>= 1) a[e] += __shfl_xor_sync(0xffffffffu, a[e], o);
        if (lane == 0) {
            float mx = a[0];
            #pragma unroll
            for (int e = 1; e < Em; e++) mx = fmaxf(mx, a[e]);
            float p[Em], sum = 0.0f;
            #pragma unroll
            for (int e = 0; e < Em; e++) { p[e] = expf(a[e] - mx); sum += p[e]; }
            float inv = 1.0f / sum;
            #pragma unroll
            for (int e = 0; e < Em; e++) p[e] *= inv;
            int i0 = 0;
            #pragma unroll
            for (int e = 1; e < Em; e++) if (p[e] > p[i0]) i0 = e;
            int i1 = (i0 == 0) ? 1 : 0;
            #pragma unroll
            for (int e = 0; e < Em; e++) if (e != i0 && p[e] > p[i1]) i1 = e;
            ti[t][0] = i0; tv[t][0] = p[i0];
            ti[t][1] = i1; tv[t][1] = p[i1];
        }
    }
    __syncthreads();

    if (tid == 0) {
        int cnt[Em];
        #pragma unroll
        for (int e = 0; e < Em; e++) cnt[e] = 0;
        for (int kk = 0; kk < Km; kk++) {
            for (int t = 0; t < GSm; t++) {
                int e = ti[t][kk];
                int pos = cnt[e]++;
                int gt = n * GSm + t;
                if (pos < CAPm) {
                    int row = (e * NGm + n) * CAPm + pos;
                    g_slot_src[row] = gt;
                    g_comb_idx[gt * Km + kk] = row;
                    g_comb_gate[gt * Km + kk] = tv[t][kk];
                } else {
                    g_comb_idx[gt * Km + kk] = -1;
                    g_comb_gate[gt * Km + kk] = 0.0f;
                }
            }
        }
    }
}

__global__ void gather_kernel(const float* __restrict__ h) {
    int i = blockIdx.x * blockDim.x + threadIdx.x;
    if (i >= TROWS * K2D) return;
    int row = i / K2D, kp = i - row * K2D;
    int src = g_slot_src[row];
    float v0 = 0.0f, v1 = 0.0f;
    if (src >= 0) {
        float2 p = *reinterpret_cast<const float2*>(h + (long)src * Dm + 2 * kp);
        v0 = p.x; v1 = p.y;
    }
    uint32_t hi, lo;
    split_bf(v0, v1, hi, lo);
    g_bf_hi[i] = hi; g_bf_lo[i] = lo;
}

__global__ void combine_kernel(float* __restrict__ x) {
    int i = blockIdx.x * blockDim.x + threadIdx.x;
    if (i >= NTOK * Dm) return;
    int t = i / Dm, c = i - t * Dm;
    float acc = 0.0f;
    #pragma unroll
    for (int kk = 0; kk < Km; kk++) {
        int r = g_comb_idx[t * Km + kk];
        if (r >= 0) acc += g_comb_gate[t * Km + kk] * g_y[(long)r * Dm + c];
    }
    x[i] += acc;
}

// ---------------- host ----------------
extern "C" void kernel_launch(void* const* d_in, const int* in_sizes, int n_in,
                              void* d_out, int out_size) {
    (void)in_sizes; (void)n_in; (void)out_size;
    const float* in_x     = (const float*)d_in[0];
    const float* posemb   = (const float*)d_in[1];
    const float* ln1_s    = (const float*)d_in[2];
    const float* ln1_b    = (const float*)d_in[3];
    const float* wq       = (const float*)d_in[4];
    const float* bq       = (const float*)d_in[5];
    const float* wk       = (const float*)d_in[6];
    const float* bk       = (const float*)d_in[7];
    const float* wv       = (const float*)d_in[8];
    const float* bv       = (const float*)d_in[9];
    const float* wo       = (const float*)d_in[10];
    const float* bo       = (const float*)d_in[11];
    const float* ln2_s    = (const float*)d_in[12];
    const float* ln2_b    = (const float*)d_in[13];
    const float* dw1      = (const float*)d_in[14];
    const float* db1      = (const float*)d_in[15];
    const float* dw2      = (const float*)d_in[16];
    const float* db2      = (const float*)d_in[17];
    const float* router_w = (const float*)d_in[18];
    const float* mw1      = (const float*)d_in[19];
    const float* mb1      = (const float*)d_in[20];
    const float* mw2      = (const float*)d_in[21];
    const float* mb2      = (const float*)d_in[22];
    const float* out_s    = (const float*)d_in[23];
    const float* out_b    = (const float*)d_in[24];
    float* out = (float*)d_out;

    float *x, *h, *qkv, *y, *bqkv;
    uint32_t *h_hi, *h_lo, *ao_hi, *ao_lo, *ml_hi, *ml_lo, *bf_hi, *bf_lo, *hx_hi, *hx_lo;
    uint32_t *wat_hi, *wat_lo, *wd1_hi, *wd1_lo, *wd2_hi, *wd2_lo, *wm1_hi, *wm1_lo, *wm2_hi, *wm2_lo;
    cudaGetSymbolAddress((void**)&x,      g_x);
    cudaGetSymbolAddress((void**)&h,      g_h);
    cudaGetSymbolAddress((void**)&qkv,    g_qkv);
    cudaGetSymbolAddress((void**)&y,      g_y);
    cudaGetSymbolAddress((void**)&bqkv,   g_bqkv);
    cudaGetSymbolAddress((void**)&h_hi,   g_h_hi);
    cudaGetSymbolAddress((void**)&h_lo,   g_h_lo);
    cudaGetSymbolAddress((void**)&ao_hi,  g_ao_hi);
    cudaGetSymbolAddress((void**)&ao_lo,  g_ao_lo);
    cudaGetSymbolAddress((void**)&ml_hi,  g_ml_hi);
    cudaGetSymbolAddress((void**)&ml_lo,  g_ml_lo);
    cudaGetSymbolAddress((void**)&bf_hi,  g_bf_hi);
    cudaGetSymbolAddress((void**)&bf_lo,  g_bf_lo);
    cudaGetSymbolAddress((void**)&hx_hi,  g_hx_hi);
    cudaGetSymbolAddress((void**)&hx_lo,  g_hx_lo);
    cudaGetSymbolAddress((void**)&wat_hi, g_wat_hi);
    cudaGetSymbolAddress((void**)&wat_lo, g_wat_lo);
    cudaGetSymbolAddress((void**)&wd1_hi, g_wd1_hi);
    cudaGetSymbolAddress((void**)&wd1_lo, g_wd1_lo);
    cudaGetSymbolAddress((void**)&wd2_hi, g_wd2_hi);
    cudaGetSymbolAddress((void**)&wd2_lo, g_wd2_lo);
    cudaGetSymbolAddress((void**)&wm1_hi, g_wm1_hi);
    cudaGetSymbolAddress((void**)&wm1_lo, g_wm1_lo);
    cudaGetSymbolAddress((void**)&wm2_hi, g_wm2_hi);
    cudaGetSymbolAddress((void**)&wm2_lo, g_wm2_lo);

    float* q = qkv;
    float* k = qkv + NQKV;
    float* v = qkv + 2 * NQKV;

    const int ATTN_SMEM = 2 * Sm * KP2 * (int)sizeof(unsigned long long);
    cudaFuncSetAttribute(attn_kernel, cudaFuncAttributeMaxDynamicSharedMemorySize, ATTN_SMEM);
    cudaFuncSetAttribute(mma_gemm, cudaFuncAttributeMaxDynamicSharedMemorySize, GEMM_SMEM);

    const float qscale = 0.125f;
    const long WAT_L = (long)4 * Dm * K2D;     // per-layer attention plane stride

    // ===== prepass: split ALL weights once =====
    {
        dim3 blk(32, 8, 1);
        // QKV (z = l*3+p) and WO (z = l, offset 3*Dm rows)
        wsplit_qkv3_kernel<<<dim3(Dm / 32, K2D / 32, Lm * 3), blk>>>(wq, wk, wv, wat_hi, wat_lo);
        wsplit_t_kernel<<<dim3(Dm / 32, K2D / 32, Lm), blk>>>(
            wo, wat_hi + 3 * (long)Dm * K2D, wat_lo + 3 * (long)Dm * K2D,
            Dm, K2D, (long)Dm * Dm, WAT_L);
        biaspack_all_kernel<<<dim3(3, 1, Lm), 256>>>(bq, bk, bv, bqkv);
        // dense MLP
        wsplit_t_kernel<<<dim3(Mm / 32, K2D / 32, NDL), blk>>>(
            dw1, wd1_hi, wd1_lo, Mm, K2D, (long)Dm * Mm, (long)Mm * K2D);
        wsplit_t_kernel<<<dim3(Dm / 32, K2M / 32, NDL), blk>>>(
            dw2, wd2_hi, wd2_lo, Dm, K2M, (long)Mm * Dm, (long)Dm * K2M);
        // MoE experts (z spans layer*expert)
        wsplit_t_kernel<<<dim3(Mm / 32, K2D / 32, NML * Em), blk>>>(
            mw1, wm1_hi, wm1_lo, Mm, K2D, (long)Dm * Mm, (long)Mm * K2D);
        wsplit_t_kernel<<<dim3(Dm / 32, K2M / 32, NML * Em), blk>>>(
            mw2, wm2_hi, wm2_lo, Dm, K2M, (long)Mm * Dm, (long)Dm * K2M);
    }

    addpos_kernel<<<(NTOK * Dm + 255) / 256, 256>>>(in_x, posemb, x);

    int di = 0, mi = 0;
    for (int l = 0; l < Lm; l++) {
        // ---- attention block ----
        ln_kernel<<<NTOK, 256>>>(x, nullptr, h_hi, h_lo,
                                 ln1_s + (size_t)l * Dm, ln1_b + (size_t)l * Dm);
        {
            dim3 gq(3 * Dm / 128, NTOK / 128, 1);   // 18, 49
            mma_gemm<<<gq, 256, GEMM_SMEM>>>(h_hi, h_lo,
                                             wat_hi + (long)l * WAT_L, wat_lo + (long)l * WAT_L,
                                             bqkv + (size_t)l * 3 * Dm,
                                             qkv, nullptr, nullptr,
                                             NTOK, K2D, 3 * Dm, 0, 0, 0, NQKV,
                                             qscale, 0, 0, 1);
        }
        attn_kernel<<<Bm * Hh, 256, ATTN_SMEM>>>(q, k, v, ao_hi, ao_lo);
        {
            dim3 gdd(Dm / 128, NTOK / 128, 1);
            mma_gemm<<<gdd, 256, GEMM_SMEM>>>(ao_hi, ao_lo,
                                              wat_hi + (long)l * WAT_L + 3 * (long)Dm * K2D,
                                              wat_lo + (long)l * WAT_L + 3 * (long)Dm * K2D,
                                              bo + (size_t)l * Dm,
                                              x, nullptr, nullptr,
                                              NTOK, K2D, Dm, 0, 0, 0, 0, 1.0f, 0, 1, 0);
        }

        // ---- mlp / moe block ----
        ln_kernel<<<NTOK, 256>>>(x, h, h_hi, h_lo,
                                 ln2_s + (size_t)l * Dm, ln2_b + (size_t)l * Dm);
        if (l & 1) {
            route_kernel<<<NGm, 256>>>(h, router_w + (size_t)mi * Dm * Em);
            gather_kernel<<<(TROWS * K2D + 255) / 256, 256>>>(h);
            dim3 g1(Mm / 128, (EROWS + 127) / 128, Em);
            mma_gemm<<<g1, 256, GEMM_SMEM>>>(bf_hi, bf_lo,
                                             wm1_hi + (long)mi * Em * Mm * K2D,
                                             wm1_lo + (long)mi * Em * Mm * K2D,
                                             mb1 + (size_t)mi * Em * Mm,
                                             nullptr, hx_hi, hx_lo,
                                             EROWS, K2D, Mm,
                                             (long)EROWS * K2D, (long)Mm * K2D, Mm,
                                             (long)EROWS * K2M, 1.0f, 1, 0, 0);
            dim3 g2(Dm / 128, (EROWS + 127) / 128, Em);
            mma_gemm<<<g2, 256, GEMM_SMEM>>>(hx_hi, hx_lo,
                                             wm2_hi + (long)mi * Em * Dm * K2M,
                                             wm2_lo + (long)mi * Em * Dm * K2M,
                                             mb2 + (size_t)mi * Em * Dm,
                                             y, nullptr, nullptr,
                                             EROWS, K2M, Dm,
                                             (long)EROWS * K2M, (long)Dm * K2M, Dm,
                                             (long)EROWS * Dm, 1.0f, 0, 0, 0);
            combine_kernel<<<(NTOK * Dm + 255) / 256, 256>>>(x);
            mi++;
        } else {
            dim3 g1(Mm / 128, NTOK / 128, 1);
            mma_gemm<<<g1, 256, GEMM_SMEM>>>(h_hi, h_lo,
                                             wd1_hi + (long)di * Mm * K2D,
                                             wd1_lo + (long)di * Mm * K2D,
                                             db1 + (size_t)di * Mm,
                                             nullptr, ml_hi, ml_lo,
                                             NTOK, K2D, Mm, 0, 0, 0, 0, 1.0f, 1, 0, 0);
            dim3 g2(Dm / 128, NTOK / 128, 1);
            mma_gemm<<<g2, 256, GEMM_SMEM>>>(ml_hi, ml_lo,
                                             wd2_hi + (long)di * Dm * K2M,
                                             wd2_lo + (long)di * Dm * K2M,
                                             db2 + (size_t)di * Dm,
                                             x, nullptr, nullptr,
                                             NTOK, K2M, Dm, 0, 0, 0, 0, 1.0f, 0, 1, 0);
            di++;
        }
    }

    ln_kernel<<<NTOK, 256>>>(x, out, nullptr, nullptr, out_s, out_b);
}

// round 17
// speedup vs baseline: 1.1087x; 1.0180x over previous
#include <cuda_runtime.h>
#include <math.h>
#include <stdint.h>

// ---------------- problem constants ----------------
#define Dm   768
#define Hh   12
#define HDm  64
#define Mm   3072
#define Lm   12
#define Em   8
#define Km   2
#define Bm   32
#define Sm   196
#define GSm  392
#define NGm  16
#define CAPm 98
#define NTOK (Bm*Sm)     // 6272
#define EROWS (NGm*CAPm) // 1568
#define TROWS (Em*EROWS) // 12544
#define K2D  (Dm/2)      // 384 k-pairs
#define K2M  (Mm/2)      // 1536 k-pairs
#define NQKV ((long)NTOK*Dm)
#define NDL  6
#define NML  6

// ---------------- scratch ----------------
__device__ float g_x [(size_t)NTOK*Dm];
__device__ float g_h [(size_t)NTOK*Dm];
__device__ float g_qkv[(size_t)3*NTOK*Dm];
__device__ float g_bqkv[(size_t)Lm*3*Dm];
// bf16-split activation planes
__device__ uint32_t g_h_hi [(size_t)NTOK*K2D],  g_h_lo [(size_t)NTOK*K2D];
__device__ uint32_t g_ao_hi[(size_t)NTOK*K2D],  g_ao_lo[(size_t)NTOK*K2D];
__device__ uint32_t g_ml_hi[(size_t)NTOK*K2M],  g_ml_lo[(size_t)NTOK*K2M];
__device__ uint32_t g_bf_hi[(size_t)(TROWS+128)*K2D], g_bf_lo[(size_t)(TROWS+128)*K2D];
__device__ uint32_t g_hx_hi[(size_t)(TROWS+128)*K2M], g_hx_lo[(size_t)(TROWS+128)*K2M];
// pre-split transposed weight planes (all layers)
__device__ uint32_t g_wat_hi[(size_t)Lm*4*Dm*K2D], g_wat_lo[(size_t)Lm*4*Dm*K2D];
__device__ uint32_t g_wd1_hi[(size_t)NDL*Mm*K2D],  g_wd1_lo[(size_t)NDL*Mm*K2D];
__device__ uint32_t g_wd2_hi[(size_t)NDL*Dm*K2M],  g_wd2_lo[(size_t)NDL*Dm*K2M];
__device__ uint32_t g_wm1_hi[(size_t)NML*Em*Mm*K2D], g_wm1_lo[(size_t)NML*Em*Mm*K2D];
__device__ uint32_t g_wm2_hi[(size_t)NML*Em*Dm*K2M], g_wm2_lo[(size_t)NML*Em*Dm*K2M];
__device__ int   g_slot_src[TROWS];
__device__ float g_slot_gate[TROWS];

// ---------------- helpers ----------------
__device__ __forceinline__ float gelu_f(float x) {
    const float c = 0.7978845608028654f;
    float t = tanhf(c * (x + 0.044715f * x * x * x));
    return 0.5f * x * (1.0f + t);
}

__device__ __forceinline__ uint32_t smem_u32(const void* p) {
    uint32_t a;
    asm("{ .reg .u64 t; cvta.to.shared.u64 t, %1; cvt.u32.u64 %0, t; }" : "=r"(a) : "l"(p));
    return a;
}

__device__ __forceinline__ void cp16(uint32_t dst, const void* src, uint32_t sz) {
    asm volatile("cp.async.ca.shared.global [%0], [%1], 16, %2;"
                 :: "r"(dst), "l"(src), "r"(sz));
}
#define CP_COMMIT() asm volatile("cp.async.commit_group;" ::: "memory")
#define CP_WAIT(n)  asm volatile("cp.async.wait_group %0;" :: "n"(n) : "memory")

__device__ __forceinline__ void mma16(float* c, const uint32_t* a, const uint32_t* b) {
    asm volatile(
        "mma.sync.aligned.m16n8k16.row.col.f32.bf16.bf16.f32 "
        "{%0,%1,%2,%3},{%4,%5,%6,%7},{%8,%9},{%0,%1,%2,%3};"
        : "+f"(c[0]), "+f"(c[1]), "+f"(c[2]), "+f"(c[3])
        : "r"(a[0]), "r"(a[1]), "r"(a[2]), "r"(a[3]), "r"(b[0]), "r"(b[1]));
}

__device__ __forceinline__ void ldsm4(uint32_t& r0, uint32_t& r1, uint32_t& r2, uint32_t& r3,
                                      uint32_t addr) {
    asm volatile("ldmatrix.sync.aligned.m8n8.x4.shared.b16 {%0,%1,%2,%3}, [%4];"
                 : "=r"(r0), "=r"(r1), "=r"(r2), "=r"(r3) : "r"(addr));
}

__device__ __forceinline__ unsigned long long pack2(float x, float y) {
    unsigned long long r;
    asm("mov.b64 %0, {%1, %2};" : "=l"(r) : "f"(x), "f"(y));
    return r;
}
__device__ __forceinline__ void unpack2(unsigned long long v, float& x, float& y) {
    asm("mov.b64 {%0, %1}, %2;" : "=f"(x), "=f"(y) : "l"(v));
}
__device__ __forceinline__ unsigned long long fma2(unsigned long long a,
                                                   unsigned long long b,
                                                   unsigned long long c) {
    unsigned long long d;
    asm("fma.rn.f32x2 %0, %1, %2, %3;" : "=l"(d) : "l"(a), "l"(b), "l"(c));
    return d;
}

__device__ __forceinline__ uint32_t packbf(float x1, float x0) {
    uint32_t d;
    asm("cvt.rn.bf16x2.f32 %0, %1, %2;" : "=r"(d) : "f"(x1), "f"(x0));
    return d;
}
__device__ __forceinline__ void split_bf(float x0, float x1, uint32_t& hi, uint32_t& lo) {
    hi = packbf(x1, x0);
    float h0 = __uint_as_float(hi << 16);
    float h1 = __uint_as_float(hi & 0xFFFF0000u);
    lo = packbf(x1 - h1, x0 - h0);
}

// ---------------- transposing weight split: W[Kd][P] -> planes [P][K2] ------
__global__ void wsplit_t_kernel(const float* __restrict__ w, uint32_t* __restrict__ whi,
                                uint32_t* __restrict__ wlo, int P, int K2,
                                long wstride, long ostride) {
    int z = blockIdx.z;
    w += (long)z * wstride; whi += (long)z * ostride; wlo += (long)z * ostride;
    __shared__ uint32_t shi[32][33], slo[32][33];
    int n0 = blockIdx.x * 32, k20 = blockIdx.y * 32;
    int tx = threadIdx.x, ty = threadIdx.y;
    #pragma unroll
    for (int rr = ty; rr < 32; rr += 8) {
        int k2 = k20 + rr;
        float v0 = w[(long)(2 * k2) * P + n0 + tx];
        float v1 = w[(long)(2 * k2 + 1) * P + n0 + tx];
        uint32_t hi, lo;
        split_bf(v0, v1, hi, lo);
        shi[rr][tx] = hi; slo[rr][tx] = lo;
    }
    __syncthreads();
    #pragma unroll
    for (int cc = ty; cc < 32; cc += 8) {
        whi[(long)(n0 + cc) * K2 + k20 + tx] = shi[tx][cc];
        wlo[(long)(n0 + cc) * K2 + k20 + tx] = slo[tx][cc];
    }
}

__global__ void wsplit_qkv3_kernel(const float* __restrict__ wq, const float* __restrict__ wk,
                                   const float* __restrict__ wv,
                                   uint32_t* __restrict__ whi, uint32_t* __restrict__ wlo) {
    int z = blockIdx.z;
    int l = z / 3, p = z - l * 3;
    const float* w = ((p == 0) ? wq : (p == 1) ? wk : wv) + (size_t)l * Dm * Dm;
    __shared__ uint32_t shi[32][33], slo[32][33];
    int n0 = blockIdx.x * 32, k20 = blockIdx.y * 32;
    int tx = threadIdx.x, ty = threadIdx.y;
    #pragma unroll
    for (int rr = ty; rr < 32; rr += 8) {
        int k2 = k20 + rr;
        float v0 = w[(long)(2 * k2) * Dm + n0 + tx];
        float v1 = w[(long)(2 * k2 + 1) * Dm + n0 + tx];
        uint32_t hi, lo;
        split_bf(v0, v1, hi, lo);
        shi[rr][tx] = hi; slo[rr][tx] = lo;
    }
    __syncthreads();
    long rbase = ((long)l * 4 + p) * Dm;
    #pragma unroll
    for (int cc = ty; cc < 32; cc += 8) {
        whi[(rbase + n0 + cc) * K2D + k20 + tx] = shi[tx][cc];
        wlo[(rbase + n0 + cc) * K2D + k20 + tx] = slo[tx][cc];
    }
}

__global__ void biaspack_all_kernel(const float* __restrict__ bq, const float* __restrict__ bk,
                                    const float* __restrict__ bv, float* __restrict__ out) {
    int l = blockIdx.z;
    int i = blockIdx.x * blockDim.x + threadIdx.x;
    if (i < Dm) {
        out[(size_t)l * 3 * Dm + i]          = bq[(size_t)l * Dm + i];
        out[(size_t)l * 3 * Dm + Dm + i]     = bk[(size_t)l * Dm + i];
        out[(size_t)l * 3 * Dm + 2 * Dm + i] = bv[(size_t)l * Dm + i];
    }
}

// ---------------- 3xBF16 GEMM ----------------
#define KCH 16
#define AST 20
#define BST 20
#define A_PLANE (128*AST)
#define B_PLANE (128*BST)
#define GEMM_SMEM ((4*A_PLANE + 4*B_PLANE)*4)   // 81920 bytes

__global__ void __launch_bounds__(256, 2)
mma_gemm(const uint32_t* __restrict__ Ahi, const uint32_t* __restrict__ Alo,
         const uint32_t* __restrict__ Whi, const uint32_t* __restrict__ Wlo,
         const float* __restrict__ bias,
         float* __restrict__ Cf, uint32_t* __restrict__ Chi, uint32_t* __restrict__ Clo,
         int Nrows, int K2, int Pc,
         long strA, long strW, long strBias, long strC,
         float alpha, int act, int accum, int qkv, int scatter) {
    int z = blockIdx.z;
    Ahi += (long)z * strA; Alo += (long)z * strA;
    Whi += (long)z * strW; Wlo += (long)z * strW;
    const float* Bp = bias + (long)z * strBias;

    extern __shared__ uint32_t smw[];
    uint32_t* sAhi = smw;
    uint32_t* sAlo = smw + 2 * A_PLANE;
    uint32_t* sBhi = smw + 4 * A_PLANE;
    uint32_t* sBlo = smw + 4 * A_PLANE + 2 * B_PLANE;

    int tid = threadIdx.x;
    int row0 = blockIdx.y * 128, col0 = blockIdx.x * 128;

    int ar = tid >> 1, ako = (tid & 1) * 8;
    const uint32_t* gAhi = Ahi + (long)(row0 + ar) * K2 + ako;
    const uint32_t* gAlo = Alo + (long)(row0 + ar) * K2 + ako;
    const uint32_t* gBhi = Whi + (long)(col0 + ar) * K2 + ako;
    const uint32_t* gBlo = Wlo + (long)(col0 + ar) * K2 + ako;
    uint32_t asz = ((row0 + ar) < Nrows) ? 16u : 0u;
    uint32_t dAhi = smem_u32(sAhi) + (uint32_t)(ar * AST + ako) * 4u;
    uint32_t dAlo = smem_u32(sAlo) + (uint32_t)(ar * AST + ako) * 4u;
    uint32_t dBhi = smem_u32(sBhi) + (uint32_t)(ar * BST + ako) * 4u;
    uint32_t dBlo = smem_u32(sBlo) + (uint32_t)(ar * BST + ako) * 4u;

    int nk = K2 / KCH;

    cp16(dAhi, gAhi, asz); cp16(dAhi + 16, gAhi + 4, asz);
    cp16(dAlo, gAlo, asz); cp16(dAlo + 16, gAlo + 4, asz);
    cp16(dBhi, gBhi, 16);  cp16(dBhi + 16, gBhi + 4, 16);
    cp16(dBlo, gBlo, 16);  cp16(dBlo + 16, gBlo + 4, 16);
    CP_COMMIT();

    int warp = tid >> 5, lane = tid & 31;
    int wm = (warp & 3) * 32, wn = (warp >> 2) * 64;
    int gid = lane >> 2, tig = lane & 3;

    int l16 = lane & 15, kh4 = (lane >> 4) * 4;
    uint32_t fAhi = smem_u32(sAhi), fAlo = smem_u32(sAlo);
    uint32_t fBhi = smem_u32(sBhi), fBlo = smem_u32(sBlo);
    uint32_t aRow = (uint32_t)((wm + l16) * AST + kh4);
    uint32_t bRow = (uint32_t)((wn + l16) * BST + kh4);

    float acc[2][8][4];
    #pragma unroll
    for (int mt = 0; mt < 2; mt++)
        #pragma unroll
        for (int nt = 0; nt < 8; nt++)
            #pragma unroll
            for (int r = 0; r < 4; r++) acc[mt][nt][r] = 0.0f;

    for (int i = 0; i < nk; i++) {
        int b = i & 1;
        if (i + 1 < nk) {
            int nb = b ^ 1;
            const uint32_t* pah = gAhi + (i + 1) * KCH;
            const uint32_t* pal = gAlo + (i + 1) * KCH;
            const uint32_t* pbh = gBhi + (i + 1) * KCH;
            const uint32_t* pbl = gBlo + (i + 1) * KCH;
            uint32_t oA = (uint32_t)(nb * A_PLANE) * 4u;
            uint32_t oB = (uint32_t)(nb * B_PLANE) * 4u;
            cp16(dAhi + oA, pah, asz); cp16(dAhi + oA + 16, pah + 4, asz);
            cp16(dAlo + oA, pal, asz); cp16(dAlo + oA + 16, pal + 4, asz);
            cp16(dBhi + oB, pbh, 16);  cp16(dBhi + oB + 16, pbh + 4, 16);
            cp16(dBlo + oB, pbl, 16);  cp16(dBlo + oB + 16, pbl + 4, 16);
            CP_COMMIT();
            CP_WAIT(1);
        } else {
            CP_WAIT(0);
        }
        __syncthreads();

        uint32_t baseA = (uint32_t)(b * A_PLANE) * 4u;
        uint32_t baseB = (uint32_t)(b * B_PLANE) * 4u;
        #pragma unroll
        for (int ks = 0; ks < 2; ks++) {
            int kq = ks * 8;
            uint32_t afh[2][4], afl[2][4];
            #pragma unroll
            for (int mt = 0; mt < 2; mt++) {
                uint32_t off = (aRow + (uint32_t)(mt * 16 * AST + kq)) * 4u;
                ldsm4(afh[mt][0], afh[mt][1], afh[mt][2], afh[mt][3], fAhi + baseA + off);
                ldsm4(afl[mt][0], afl[mt][1], afl[mt][2], afl[mt][3], fAlo + baseA + off);
            }
            #pragma unroll
            for (int np_ = 0; np_ < 4; np_++) {
                int nt0 = np_ * 2, nt1 = nt0 + 1;
                uint32_t off = (bRow + (uint32_t)(np_ * 16 * BST + kq)) * 4u;
                uint32_t bh[4], bl[4];
                ldsm4(bh[0], bh[1], bh[2], bh[3], fBhi + baseB + off);
                ldsm4(bl[0], bl[1], bl[2], bl[3], fBlo + baseB + off);
                uint32_t b0h[2] = { bh[0], bh[2] }, b1h[2] = { bh[1], bh[3] };
                uint32_t b0l[2] = { bl[0], bl[2] }, b1l[2] = { bl[1], bl[3] };
                mma16(acc[0][nt0], afh[0], b0l);
                mma16(acc[1][nt0], afh[1], b0l);
                mma16(acc[0][nt1], afh[0], b1l);
                mma16(acc[1][nt1], afh[1], b1l);
                mma16(acc[0][nt0], afl[0], b0h);
                mma16(acc[1][nt0], afl[1], b0h);
                mma16(acc[0][nt1], afl[0], b1h);
                mma16(acc[1][nt1], afl[1], b1h);
                mma16(acc[0][nt0], afh[0], b0h);
                mma16(acc[1][nt0], afh[1], b0h);
                mma16(acc[0][nt1], afh[0], b1h);
                mma16(acc[1][nt1], afh[1], b1h);
            }
        }
        __syncthreads();
    }

    // epilogue
    int P2 = Pc >> 1;
    #pragma unroll
    for (int mt = 0; mt < 2; mt++) {
        int r0 = row0 + wm + mt * 16 + gid;
        #pragma unroll
        for (int half = 0; half < 2; half++) {
            int gr = r0 + half * 8;
            if (gr >= Nrows) continue;
            int tok = -1; float gate = 0.0f;
            if (scatter) {
                long slot = (long)z * EROWS + gr;
                tok = g_slot_src[slot];
                gate = g_slot_gate[slot];
                if (tok < 0) continue;
            }
            #pragma unroll
            for (int nt = 0; nt < 8; nt++) {
                int gc = col0 + wn + nt * 8 + 2 * tig;
                float2 bv = *reinterpret_cast<const float2*>(Bp + gc);
                float v0, v1;
                if (qkv) {
                    int band = gc / Dm;
                    int cc = gc - band * Dm;
                    float a = (band == 0) ? alpha : 1.0f;
                    v0 = (acc[mt][nt][half * 2 + 0] + bv.x) * a;
                    v1 = (acc[mt][nt][half * 2 + 1] + bv.y) * a;
                    float* Cp = Cf + (long)band * strC + (long)gr * Dm + cc;
                    *reinterpret_cast<float2*>(Cp) = make_float2(v0, v1);
                    continue;
                }
                v0 = (acc[mt][nt][half * 2 + 0] + bv.x) * alpha;
                v1 = (acc[mt][nt][half * 2 + 1] + bv.y) * alpha;
                if (act) { v0 = gelu_f(v0); v1 = gelu_f(v1); }
                if (scatter) {
                    float* Cp = Cf + (long)tok * Dm + gc;
                    atomicAdd(Cp, v0 * gate);
                    atomicAdd(Cp + 1, v1 * gate);
                } else if (Chi) {
                    long o = (long)z * strC + (long)gr * P2 + (gc >> 1);
                    uint32_t hi, lo;
                    split_bf(v0, v1, hi, lo);
                    Chi[o] = hi; Clo[o] = lo;
                } else {
                    float* Cp = Cf + (long)z * strC + (long)gr * Pc + gc;
                    if (accum) {
                        float2 o = *reinterpret_cast<float2*>(Cp);
                        v0 += o.x; v1 += o.y;
                    }
                    *reinterpret_cast<float2*>(Cp) = make_float2(v0, v1);
                }
            }
        }
    }
}

// ---------------- elementwise ----------------
__global__ void addpos_kernel(const float* __restrict__ x, const float* __restrict__ pe,
                              float* __restrict__ out) {
    int i = blockIdx.x * blockDim.x + threadIdx.x;
    if (i < NTOK * Dm) out[i] = x[i] + pe[i % (Sm * Dm)];
}

// warp-per-token LayerNorm (grid = NTOK/8 blocks x 256 threads)
__global__ void ln_kernel(const float* __restrict__ in, float* __restrict__ outf,
                          uint32_t* __restrict__ ohi, uint32_t* __restrict__ olo,
                          const float* __restrict__ s, const float* __restrict__ b) {
    int warp = threadIdx.x >> 5, lane = threadIdx.x & 31;
    int t = blockIdx.x * 8 + warp;
    const float* xr = in + (size_t)t * Dm;
    float2 v[12];
    float sum = 0.0f;
    #pragma unroll
    for (int j = 0; j < 12; j++) {
        v[j] = *reinterpret_cast<const float2*>(xr + 2 * (lane + 32 * j));
        sum += v[j].x + v[j].y;
    }
    #pragma unroll
    for (int o = 16; o; o >>= 1) sum += __shfl_xor_sync(0xffffffffu, sum, o);
    float mu = sum * (1.0f / Dm);
    float vs = 0.0f;
    #pragma unroll
    for (int j = 0; j < 12; j++) {
        float d0 = v[j].x - mu, d1 = v[j].y - mu;
        vs += d0 * d0 + d1 * d1;
    }
    #pragma unroll
    for (int o = 16; o; o >>= 1) vs += __shfl_xor_sync(0xffffffffu, vs, o);
    float inv = rsqrtf(vs * (1.0f / Dm) + 1e-6f);
    #pragma unroll
    for (int j = 0; j < 12; j++) {
        int p = lane + 32 * j;
        int i = 2 * p;
        float2 sv = *reinterpret_cast<const float2*>(s + i);
        float2 bv = *reinterpret_cast<const float2*>(b + i);
        float v0 = (v[j].x - mu) * inv * sv.x + bv.x;
        float v1 = (v[j].y - mu) * inv * sv.y + bv.y;
        if (outf) *reinterpret_cast<float2*>(outf + (size_t)t * Dm + i) = make_float2(v0, v1);
        if (ohi) {
            uint32_t hi, lo;
            split_bf(v0, v1, hi, lo);
            ohi[(size_t)t * K2D + p] = hi;
            olo[(size_t)t * K2D + p] = lo;
        }
    }
}

// ---------------- attention ----------------
#define KP2 33
__global__ void attn_kernel(const float* __restrict__ q, const float* __restrict__ k,
                            const float* __restrict__ v,
                            uint32_t* __restrict__ ohi, uint32_t* __restrict__ olo) {
    extern __shared__ unsigned long long sm64[];
    unsigned long long* Ks = sm64;
    unsigned long long* Vs = sm64 + Sm * KP2;
    __shared__ float att[8][Sm];
    __shared__ unsigned long long qrow[8][32];

    int bh = blockIdx.x;
    int b = bh / Hh, h = bh % Hh;
    int tid = threadIdx.x, warp = tid >> 5, lane = tid & 31;
    const long base = (long)(b * Sm) * Dm + h * HDm;
    const long base2 = (long)(b * Sm) * K2D + h * (HDm / 2);

    for (int idx = tid; idx < Sm * 32; idx += blockDim.x) {
        int j = idx >> 5, c2 = idx & 31;
        float2 kk = *reinterpret_cast<const float2*>(k + base + (long)j * Dm + 2 * c2);
        float2 vv = *reinterpret_cast<const float2*>(v + base + (long)j * Dm + 2 * c2);
        Ks[j * KP2 + c2] = pack2(kk.x, kk.y);
        Vs[j * KP2 + c2] = pack2(vv.x, vv.y);
    }
    __syncthreads();

    for (int i = warp; i < Sm; i += 8) {
        {
            float2 qq = *reinterpret_cast<const float2*>(q + base + (long)i * Dm + 2 * lane);
            qrow[warp][lane] = pack2(qq.x, qq.y);
        }
        __syncwarp();
        float lmax = -1e30f;
        for (int j = lane; j < Sm; j += 32) {
            unsigned long long a2 = 0ull;
            const unsigned long long* kr = Ks + j * KP2;
            #pragma unroll
            for (int c2 = 0; c2 < 32; c2++)
                a2 = fma2(qrow[warp][c2], kr[c2], a2);
            float s0, s1;
            unpack2(a2, s0, s1);
            float d = s0 + s1;
            att[warp][j] = d;
            lmax = fmaxf(lmax, d);
        }
        #pragma unroll
        for (int off = 16; off; off >>= 1)
            lmax = fmaxf(lmax, __shfl_xor_sync(0xffffffffu, lmax, off));
        float lsum = 0.0f;
        for (int j = lane; j < Sm; j += 32) {
            float e = __expf(att[warp][j] - lmax);
            att[warp][j] = e;
            lsum += e;
        }
        #pragma unroll
        for (int off = 16; off; off >>= 1)
            lsum += __shfl_xor_sync(0xffffffffu, lsum, off);
        float inv = 1.0f / lsum;
        __syncwarp();
        {
            unsigned long long a2 = 0ull;
            const unsigned long long* vr = Vs + lane;
            for (int j = 0; j < Sm; j++) {
                float w = att[warp][j];
                a2 = fma2(pack2(w, w), vr[j * KP2], a2);
            }
            float a0, a1;
            unpack2(a2, a0, a1);
            uint32_t hi, lo;
            split_bf(a0 * inv, a1 * inv, hi, lo);
            ohi[base2 + (long)i * K2D + lane] = hi;
            olo[base2 + (long)i * K2D + lane] = lo;
        }
        __syncwarp();
    }
}

// ---------------- MoE routing ----------------
__global__ void route_kernel(const float* __restrict__ h, const float* __restrict__ wr) {
    int n = blockIdx.x;
    __shared__ float wrs[Em * Dm];
    __shared__ float tv[GSm][Km];
    __shared__ int   ti[GSm][Km];
    int tid = threadIdx.x, warp = tid >> 5, lane = tid & 31;

    for (int idx = tid; idx < Em * Dm; idx += blockDim.x) {
        int e = idx / Dm, c = idx % Dm;
        wrs[e * Dm + c] = wr[c * Em + e];
    }
    for (int s = tid; s < Em * CAPm; s += blockDim.x) {
        int e = s / CAPm, c = s % CAPm;
        g_slot_src[(e * NGm + n) * CAPm + c] = -1;
    }
    __syncthreads();

    for (int t = warp; t < GSm; t += 8) {
        const float* xr = h + (long)(n * GSm + t) * Dm;
        float a[Em];
        #pragma unroll
        for (int e = 0; e < Em; e++) a[e] = 0.0f;
        for (int c = lane; c < Dm; c += 32) {
            float xv = xr[c];
            #pragma unroll
            for (int e = 0; e < Em; e++) a[e] += xv * wrs[e * Dm + c];
        }
        #pragma unroll
        for (int e = 0; e < Em; e++)
            #pragma unroll
            for (int o = 16; o; o >>= 1) a[e] += __shfl_xor_sync(0xffffffffu, a[e], o);
        if (lane == 0) {
            float mx = a[0];
            #pragma unroll
            for (int e = 1; e < Em; e++) mx = fmaxf(mx, a[e]);
            float p[Em], sum = 0.0f;
            #pragma unroll
            for (int e = 0; e < Em; e++) { p[e] = expf(a[e] - mx); sum += p[e]; }
            float inv = 1.0f / sum;
            #pragma unroll
            for (int e = 0; e < Em; e++) p[e] *= inv;
            int i0 = 0;
            #pragma unroll
            for (int e = 1; e < Em; e++) if (p[e] > p[i0]) i0 = e;
            int i1 = (i0 == 0) ? 1 : 0;
            #pragma unroll
            for (int e = 0; e < Em; e++) if (e != i0 && p[e] > p[i1]) i1 = e;
            ti[t][0] = i0; tv[t][0] = p[i0];
            ti[t][1] = i1; tv[t][1] = p[i1];
        }
    }
    __syncthreads();

    if (tid == 0) {
        int cnt[Em];
        #pragma unroll
        for (int e = 0; e < Em; e++) cnt[e] = 0;
        for (int kk = 0; kk < Km; kk++) {
            for (int t = 0; t < GSm; t++) {
                int e = ti[t][kk];
                int pos = cnt[e]++;
                if (pos < CAPm) {
                    int row = (e * NGm + n) * CAPm + pos;
                    g_slot_src[row] = n * GSm + t;
                    g_slot_gate[row] = tv[t][kk];
                }
            }
        }
    }
}

__global__ void gather_kernel(const float* __restrict__ h) {
    int i = blockIdx.x * blockDim.x + threadIdx.x;
    if (i >= TROWS * K2D) return;
    int row = i / K2D, kp = i - row * K2D;
    int src = g_slot_src[row];
    float v0 = 0.0f, v1 = 0.0f;
    if (src >= 0) {
        float2 p = *reinterpret_cast<const float2*>(h + (long)src * Dm + 2 * kp);
        v0 = p.x; v1 = p.y;
    }
    uint32_t hi, lo;
    split_bf(v0, v1, hi, lo);
    g_bf_hi[i] = hi; g_bf_lo[i] = lo;
}

// ---------------- host ----------------
extern "C" void kernel_launch(void* const* d_in, const int* in_sizes, int n_in,
                              void* d_out, int out_size) {
    (void)in_sizes; (void)n_in; (void)out_size;
    const float* in_x     = (const float*)d_in[0];
    const float* posemb   = (const float*)d_in[1];
    const float* ln1_s    = (const float*)d_in[2];
    const float* ln1_b    = (const float*)d_in[3];
    const float* wq       = (const float*)d_in[4];
    const float* bq       = (const float*)d_in[5];
    const float* wk       = (const float*)d_in[6];
    const float* bk       = (const float*)d_in[7];
    const float* wv       = (const float*)d_in[8];
    const float* bv       = (const float*)d_in[9];
    const float* wo       = (const float*)d_in[10];
    const float* bo       = (const float*)d_in[11];
    const float* ln2_s    = (const float*)d_in[12];
    const float* ln2_b    = (const float*)d_in[13];
    const float* dw1      = (const float*)d_in[14];
    const float* db1      = (const float*)d_in[15];
    const float* dw2      = (const float*)d_in[16];
    const float* db2      = (const float*)d_in[17];
    const float* router_w = (const float*)d_in[18];
    const float* mw1      = (const float*)d_in[19];
    const float* mb1      = (const float*)d_in[20];
    const float* mw2      = (const float*)d_in[21];
    const float* mb2      = (const float*)d_in[22];
    const float* out_s    = (const float*)d_in[23];
    const float* out_b    = (const float*)d_in[24];
    float* out = (float*)d_out;

    float *x, *h, *qkv, *bqkv;
    uint32_t *h_hi, *h_lo, *ao_hi, *ao_lo, *ml_hi, *ml_lo, *bf_hi, *bf_lo, *hx_hi, *hx_lo;
    uint32_t *wat_hi, *wat_lo, *wd1_hi, *wd1_lo, *wd2_hi, *wd2_lo, *wm1_hi, *wm1_lo, *wm2_hi, *wm2_lo;
    cudaGetSymbolAddress((void**)&x,      g_x);
    cudaGetSymbolAddress((void**)&h,      g_h);
    cudaGetSymbolAddress((void**)&qkv,    g_qkv);
    cudaGetSymbolAddress((void**)&bqkv,   g_bqkv);
    cudaGetSymbolAddress((void**)&h_hi,   g_h_hi);
    cudaGetSymbolAddress((void**)&h_lo,   g_h_lo);
    cudaGetSymbolAddress((void**)&ao_hi,  g_ao_hi);
    cudaGetSymbolAddress((void**)&ao_lo,  g_ao_lo);
    cudaGetSymbolAddress((void**)&ml_hi,  g_ml_hi);
    cudaGetSymbolAddress((void**)&ml_lo,  g_ml_lo);
    cudaGetSymbolAddress((void**)&bf_hi,  g_bf_hi);
    cudaGetSymbolAddress((void**)&bf_lo,  g_bf_lo);
    cudaGetSymbolAddress((void**)&hx_hi,  g_hx_hi);
    cudaGetSymbolAddress((void**)&hx_lo,  g_hx_lo);
    cudaGetSymbolAddress((void**)&wat_hi, g_wat_hi);
    cudaGetSymbolAddress((void**)&wat_lo, g_wat_lo);
    cudaGetSymbolAddress((void**)&wd1_hi, g_wd1_hi);
    cudaGetSymbolAddress((void**)&wd1_lo, g_wd1_lo);
    cudaGetSymbolAddress((void**)&wd2_hi, g_wd2_hi);
    cudaGetSymbolAddress((void**)&wd2_lo, g_wd2_lo);
    cudaGetSymbolAddress((void**)&wm1_hi, g_wm1_hi);
    cudaGetSymbolAddress((void**)&wm1_lo, g_wm1_lo);
    cudaGetSymbolAddress((void**)&wm2_hi, g_wm2_hi);
    cudaGetSymbolAddress((void**)&wm2_lo, g_wm2_lo);

    float* q = qkv;
    float* k = qkv + NQKV;
    float* v = qkv + 2 * NQKV;

    const int ATTN_SMEM = 2 * Sm * KP2 * (int)sizeof(unsigned long long);
    cudaFuncSetAttribute(attn_kernel, cudaFuncAttributeMaxDynamicSharedMemorySize, ATTN_SMEM);
    cudaFuncSetAttribute(mma_gemm, cudaFuncAttributeMaxDynamicSharedMemorySize, GEMM_SMEM);

    const float qscale = 0.125f;
    const long WAT_L = (long)4 * Dm * K2D;

    // ===== prepass: split ALL weights once =====
    {
        dim3 blk(32, 8, 1);
        wsplit_qkv3_kernel<<<dim3(Dm / 32, K2D / 32, Lm * 3), blk>>>(wq, wk, wv, wat_hi, wat_lo);
        wsplit_t_kernel<<<dim3(Dm / 32, K2D / 32, Lm), blk>>>(
            wo, wat_hi + 3 * (long)Dm * K2D, wat_lo + 3 * (long)Dm * K2D,
            Dm, K2D, (long)Dm * Dm, WAT_L);
        biaspack_all_kernel<<<dim3(3, 1, Lm), 256>>>(bq, bk, bv, bqkv);
        wsplit_t_kernel<<<dim3(Mm / 32, K2D / 32, NDL), blk>>>(
            dw1, wd1_hi, wd1_lo, Mm, K2D, (long)Dm * Mm, (long)Mm * K2D);
        wsplit_t_kernel<<<dim3(Dm / 32, K2M / 32, NDL), blk>>>(
            dw2, wd2_hi, wd2_lo, Dm, K2M, (long)Mm * Dm, (long)Dm * K2M);
        wsplit_t_kernel<<<dim3(Mm / 32, K2D / 32, NML * Em), blk>>>(
            mw1, wm1_hi, wm1_lo, Mm, K2D, (long)Dm * Mm, (long)Mm * K2D);
        wsplit_t_kernel<<<dim3(Dm / 32, K2M / 32, NML * Em), blk>>>(
            mw2, wm2_hi, wm2_lo, Dm, K2M, (long)Mm * Dm, (long)Dm * K2M);
    }

    addpos_kernel<<<(NTOK * Dm + 255) / 256, 256>>>(in_x, posemb, x);

    int di = 0, mi = 0;
    for (int l = 0; l < Lm; l++) {
        // ---- attention block ----
        ln_kernel<<<NTOK / 8, 256>>>(x, nullptr, h_hi, h_lo,
                                     ln1_s + (size_t)l * Dm, ln1_b + (size_t)l * Dm);
        {
            dim3 gq(3 * Dm / 128, NTOK / 128, 1);
            mma_gemm<<<gq, 256, GEMM_SMEM>>>(h_hi, h_lo,
                                             wat_hi + (long)l * WAT_L, wat_lo + (long)l * WAT_L,
                                             bqkv + (size_t)l * 3 * Dm,
                                             qkv, nullptr, nullptr,
                                             NTOK, K2D, 3 * Dm, 0, 0, 0, NQKV,
                                             qscale, 0, 0, 1, 0);
        }
        attn_kernel<<<Bm * Hh, 256, ATTN_SMEM>>>(q, k, v, ao_hi, ao_lo);
        {
            dim3 gdd(Dm / 128, NTOK / 128, 1);
            mma_gemm<<<gdd, 256, GEMM_SMEM>>>(ao_hi, ao_lo,
                                              wat_hi + (long)l * WAT_L + 3 * (long)Dm * K2D,
                                              wat_lo + (long)l * WAT_L + 3 * (long)Dm * K2D,
                                              bo + (size_t)l * Dm,
                                              x, nullptr, nullptr,
                                              NTOK, K2D, Dm, 0, 0, 0, 0, 1.0f, 0, 1, 0, 0);
        }

        // ---- mlp / moe block ----
        ln_kernel<<<NTOK / 8, 256>>>(x, h, h_hi, h_lo,
                                     ln2_s + (size_t)l * Dm, ln2_b + (size_t)l * Dm);
        if (l & 1) {
            route_kernel<<<NGm, 256>>>(h, router_w + (size_t)mi * Dm * Em);
            gather_kernel<<<(TROWS * K2D + 255) / 256, 256>>>(h);
            dim3 g1(Mm / 128, (EROWS + 127) / 128, Em);
            mma_gemm<<<g1, 256, GEMM_SMEM>>>(bf_hi, bf_lo,
                                             wm1_hi + (long)mi * Em * Mm * K2D,
                                             wm1_lo + (long)mi * Em * Mm * K2D,
                                             mb1 + (size_t)mi * Em * Mm,
                                             nullptr, hx_hi, hx_lo,
                                             EROWS, K2D, Mm,
                                             (long)EROWS * K2D, (long)Mm * K2D, Mm,
                                             (long)EROWS * K2M, 1.0f, 1, 0, 0, 0);
            dim3 g2(Dm / 128, (EROWS + 127) / 128, Em);
            mma_gemm<<<g2, 256, GEMM_SMEM>>>(hx_hi, hx_lo,
                                             wm2_hi + (long)mi * Em * Dm * K2M,
                                             wm2_lo + (long)mi * Em * Dm * K2M,
                                             mb2 + (size_t)mi * Em * Dm,
                                             x, nullptr, nullptr,
                                             EROWS, K2M, Dm,
                                             (long)EROWS * K2M, (long)Dm * K2M, Dm,
                                             0, 1.0f, 0, 0, 0, 1);   // scatter into x
            mi++;
        } else {
            dim3 g1(Mm / 128, NTOK / 128, 1);
            mma_gemm<<<g1, 256, GEMM_SMEM>>>(h_hi, h_lo,
                                             wd1_hi + (long)di * Mm * K2D,
                                             wd1_lo + (long)di * Mm * K2D,
                                             db1 + (size_t)di * Mm,
                                             nullptr, ml_hi, ml_lo,
                                             NTOK, K2D, Mm, 0, 0, 0, 0, 1.0f, 1, 0, 0, 0);
            dim3 g2(Dm / 128, NTOK / 128, 1);
            mma_gemm<<<g2, 256, GEMM_SMEM>>>(ml_hi, ml_lo,
                                             wd2_hi + (long)di * Dm * K2M,
                                             wd2_lo + (long)di * Dm * K2M,
                                             db2 + (size_t)di * Dm,
                                             x, nullptr, nullptr,
                                             NTOK, K2M, Dm, 0, 0, 0, 0, 1.0f, 0, 1, 0, 0);
            di++;
        }
    }

    ln_kernel<<<NTOK / 8, 256>>>(x, out, nullptr, nullptr, out_s, out_b);
}